// round 7
// baseline (speedup 1.0000x reference)
#include <cuda_runtime.h>
#include <math.h>
#include <stdint.h>

#define B_    8
#define C_    96
#define C2_   192
#define NPIX  16384
#define HEADS_ 6

typedef unsigned long long u64;

__device__ __forceinline__ float to_tf32(float f) {
    unsigned u; asm("cvt.rna.tf32.f32 %0, %1;" : "=r"(u) : "f"(f));
    return __uint_as_float(u);
}
__device__ __forceinline__ void mma8(float* c, const uint32_t* a, uint32_t b0, uint32_t b1) {
    asm volatile("mma.sync.aligned.m16n8k8.row.col.f32.tf32.tf32.f32 "
                 "{%0,%1,%2,%3}, {%4,%5,%6,%7}, {%8,%9}, {%0,%1,%2,%3};"
                 : "+f"(c[0]), "+f"(c[1]), "+f"(c[2]), "+f"(c[3])
                 : "r"(a[0]), "r"(a[1]), "r"(a[2]), "r"(a[3]), "r"(b0), "r"(b1));
}

// ---- device-global scratch ----
__device__ float g_t  [B_ * C2_ * NPIX];   // qv pre-dw
__device__ float g_t2 [B_ * C2_ * NPIX];   // kv pre-dw
__device__ float g_qv [B_ * C2_ * NPIX];
__device__ float g_kv [B_ * C2_ * NPIX];
__device__ float g_v  [B_ * C_  * NPIX];
__device__ float g_attn[B_ * HEADS_ * 16 * 16];
__device__ float g_wq  [C2_ * 96];
__device__ float g_wk  [C2_ * 96];
__device__ float g_wft [9 * 96 * 192];
__device__ float g_wfin[B_ * C2_ * 288];   // per-batch [Wproj@A_b | Wpos]

__device__ __forceinline__ int kp(int kin) {   // interleave within 8-k group
    return (kin & 24) + ((kin & 3) << 1) + ((kin >> 2) & 1);
}

// ============== tf32 mma.sync 1x1 GEMM, M=192 in one CTA ==============
#define GASTR 40
#define GABUF  (192 * GASTR)
#define GBBUF  (128 * GASTR)
#define GBUFSZ (GABUF + GBBUF)
#define SMEM_G (2 * GBUFSZ * 4)         // 102400 bytes

__global__ __launch_bounds__(384, 1)
void mma_gemm(const float* __restrict__ s0, const float* __restrict__ s1,
              const float* __restrict__ s2, const float* __restrict__ W,
              float* __restrict__ out, int K, int rowoff, int wbstride)
{
    extern __shared__ float sm[];
    const int tid = threadIdx.x;
    const int wid = tid >> 5, lane = tid & 31;
    const int mw = wid >> 1, nw = wid & 1;          // 6 x 2 warps
    const int r = lane >> 2, cl = lane & 3;
    const int b = blockIdx.y;
    const int n0 = (rowoff + blockIdx.x) * 128;

    float acc[2][8][4];
#pragma unroll
    for (int i = 0; i < 2; i++)
#pragma unroll
        for (int j = 0; j < 8; j++)
#pragma unroll
            for (int q = 0; q < 4; q++) acc[i][j][q] = 0.f;

    const int nsteps = K / 32;
    const float* Wb = W + (size_t)b * wbstride;

    auto stage = [&](int kc, int buf) {
        float* sA = sm + buf * GBUFSZ;
        float* sB = sA + GABUF;
        const float* wb = Wb + kc * 32;
        for (int i = tid; i < 192 * 32; i += 384) {
            int oc = i >> 5, kin = i & 31;
            sA[oc * GASTR + kp(kin)] = wb[(size_t)oc * K + kin];
        }
        for (int i = tid; i < 128 * 32; i += 384) {
            int c = i >> 7, px = i & 127;
            int cg = kc * 32 + c;
            const float* base = (cg < 96) ? s0 : (cg < 192) ? s1 : s2;
            float v = base[((size_t)b * 96 + (cg % 96)) * NPIX + n0 + px];
            sB[px * GASTR + kp(c)] = to_tf32(v);
        }
    };

    stage(0, 0);
    __syncthreads();
    for (int s = 0; s < nsteps; s++) {
        int buf = s & 1;
        if (s + 1 < nsteps) stage(s + 1, buf ^ 1);
        const float* sA = sm + buf * GBUFSZ;
        const float* sB = sA + GABUF;
#pragma unroll
        for (int ks = 0; ks < 4; ks++) {
            uint32_t af[2][4];
#pragma unroll
            for (int mt = 0; mt < 2; mt++) {
                int row = mw * 32 + mt * 16 + r;
                float2 lo = *(const float2*)(sA + row * GASTR + ks * 8 + cl * 2);
                float2 hi = *(const float2*)(sA + (row + 8) * GASTR + ks * 8 + cl * 2);
                af[mt][0] = __float_as_uint(lo.x);
                af[mt][2] = __float_as_uint(lo.y);
                af[mt][1] = __float_as_uint(hi.x);
                af[mt][3] = __float_as_uint(hi.y);
            }
#pragma unroll
            for (int nt = 0; nt < 8; nt++) {
                int px = nw * 64 + nt * 8 + r;
                float2 bb = *(const float2*)(sB + px * GASTR + ks * 8 + cl * 2);
                uint32_t b0 = __float_as_uint(bb.x), b1 = __float_as_uint(bb.y);
                mma8(acc[0][nt], af[0], b0, b1);
                mma8(acc[1][nt], af[1], b0, b1);
            }
        }
        __syncthreads();
    }

    int ocb = mw * 32;
#pragma unroll
    for (int mt = 0; mt < 2; mt++) {
        int oc = ocb + mt * 16 + r;
        float* ob = out + ((size_t)b * 192 + oc) * NPIX + n0 + nw * 64 + 2 * cl;
#pragma unroll
        for (int nt = 0; nt < 8; nt++) {
            float* op = ob + nt * 8;
            *(float2*)op = make_float2(acc[mt][nt][0], acc[mt][nt][1]);
            *(float2*)(op + (size_t)8 * NPIX) = make_float2(acc[mt][nt][2], acc[mt][nt][3]);
        }
    }
}

// ============== fuse conv 3x3 (192->96): halo-resident taps ==============
#define FICSTR 536
#define FROWSTR 132
#define FIN_SZ (32 * FICSTR)
#define FW_SZ  (96 * 40)
#define SMEM_F ((FIN_SZ + 2 * FW_SZ) * 4)

__global__ __launch_bounds__(384, 1)
void fuse_mma(const float* __restrict__ Wt, const float* __restrict__ bias, int band)
{
    extern __shared__ float sm[];
    float* sIn = sm;
    float* sW  = sm + FIN_SZ;
    const int tid = threadIdx.x;
    const int wid = tid >> 5, lane = tid & 31;
    const int mw = wid >> 2, nw = wid & 3;          // 3 x 4 warps
    const int r = lane >> 2, cl = lane & 3;
    const int b = blockIdx.y;
    const int r0 = band * 16 + blockIdx.x * 2;
    const int pr = nw >> 1;
    const int xh = (nw & 1) * 64;

    float acc[2][8][4];
#pragma unroll
    for (int i = 0; i < 2; i++)
#pragma unroll
        for (int j = 0; j < 8; j++)
#pragma unroll
            for (int q = 0; q < 4; q++) acc[i][j][q] = 0.f;

    auto stageW = [&](int kc, int t, int buf) {
        float* dst = sW + buf * FW_SZ;
        const float* wb = Wt + (size_t)t * 96 * 192 + kc * 32;
        for (int i = tid; i < 96 * 32; i += 384) {
            int oc = i >> 5, ic = i & 31;
            dst[oc * 40 + kp(ic)] = wb[(size_t)oc * 192 + ic];
        }
    };

    for (int kc = 0; kc < 6; kc++) {
        __syncthreads();
        {
            int icg0 = kc * 32;
            const float* srcbase = (icg0 < 96)
                ? (g_kv + ((size_t)b * C2_ + 96 + icg0) * NPIX)
                : (g_qv + ((size_t)b * C2_ + icg0) * NPIX);
            for (int seg = wid; seg < 128; seg += 12) {
                int c = seg >> 2, rr = seg & 3;
                int gy = r0 + rr - 1;
                float* drow = sIn + c * FICSTR + rr * FROWSTR;
                const float* srow = srcbase + (size_t)c * NPIX + gy * 128;
                bool rowok = (unsigned)gy < 128u;
#pragma unroll
                for (int cc = lane; cc < 132; cc += 32) {
                    int gx = cc - 1;
                    float v = (rowok && (unsigned)gx < 128u) ? srow[gx] : 0.f;
                    drow[cc] = to_tf32(v);
                }
            }
        }
        stageW(kc, 0, 0);
        __syncthreads();

        for (int t = 0; t < 9; t++) {
            int buf = t & 1;
            if (t + 1 < 9) stageW(kc, t + 1, buf ^ 1);
            int dy = t / 3 - 1, dx = t - (t / 3) * 3 - 1;
            const float* sA = sW + buf * FW_SZ;
            const float* bbase = sIn + (pr + dy + 1) * FROWSTR + xh + dx + 1 + r;
#pragma unroll
            for (int ks = 0; ks < 4; ks++) {
                uint32_t af[2][4];
#pragma unroll
                for (int mt = 0; mt < 2; mt++) {
                    int row = mw * 32 + mt * 16 + r;
                    float2 lo = *(const float2*)(sA + row * 40 + ks * 8 + cl * 2);
                    float2 hi = *(const float2*)(sA + (row + 8) * 40 + ks * 8 + cl * 2);
                    af[mt][0] = __float_as_uint(lo.x);
                    af[mt][2] = __float_as_uint(lo.y);
                    af[mt][1] = __float_as_uint(hi.x);
                    af[mt][3] = __float_as_uint(hi.y);
                }
                const float* b0p = bbase + (ks * 8 + cl) * FICSTR;
                const float* b1p = b0p + 4 * FICSTR;
#pragma unroll
                for (int nt = 0; nt < 8; nt++) {
                    uint32_t b0 = __float_as_uint(b0p[nt * 8]);
                    uint32_t b1 = __float_as_uint(b1p[nt * 8]);
                    mma8(acc[0][nt], af[0], b0, b1);
                    mma8(acc[1][nt], af[1], b0, b1);
                }
            }
            __syncthreads();
        }
    }

#pragma unroll
    for (int mt = 0; mt < 2; mt++) {
        int oc = mw * 32 + mt * 16 + r;
        float bv0 = bias[oc];
        float bv8 = bias[oc + 8];
        float* ob = g_v + ((size_t)b * C_ + oc) * NPIX + (r0 + pr) * 128 + xh + 2 * cl;
#pragma unroll
        for (int nt = 0; nt < 8; nt++) {
            float* op = ob + nt * 8;
            *(float2*)op = make_float2(acc[mt][nt][0] + bv0, acc[mt][nt][1] + bv0);
            *(float2*)(op + (size_t)8 * NPIX) =
                make_float2(acc[mt][nt][2] + bv8, acc[mt][nt][3] + bv8);
        }
    }
}

// ======================= weight pack kernels (tf32 round) =======================
__global__ void pack_a(const float* __restrict__ w, float* __restrict__ dst, int total)
{
    int idx = blockIdx.x * 256 + threadIdx.x;
    if (idx < total) dst[idx] = to_tf32(w[idx]);
}
__global__ void pack_fuse(const float* __restrict__ wf, float* __restrict__ dst)
{
    int idx = blockIdx.x * 256 + threadIdx.x;   // [t][oc 96][ic 192]
    if (idx < 9 * 96 * 192) {
        int t = idx / (96 * 192);
        int rem = idx - t * (96 * 192);
        int oc = rem / 192, ic = rem - oc * 192;
        dst[idx] = to_tf32(wf[((size_t)oc * 192 + ic) * 9 + t]);
    }
}
// g_wfin[b][oc][k]: k<96 -> (Wproj @ A_b)[oc][k] ; else wpos[oc][k-96]
__global__ void pack_wfin(const float* __restrict__ wp, const float* __restrict__ wpos)
{
    int idx = blockIdx.x * 256 + threadIdx.x;
    if (idx >= B_ * C2_ * 288) return;
    int b = idx / (C2_ * 288);
    int rem = idx - b * (C2_ * 288);
    int oc = rem / 288, k = rem - oc * 288;
    float v;
    if (k < 96) {
        int h = k >> 4, d = k & 15;
        float s = 0.f;
#pragma unroll
        for (int i = 0; i < 16; i++)
            s = fmaf(wp[oc * 96 + h * 16 + i],
                     g_attn[(((size_t)b * HEADS_ + h) * 16 + i) * 16 + d], s);
        v = s;
    } else {
        v = wpos[(size_t)oc * 192 + (k - 96)];
    }
    g_wfin[idx] = to_tf32(v);
}

// ======================= depthwise 3x3, pad 1 (banded) =======================
__global__ void dw3x3_kernel(const float* __restrict__ in, const float* __restrict__ wdw,
                             float* __restrict__ out, int rowoff)
{
    int b = blockIdx.z, c = blockIdx.y;
    int n = rowoff * 128 + blockIdx.x * 256 + threadIdx.x;
    int yy = n >> 7, xx = n & 127;
    const float* ip = in + ((size_t)b * C2_ + c) * NPIX;
    const float* wp = wdw + c * 9;
    float acc = 0.f;
#pragma unroll
    for (int ky = 0; ky < 3; ky++) {
        int gy = yy + ky - 1;
        if ((unsigned)gy < 128u) {
#pragma unroll
            for (int kx = 0; kx < 3; kx++) {
                int gx = xx + kx - 1;
                if ((unsigned)gx < 128u) acc = fmaf(wp[ky * 3 + kx], ip[gy * 128 + gx], acc);
            }
        }
    }
    out[((size_t)b * C2_ + c) * NPIX + n] = acc;
}

// ===== 16x16 gram + inline L2 norms + temperature + softmax per (b,h) =====
#define GR_NC 256
__global__ void attn_kernel(const float* __restrict__ temp)
{
    __shared__ float sq[16][GR_NC + 2];
    __shared__ float sk[16][GR_NC + 2];
    __shared__ float gm[16][17];
    __shared__ float nrm[32];
    int h = blockIdx.x, b = blockIdx.y;
    int tid = threadIdx.x;
    int i = tid >> 4, j = tid & 15;
    int tgt = tid >> 3;            // 0..31: which norm this thread helps
    int toff = (tid & 7) * 32;     // its 32-wide slice
    const float* qb = g_qv + ((size_t)b * C2_ + h * 16) * NPIX;
    const float* kb = g_kv + ((size_t)b * C2_ + h * 16) * NPIX;
    float acc = 0.f, np = 0.f;
    for (int n0 = 0; n0 < NPIX; n0 += GR_NC) {
        for (int idx = tid; idx < 16 * GR_NC; idx += 256) {
            int c = idx >> 8, nn = idx & (GR_NC - 1);
            sq[c][nn] = qb[(size_t)c * NPIX + n0 + nn];
            sk[c][nn] = kb[(size_t)c * NPIX + n0 + nn];
        }
        __syncthreads();
#pragma unroll 4
        for (int nn = 0; nn < GR_NC; nn++) acc = fmaf(sq[i][nn], sk[j][nn], acc);
        {
            const float* src = (tgt < 16) ? sq[tgt] : sk[tgt - 16];
#pragma unroll 8
            for (int u = 0; u < 32; u++) { float v = src[toff + u]; np = fmaf(v, v, np); }
        }
        __syncthreads();
    }
    // reduce norm partials within 8-lane groups
    np += __shfl_down_sync(0xffffffffu, np, 4);
    np += __shfl_down_sync(0xffffffffu, np, 2);
    np += __shfl_down_sync(0xffffffffu, np, 1);
    if ((tid & 7) == 0) nrm[tgt] = np;
    __syncthreads();
    float invq = 1.f / fmaxf(sqrtf(nrm[i]), 1e-12f);
    float invk = 1.f / fmaxf(sqrtf(nrm[16 + j]), 1e-12f);
    gm[i][j] = acc * invq * invk * temp[h];
    __syncthreads();
    if (tid < 16) {
        int ii = tid;
        float m = -1e30f;
        for (int jj = 0; jj < 16; jj++) m = fmaxf(m, gm[ii][jj]);
        float e[16], ssum = 0.f;
        for (int jj = 0; jj < 16; jj++) { e[jj] = expf(gm[ii][jj] - m); ssum += e[jj]; }
        float inv = 1.f / ssum;
        for (int jj = 0; jj < 16; jj++)
            g_attn[(((size_t)b * HEADS_ + h) * 16 + ii) * 16 + jj] = e[jj] * inv;
    }
}

extern "C" void kernel_launch(void* const* d_in, const int* in_sizes, int n_in,
                              void* d_out, int out_size)
{
    const float* x        = (const float*)d_in[0];
    const float* y        = (const float*)d_in[1];
    const float* w_pos    = (const float*)d_in[2];
    const float* w_qv     = (const float*)d_in[3];
    const float* w_qv_dw  = (const float*)d_in[4];
    const float* w_kv     = (const float*)d_in[5];
    const float* w_kv_dw  = (const float*)d_in[6];
    const float* w_proj   = (const float*)d_in[7];
    const float* w_fuse   = (const float*)d_in[8];
    const float* b_fuse   = (const float*)d_in[9];
    const float* temp     = (const float*)d_in[10];
    float* out = (float*)d_out;

    void *pt, *pt2, *pqv, *pkv, *pv, *pwq, *pwk, *pwft, *pwfin;
    cudaGetSymbolAddress(&pt, g_t);
    cudaGetSymbolAddress(&pt2, g_t2);
    cudaGetSymbolAddress(&pqv, g_qv);
    cudaGetSymbolAddress(&pkv, g_kv);
    cudaGetSymbolAddress(&pv, g_v);
    cudaGetSymbolAddress(&pwq, g_wq);
    cudaGetSymbolAddress(&pwk, g_wk);
    cudaGetSymbolAddress(&pwft, g_wft);
    cudaGetSymbolAddress(&pwfin, g_wfin);

    cudaFuncSetAttribute(mma_gemm, cudaFuncAttributeMaxDynamicSharedMemorySize, SMEM_G);
    cudaFuncSetAttribute(fuse_mma, cudaFuncAttributeMaxDynamicSharedMemorySize, SMEM_F);

    // weight packing (tf32-rounded)
    pack_a<<<(C2_ * 96 + 255) / 256, 256>>>(w_qv, (float*)pwq, C2_ * 96);
    pack_a<<<(C2_ * 96 + 255) / 256, 256>>>(w_kv, (float*)pwk, C2_ * 96);
    pack_fuse<<<(9 * 96 * 192 + 255) / 256, 256>>>(w_fuse, (float*)pwft);

    // Banded conv chain: 8 bands of 16 rows; software pipeline keeps each
    // band's intermediates (g_t/g_t2/g_qv/g_kv) L2-resident between stages.
    for (int i = 0; i < 10; i++) {
        if (i < 8) {
            mma_gemm<<<dim3(16, B_), 384, SMEM_G>>>(
                x, nullptr, nullptr, (const float*)pwq, (float*)pt, 96, i * 16, 0);
            mma_gemm<<<dim3(16, B_), 384, SMEM_G>>>(
                y, nullptr, nullptr, (const float*)pwk, (float*)pt2, 96, i * 16, 0);
        }
        if (i >= 1 && i <= 8) {
            dw3x3_kernel<<<dim3(8, C2_, B_), 256>>>(
                (const float*)pt, w_qv_dw, (float*)pqv, (i - 1) * 16);
            dw3x3_kernel<<<dim3(8, C2_, B_), 256>>>(
                (const float*)pt2, w_kv_dw, (float*)pkv, (i - 1) * 16);
        }
        if (i >= 2) {
            fuse_mma<<<dim3(8, B_), 384, SMEM_F>>>(
                (const float*)pwft, b_fuse, i - 2);
        }
    }

    // attention (gram + norms + softmax in one pass)
    attn_kernel<<<dim3(HEADS_, B_), 256>>>(temp);
    // per-batch fused final weights: [Wproj@A_b | Wpos]
    pack_wfin<<<(B_ * C2_ * 288 + 255) / 256, 256>>>(w_proj, w_pos);
    // final: g_wfin_b @ [v; x; y]
    mma_gemm<<<dim3(128, B_), 384, SMEM_G>>>(
        (const float*)pv, x, y, (const float*)pwfin, out, 288, 0, C2_ * 288);
}

// round 8
// speedup vs baseline: 1.3850x; 1.3850x over previous
#include <cuda_runtime.h>
#include <math.h>
#include <stdint.h>

#define B_    8
#define C_    96
#define C2_   192
#define NPIX  16384
#define HEADS_ 6

typedef unsigned long long u64;

__device__ __forceinline__ float to_tf32(float f) {
    unsigned u; asm("cvt.rna.tf32.f32 %0, %1;" : "=r"(u) : "f"(f));
    return __uint_as_float(u);
}
__device__ __forceinline__ void mma8(float* c, const uint32_t* a, uint32_t b0, uint32_t b1) {
    asm volatile("mma.sync.aligned.m16n8k8.row.col.f32.tf32.tf32.f32 "
                 "{%0,%1,%2,%3}, {%4,%5,%6,%7}, {%8,%9}, {%0,%1,%2,%3};"
                 : "+f"(c[0]), "+f"(c[1]), "+f"(c[2]), "+f"(c[3])
                 : "r"(a[0]), "r"(a[1]), "r"(a[2]), "r"(a[3]), "r"(b0), "r"(b1));
}

// ---- device-global scratch ----
__device__ float g_t  [B_ * C2_ * NPIX];   // pre-dw scratch (shared by q/k branches)
__device__ float g_qv [B_ * C2_ * NPIX];
__device__ float g_kv [B_ * C2_ * NPIX];
__device__ float g_v  [B_ * C_  * NPIX];
__device__ float g_attn[B_ * HEADS_ * 16 * 16];
__device__ float g_wq  [C2_ * 96];
__device__ float g_wk  [C2_ * 96];
__device__ float g_wft [9 * 96 * 192];
__device__ float g_wfin[B_ * C2_ * 288];   // per-batch [Wproj@A_b | Wpos]

__device__ __forceinline__ int kp(int kin) {   // interleave within 8-k group
    return (kin & 24) + ((kin & 3) << 1) + ((kin >> 2) & 1);
}

// ============== tf32 mma.sync 1x1 GEMM, M=192 in one CTA ==============
// CTA: 192 oc x 128 px, 12 warps (6m x 2n), warp tile 32x64.
#define GASTR 40
#define GABUF  (192 * GASTR)
#define GBBUF  (128 * GASTR)
#define GBUFSZ (GABUF + GBBUF)
#define SMEM_G (2 * GBUFSZ * 4)         // 102400 bytes

__global__ __launch_bounds__(384, 1)
void mma_gemm(const float* __restrict__ s0, const float* __restrict__ s1,
              const float* __restrict__ s2, const float* __restrict__ W,
              float* __restrict__ out, int K, int wbstride)
{
    extern __shared__ float sm[];
    const int tid = threadIdx.x;
    const int wid = tid >> 5, lane = tid & 31;
    const int mw = wid >> 1, nw = wid & 1;          // 6 x 2 warps
    const int r = lane >> 2, cl = lane & 3;
    const int b = blockIdx.y;
    const int n0 = blockIdx.x * 128;

    float acc[2][8][4];
#pragma unroll
    for (int i = 0; i < 2; i++)
#pragma unroll
        for (int j = 0; j < 8; j++)
#pragma unroll
            for (int q = 0; q < 4; q++) acc[i][j][q] = 0.f;

    const int nsteps = K / 32;
    const float* Wb = W + (size_t)b * wbstride;

    auto stage = [&](int kc, int buf) {
        float* sA = sm + buf * GBUFSZ;
        float* sB = sA + GABUF;
        const float* wb = Wb + kc * 32;
        for (int i = tid; i < 192 * 32; i += 384) {
            int oc = i >> 5, kin = i & 31;
            sA[oc * GASTR + kp(kin)] = wb[(size_t)oc * K + kin];
        }
        for (int i = tid; i < 128 * 32; i += 384) {
            int c = i >> 7, px = i & 127;
            int cg = kc * 32 + c;
            const float* base = (cg < 96) ? s0 : (cg < 192) ? s1 : s2;
            float v = base[((size_t)b * 96 + (cg % 96)) * NPIX + n0 + px];
            sB[px * GASTR + kp(c)] = to_tf32(v);
        }
    };

    stage(0, 0);
    __syncthreads();
    for (int s = 0; s < nsteps; s++) {
        int buf = s & 1;
        if (s + 1 < nsteps) stage(s + 1, buf ^ 1);
        const float* sA = sm + buf * GBUFSZ;
        const float* sB = sA + GABUF;
#pragma unroll
        for (int ks = 0; ks < 4; ks++) {
            uint32_t af[2][4];
#pragma unroll
            for (int mt = 0; mt < 2; mt++) {
                int row = mw * 32 + mt * 16 + r;
                float2 lo = *(const float2*)(sA + row * GASTR + ks * 8 + cl * 2);
                float2 hi = *(const float2*)(sA + (row + 8) * GASTR + ks * 8 + cl * 2);
                af[mt][0] = __float_as_uint(lo.x);
                af[mt][2] = __float_as_uint(lo.y);
                af[mt][1] = __float_as_uint(hi.x);
                af[mt][3] = __float_as_uint(hi.y);
            }
#pragma unroll
            for (int nt = 0; nt < 8; nt++) {
                int px = nw * 64 + nt * 8 + r;
                float2 bb = *(const float2*)(sB + px * GASTR + ks * 8 + cl * 2);
                uint32_t b0 = __float_as_uint(bb.x), b1 = __float_as_uint(bb.y);
                mma8(acc[0][nt], af[0], b0, b1);
                mma8(acc[1][nt], af[1], b0, b1);
            }
        }
        __syncthreads();
    }

    int ocb = mw * 32;
#pragma unroll
    for (int mt = 0; mt < 2; mt++) {
        int oc = ocb + mt * 16 + r;
        float* ob = out + ((size_t)b * 192 + oc) * NPIX + n0 + nw * 64 + 2 * cl;
#pragma unroll
        for (int nt = 0; nt < 8; nt++) {
            float* op = ob + nt * 8;
            *(float2*)op = make_float2(acc[mt][nt][0], acc[mt][nt][1]);
            *(float2*)(op + (size_t)8 * NPIX) = make_float2(acc[mt][nt][2], acc[mt][nt][3]);
        }
    }
}

// ============== fuse conv 3x3 (192->96): halo-resident taps ==============
#define FICSTR 536
#define FROWSTR 132
#define FIN_SZ (32 * FICSTR)
#define FW_SZ  (96 * 40)
#define SMEM_F ((FIN_SZ + 2 * FW_SZ) * 4)

__global__ __launch_bounds__(384, 1)
void fuse_mma(const float* __restrict__ Wt, const float* __restrict__ bias)
{
    extern __shared__ float sm[];
    float* sIn = sm;
    float* sW  = sm + FIN_SZ;
    const int tid = threadIdx.x;
    const int wid = tid >> 5, lane = tid & 31;
    const int mw = wid >> 2, nw = wid & 3;          // 3 x 4 warps
    const int r = lane >> 2, cl = lane & 3;
    const int b = blockIdx.y;
    const int r0 = blockIdx.x * 2;
    const int pr = nw >> 1;
    const int xh = (nw & 1) * 64;

    float acc[2][8][4];
#pragma unroll
    for (int i = 0; i < 2; i++)
#pragma unroll
        for (int j = 0; j < 8; j++)
#pragma unroll
            for (int q = 0; q < 4; q++) acc[i][j][q] = 0.f;

    auto stageW = [&](int kc, int t, int buf) {
        float* dst = sW + buf * FW_SZ;
        const float* wb = Wt + (size_t)t * 96 * 192 + kc * 32;
        for (int i = tid; i < 96 * 32; i += 384) {
            int oc = i >> 5, ic = i & 31;
            dst[oc * 40 + kp(ic)] = wb[(size_t)oc * 192 + ic];
        }
    };

    for (int kc = 0; kc < 6; kc++) {
        __syncthreads();
        {
            int icg0 = kc * 32;
            const float* srcbase = (icg0 < 96)
                ? (g_kv + ((size_t)b * C2_ + 96 + icg0) * NPIX)
                : (g_qv + ((size_t)b * C2_ + icg0) * NPIX);
            for (int seg = wid; seg < 128; seg += 12) {
                int c = seg >> 2, rr = seg & 3;
                int gy = r0 + rr - 1;
                float* drow = sIn + c * FICSTR + rr * FROWSTR;
                const float* srow = srcbase + (size_t)c * NPIX + gy * 128;
                bool rowok = (unsigned)gy < 128u;
#pragma unroll
                for (int cc = lane; cc < 132; cc += 32) {
                    int gx = cc - 1;
                    float v = (rowok && (unsigned)gx < 128u) ? srow[gx] : 0.f;
                    drow[cc] = to_tf32(v);
                }
            }
        }
        stageW(kc, 0, 0);
        __syncthreads();

        for (int t = 0; t < 9; t++) {
            int buf = t & 1;
            if (t + 1 < 9) stageW(kc, t + 1, buf ^ 1);
            int dy = t / 3 - 1, dx = t - (t / 3) * 3 - 1;
            const float* sA = sW + buf * FW_SZ;
            const float* bbase = sIn + (pr + dy + 1) * FROWSTR + xh + dx + 1 + r;
#pragma unroll
            for (int ks = 0; ks < 4; ks++) {
                uint32_t af[2][4];
#pragma unroll
                for (int mt = 0; mt < 2; mt++) {
                    int row = mw * 32 + mt * 16 + r;
                    float2 lo = *(const float2*)(sA + row * 40 + ks * 8 + cl * 2);
                    float2 hi = *(const float2*)(sA + (row + 8) * 40 + ks * 8 + cl * 2);
                    af[mt][0] = __float_as_uint(lo.x);
                    af[mt][2] = __float_as_uint(lo.y);
                    af[mt][1] = __float_as_uint(hi.x);
                    af[mt][3] = __float_as_uint(hi.y);
                }
                const float* b0p = bbase + (ks * 8 + cl) * FICSTR;
                const float* b1p = b0p + 4 * FICSTR;
#pragma unroll
                for (int nt = 0; nt < 8; nt++) {
                    uint32_t b0 = __float_as_uint(b0p[nt * 8]);
                    uint32_t b1 = __float_as_uint(b1p[nt * 8]);
                    mma8(acc[0][nt], af[0], b0, b1);
                    mma8(acc[1][nt], af[1], b0, b1);
                }
            }
            __syncthreads();
        }
    }

#pragma unroll
    for (int mt = 0; mt < 2; mt++) {
        int oc = mw * 32 + mt * 16 + r;
        float bv0 = bias[oc];
        float bv8 = bias[oc + 8];
        float* ob = g_v + ((size_t)b * C_ + oc) * NPIX + (r0 + pr) * 128 + xh + 2 * cl;
#pragma unroll
        for (int nt = 0; nt < 8; nt++) {
            float* op = ob + nt * 8;
            *(float2*)op = make_float2(acc[mt][nt][0] + bv0, acc[mt][nt][1] + bv0);
            *(float2*)(op + (size_t)8 * NPIX) =
                make_float2(acc[mt][nt][2] + bv8, acc[mt][nt][3] + bv8);
        }
    }
}

// ======================= weight pack kernels (tf32 round) =======================
__global__ void pack_a(const float* __restrict__ w, float* __restrict__ dst, int total)
{
    int idx = blockIdx.x * 256 + threadIdx.x;
    if (idx < total) dst[idx] = to_tf32(w[idx]);
}
__global__ void pack_fuse(const float* __restrict__ wf, float* __restrict__ dst)
{
    int idx = blockIdx.x * 256 + threadIdx.x;   // [t][oc 96][ic 192]
    if (idx < 9 * 96 * 192) {
        int t = idx / (96 * 192);
        int rem = idx - t * (96 * 192);
        int oc = rem / 192, ic = rem - oc * 192;
        dst[idx] = to_tf32(wf[((size_t)oc * 192 + ic) * 9 + t]);
    }
}
// g_wfin[b][oc][k]: k<96 -> (Wproj @ A_b)[oc][k] ; else wpos[oc][k-96]
__global__ void pack_wfin(const float* __restrict__ wp, const float* __restrict__ wpos)
{
    int idx = blockIdx.x * 256 + threadIdx.x;
    if (idx >= B_ * C2_ * 288) return;
    int b = idx / (C2_ * 288);
    int rem = idx - b * (C2_ * 288);
    int oc = rem / 288, k = rem - oc * 288;
    float v;
    if (k < 96) {
        int h = k >> 4, d = k & 15;
        float s = 0.f;
#pragma unroll
        for (int i = 0; i < 16; i++)
            s = fmaf(wp[oc * 96 + h * 16 + i],
                     g_attn[(((size_t)b * HEADS_ + h) * 16 + i) * 16 + d], s);
        v = s;
    } else {
        v = wpos[(size_t)oc * 192 + (k - 96)];
    }
    g_wfin[idx] = to_tf32(v);
}

// ======================= depthwise 3x3, pad 1 =======================
__global__ void dw3x3_kernel(const float* __restrict__ in, const float* __restrict__ wdw,
                             float* __restrict__ out)
{
    int b = blockIdx.z, c = blockIdx.y;
    int n = blockIdx.x * 256 + threadIdx.x;
    int yy = n >> 7, xx = n & 127;
    const float* ip = in + ((size_t)b * C2_ + c) * NPIX;
    const float* wp = wdw + c * 9;
    float acc = 0.f;
#pragma unroll
    for (int ky = 0; ky < 3; ky++) {
        int gy = yy + ky - 1;
        if ((unsigned)gy < 128u) {
#pragma unroll
            for (int kx = 0; kx < 3; kx++) {
                int gx = xx + kx - 1;
                if ((unsigned)gx < 128u) acc = fmaf(wp[ky * 3 + kx], ip[gy * 128 + gx], acc);
            }
        }
    }
    out[((size_t)b * C2_ + c) * NPIX + n] = acc;
}

// ===== 16x16 gram + inline L2 norms + temperature + softmax per (b,h) =====
#define GR_NC 256
__global__ void attn_kernel(const float* __restrict__ temp)
{
    __shared__ float sq[16][GR_NC + 2];
    __shared__ float sk[16][GR_NC + 2];
    __shared__ float gm[16][17];
    __shared__ float nrm[32];
    int h = blockIdx.x, b = blockIdx.y;
    int tid = threadIdx.x;
    int i = tid >> 4, j = tid & 15;
    int tgt = tid >> 3;            // 0..31: which norm this thread helps
    int toff = (tid & 7) * 32;     // its 32-wide slice
    const float* qb = g_qv + ((size_t)b * C2_ + h * 16) * NPIX;
    const float* kb = g_kv + ((size_t)b * C2_ + h * 16) * NPIX;
    float acc = 0.f, np = 0.f;
    for (int n0 = 0; n0 < NPIX; n0 += GR_NC) {
        for (int idx = tid; idx < 16 * GR_NC; idx += 256) {
            int c = idx >> 8, nn = idx & (GR_NC - 1);
            sq[c][nn] = qb[(size_t)c * NPIX + n0 + nn];
            sk[c][nn] = kb[(size_t)c * NPIX + n0 + nn];
        }
        __syncthreads();
#pragma unroll 4
        for (int nn = 0; nn < GR_NC; nn++) acc = fmaf(sq[i][nn], sk[j][nn], acc);
        {
            const float* src = (tgt < 16) ? sq[tgt] : sk[tgt - 16];
#pragma unroll 8
            for (int u = 0; u < 32; u++) { float v = src[toff + u]; np = fmaf(v, v, np); }
        }
        __syncthreads();
    }
    np += __shfl_down_sync(0xffffffffu, np, 4);
    np += __shfl_down_sync(0xffffffffu, np, 2);
    np += __shfl_down_sync(0xffffffffu, np, 1);
    if ((tid & 7) == 0) nrm[tgt] = np;
    __syncthreads();
    float invq = 1.f / fmaxf(sqrtf(nrm[i]), 1e-12f);
    float invk = 1.f / fmaxf(sqrtf(nrm[16 + j]), 1e-12f);
    gm[i][j] = acc * invq * invk * temp[h];
    __syncthreads();
    if (tid < 16) {
        int ii = tid;
        float m = -1e30f;
        for (int jj = 0; jj < 16; jj++) m = fmaxf(m, gm[ii][jj]);
        float e[16], ssum = 0.f;
        for (int jj = 0; jj < 16; jj++) { e[jj] = expf(gm[ii][jj] - m); ssum += e[jj]; }
        float inv = 1.f / ssum;
        for (int jj = 0; jj < 16; jj++)
            g_attn[(((size_t)b * HEADS_ + h) * 16 + ii) * 16 + jj] = e[jj] * inv;
    }
}

extern "C" void kernel_launch(void* const* d_in, const int* in_sizes, int n_in,
                              void* d_out, int out_size)
{
    const float* x        = (const float*)d_in[0];
    const float* y        = (const float*)d_in[1];
    const float* w_pos    = (const float*)d_in[2];
    const float* w_qv     = (const float*)d_in[3];
    const float* w_qv_dw  = (const float*)d_in[4];
    const float* w_kv     = (const float*)d_in[5];
    const float* w_kv_dw  = (const float*)d_in[6];
    const float* w_proj   = (const float*)d_in[7];
    const float* w_fuse   = (const float*)d_in[8];
    const float* b_fuse   = (const float*)d_in[9];
    const float* temp     = (const float*)d_in[10];
    float* out = (float*)d_out;

    void *pt, *pqv, *pkv, *pv, *pwq, *pwk, *pwft, *pwfin;
    cudaGetSymbolAddress(&pt, g_t);
    cudaGetSymbolAddress(&pqv, g_qv);
    cudaGetSymbolAddress(&pkv, g_kv);
    cudaGetSymbolAddress(&pv, g_v);
    cudaGetSymbolAddress(&pwq, g_wq);
    cudaGetSymbolAddress(&pwk, g_wk);
    cudaGetSymbolAddress(&pwft, g_wft);
    cudaGetSymbolAddress(&pwfin, g_wfin);

    cudaFuncSetAttribute(mma_gemm, cudaFuncAttributeMaxDynamicSharedMemorySize, SMEM_G);
    cudaFuncSetAttribute(fuse_mma, cudaFuncAttributeMaxDynamicSharedMemorySize, SMEM_F);

    // weight packing (tf32-rounded)
    pack_a<<<(C2_ * 96 + 255) / 256, 256>>>(w_qv, (float*)pwq, C2_ * 96);
    pack_a<<<(C2_ * 96 + 255) / 256, 256>>>(w_kv, (float*)pwk, C2_ * 96);
    pack_fuse<<<(9 * 96 * 192 + 255) / 256, 256>>>(w_fuse, (float*)pwft);

    // qv branch (full-image launches — 1024 CTAs)
    mma_gemm<<<dim3(128, B_), 384, SMEM_G>>>(
        x, nullptr, nullptr, (const float*)pwq, (float*)pt, 96, 0);
    dw3x3_kernel<<<dim3(NPIX / 256, C2_, B_), 256>>>((const float*)pt, w_qv_dw, (float*)pqv);
    // kv branch
    mma_gemm<<<dim3(128, B_), 384, SMEM_G>>>(
        y, nullptr, nullptr, (const float*)pwk, (float*)pt, 96, 0);
    dw3x3_kernel<<<dim3(NPIX / 256, C2_, B_), 256>>>((const float*)pt, w_kv_dw, (float*)pkv);
    // v = fuse3x3(cat(v0, v_)) + bias
    fuse_mma<<<dim3(64, B_), 384, SMEM_F>>>((const float*)pwft, b_fuse);
    // attention (gram + norms + softmax in one pass)
    attn_kernel<<<dim3(HEADS_, B_), 256>>>(temp);
    // per-batch fused final weights: [Wproj@A_b | Wpos]
    pack_wfin<<<(B_ * C2_ * 288 + 255) / 256, 256>>>(w_proj, w_pos);
    // final: g_wfin_b @ [v; x; y]
    mma_gemm<<<dim3(128, B_), 384, SMEM_G>>>(
        (const float*)pv, x, y, (const float*)pwfin, out, 288, C2_ * 288);
}

// round 9
// speedup vs baseline: 1.3865x; 1.0011x over previous
#include <cuda_runtime.h>
#include <math.h>
#include <stdint.h>

#define B_    8
#define C_    96
#define C2_   192
#define NPIX  16384
#define HEADS_ 6

typedef unsigned long long u64;

__device__ __forceinline__ float to_tf32(float f) {
    unsigned u; asm("cvt.rna.tf32.f32 %0, %1;" : "=r"(u) : "f"(f));
    return __uint_as_float(u);
}
__device__ __forceinline__ void mma8(float* c, const uint32_t* a, uint32_t b0, uint32_t b1) {
    asm volatile("mma.sync.aligned.m16n8k8.row.col.f32.tf32.tf32.f32 "
                 "{%0,%1,%2,%3}, {%4,%5,%6,%7}, {%8,%9}, {%0,%1,%2,%3};"
                 : "+f"(c[0]), "+f"(c[1]), "+f"(c[2]), "+f"(c[3])
                 : "r"(a[0]), "r"(a[1]), "r"(a[2]), "r"(a[3]), "r"(b0), "r"(b1));
}

// ---- device-global scratch ----
__device__ float g_t  [B_ * C2_ * NPIX];   // pre-dw scratch (shared by q/k branches)
__device__ float g_qv [B_ * C2_ * NPIX];
__device__ float g_kv [B_ * C2_ * NPIX];
__device__ float g_v  [B_ * C_  * NPIX];
__device__ float g_attn[B_ * HEADS_ * 16 * 16];
__device__ float g_wq  [C2_ * 96];
__device__ float g_wk  [C2_ * 96];
__device__ float g_wft [9 * 96 * 192];
__device__ float g_wfin[B_ * C2_ * 288];   // per-batch [Wproj@A_b | Wpos]

__device__ __forceinline__ int kp(int kin) {   // interleave within 8-k group
    return (kin & 24) + ((kin & 3) << 1) + ((kin >> 2) & 1);
}

// ============== tf32 mma.sync 1x1 GEMM, M=192 in one CTA ==============
// CTA: 192 oc x 128 px, 12 warps (6m x 2n), warp tile 32x64.
#define GASTR 40
#define GABUF  (192 * GASTR)
#define GBBUF  (128 * GASTR)
#define GBUFSZ (GABUF + GBBUF)
#define SMEM_G (2 * GBUFSZ * 4)         // 102400 bytes

__global__ __launch_bounds__(384, 1)
void mma_gemm(const float* __restrict__ s0, const float* __restrict__ s1,
              const float* __restrict__ s2, const float* __restrict__ W,
              float* __restrict__ out, int K, int wbstride)
{
    extern __shared__ float sm[];
    const int tid = threadIdx.x;
    const int wid = tid >> 5, lane = tid & 31;
    const int mw = wid >> 1, nw = wid & 1;          // 6 x 2 warps
    const int r = lane >> 2, cl = lane & 3;
    const int b = blockIdx.y;
    const int n0 = blockIdx.x * 128;

    float acc[2][8][4];
#pragma unroll
    for (int i = 0; i < 2; i++)
#pragma unroll
        for (int j = 0; j < 8; j++)
#pragma unroll
            for (int q = 0; q < 4; q++) acc[i][j][q] = 0.f;

    const int nsteps = K / 32;
    const float* Wb = W + (size_t)b * wbstride;

    auto stage = [&](int kc, int buf) {
        float* sA = sm + buf * GBUFSZ;
        float* sB = sA + GABUF;
        const float* wb = Wb + kc * 32;
        for (int i = tid; i < 192 * 32; i += 384) {
            int oc = i >> 5, kin = i & 31;
            sA[oc * GASTR + kp(kin)] = wb[(size_t)oc * K + kin];
        }
        for (int i = tid; i < 128 * 32; i += 384) {
            int c = i >> 7, px = i & 127;
            int cg = kc * 32 + c;
            const float* base = (cg < 96) ? s0 : (cg < 192) ? s1 : s2;
            float v = base[((size_t)b * 96 + (cg % 96)) * NPIX + n0 + px];
            sB[px * GASTR + kp(c)] = to_tf32(v);
        }
    };

    stage(0, 0);
    __syncthreads();
    for (int s = 0; s < nsteps; s++) {
        int buf = s & 1;
        if (s + 1 < nsteps) stage(s + 1, buf ^ 1);
        const float* sA = sm + buf * GBUFSZ;
        const float* sB = sA + GABUF;
#pragma unroll
        for (int ks = 0; ks < 4; ks++) {
            uint32_t af[2][4];
#pragma unroll
            for (int mt = 0; mt < 2; mt++) {
                int row = mw * 32 + mt * 16 + r;
                float2 lo = *(const float2*)(sA + row * GASTR + ks * 8 + cl * 2);
                float2 hi = *(const float2*)(sA + (row + 8) * GASTR + ks * 8 + cl * 2);
                af[mt][0] = __float_as_uint(lo.x);
                af[mt][2] = __float_as_uint(lo.y);
                af[mt][1] = __float_as_uint(hi.x);
                af[mt][3] = __float_as_uint(hi.y);
            }
#pragma unroll
            for (int nt = 0; nt < 8; nt++) {
                int px = nw * 64 + nt * 8 + r;
                float2 bb = *(const float2*)(sB + px * GASTR + ks * 8 + cl * 2);
                uint32_t b0 = __float_as_uint(bb.x), b1 = __float_as_uint(bb.y);
                mma8(acc[0][nt], af[0], b0, b1);
                mma8(acc[1][nt], af[1], b0, b1);
            }
        }
        __syncthreads();
    }

    int ocb = mw * 32;
#pragma unroll
    for (int mt = 0; mt < 2; mt++) {
        int oc = ocb + mt * 16 + r;
        float* ob = out + ((size_t)b * 192 + oc) * NPIX + n0 + nw * 64 + 2 * cl;
#pragma unroll
        for (int nt = 0; nt < 8; nt++) {
            float* op = ob + nt * 8;
            *(float2*)op = make_float2(acc[mt][nt][0], acc[mt][nt][1]);
            *(float2*)(op + (size_t)8 * NPIX) = make_float2(acc[mt][nt][2], acc[mt][nt][3]);
        }
    }
}

// ============== fuse conv 3x3 (192->96): halo-resident taps ==============
#define FICSTR 536
#define FROWSTR 132
#define FIN_SZ (32 * FICSTR)
#define FW_SZ  (96 * 40)
#define SMEM_F ((FIN_SZ + 2 * FW_SZ) * 4)

__global__ __launch_bounds__(384, 1)
void fuse_mma(const float* __restrict__ Wt, const float* __restrict__ bias)
{
    extern __shared__ float sm[];
    float* sIn = sm;
    float* sW  = sm + FIN_SZ;
    const int tid = threadIdx.x;
    const int wid = tid >> 5, lane = tid & 31;
    const int mw = wid >> 2, nw = wid & 3;          // 3 x 4 warps
    const int r = lane >> 2, cl = lane & 3;
    const int b = blockIdx.y;
    const int r0 = blockIdx.x * 2;
    const int pr = nw >> 1;
    const int xh = (nw & 1) * 64;

    float acc[2][8][4];
#pragma unroll
    for (int i = 0; i < 2; i++)
#pragma unroll
        for (int j = 0; j < 8; j++)
#pragma unroll
            for (int q = 0; q < 4; q++) acc[i][j][q] = 0.f;

    auto stageW = [&](int kc, int t, int buf) {
        float* dst = sW + buf * FW_SZ;
        const float* wb = Wt + (size_t)t * 96 * 192 + kc * 32;
        for (int i = tid; i < 96 * 32; i += 384) {
            int oc = i >> 5, ic = i & 31;
            dst[oc * 40 + kp(ic)] = wb[(size_t)oc * 192 + ic];
        }
    };

    for (int kc = 0; kc < 6; kc++) {
        __syncthreads();
        {
            int icg0 = kc * 32;
            const float* srcbase = (icg0 < 96)
                ? (g_kv + ((size_t)b * C2_ + 96 + icg0) * NPIX)
                : (g_qv + ((size_t)b * C2_ + icg0) * NPIX);
            for (int seg = wid; seg < 128; seg += 12) {
                int c = seg >> 2, rr = seg & 3;
                int gy = r0 + rr - 1;
                float* drow = sIn + c * FICSTR + rr * FROWSTR;
                const float* srow = srcbase + (size_t)c * NPIX + gy * 128;
                bool rowok = (unsigned)gy < 128u;
#pragma unroll
                for (int cc = lane; cc < 132; cc += 32) {
                    int gx = cc - 1;
                    float v = (rowok && (unsigned)gx < 128u) ? srow[gx] : 0.f;
                    drow[cc] = to_tf32(v);
                }
            }
        }
        stageW(kc, 0, 0);
        __syncthreads();

        for (int t = 0; t < 9; t++) {
            int buf = t & 1;
            if (t + 1 < 9) stageW(kc, t + 1, buf ^ 1);
            int dy = t / 3 - 1, dx = t - (t / 3) * 3 - 1;
            const float* sA = sW + buf * FW_SZ;
            const float* bbase = sIn + (pr + dy + 1) * FROWSTR + xh + dx + 1 + r;
#pragma unroll
            for (int ks = 0; ks < 4; ks++) {
                uint32_t af[2][4];
#pragma unroll
                for (int mt = 0; mt < 2; mt++) {
                    int row = mw * 32 + mt * 16 + r;
                    float2 lo = *(const float2*)(sA + row * 40 + ks * 8 + cl * 2);
                    float2 hi = *(const float2*)(sA + (row + 8) * 40 + ks * 8 + cl * 2);
                    af[mt][0] = __float_as_uint(lo.x);
                    af[mt][2] = __float_as_uint(lo.y);
                    af[mt][1] = __float_as_uint(hi.x);
                    af[mt][3] = __float_as_uint(hi.y);
                }
                const float* b0p = bbase + (ks * 8 + cl) * FICSTR;
                const float* b1p = b0p + 4 * FICSTR;
#pragma unroll
                for (int nt = 0; nt < 8; nt++) {
                    uint32_t b0 = __float_as_uint(b0p[nt * 8]);
                    uint32_t b1 = __float_as_uint(b1p[nt * 8]);
                    mma8(acc[0][nt], af[0], b0, b1);
                    mma8(acc[1][nt], af[1], b0, b1);
                }
            }
            __syncthreads();
        }
    }

#pragma unroll
    for (int mt = 0; mt < 2; mt++) {
        int oc = mw * 32 + mt * 16 + r;
        float bv0 = bias[oc];
        float bv8 = bias[oc + 8];
        float* ob = g_v + ((size_t)b * C_ + oc) * NPIX + (r0 + pr) * 128 + xh + 2 * cl;
#pragma unroll
        for (int nt = 0; nt < 8; nt++) {
            float* op = ob + nt * 8;
            *(float2*)op = make_float2(acc[mt][nt][0] + bv0, acc[mt][nt][1] + bv0);
            *(float2*)(op + (size_t)8 * NPIX) =
                make_float2(acc[mt][nt][2] + bv8, acc[mt][nt][3] + bv8);
        }
    }
}

// ======================= weight pack kernels (tf32 round) =======================
__global__ void pack_a(const float* __restrict__ w, float* __restrict__ dst, int total)
{
    int idx = blockIdx.x * 256 + threadIdx.x;
    if (idx < total) dst[idx] = to_tf32(w[idx]);
}
__global__ void pack_fuse(const float* __restrict__ wf, float* __restrict__ dst)
{
    int idx = blockIdx.x * 256 + threadIdx.x;   // [t][oc 96][ic 192]
    if (idx < 9 * 96 * 192) {
        int t = idx / (96 * 192);
        int rem = idx - t * (96 * 192);
        int oc = rem / 192, ic = rem - oc * 192;
        dst[idx] = to_tf32(wf[((size_t)oc * 192 + ic) * 9 + t]);
    }
}
// g_wfin[b][oc][k]: k<96 -> (Wproj @ A_b)[oc][k] ; else wpos[oc][k-96]
__global__ void pack_wfin(const float* __restrict__ wp, const float* __restrict__ wpos)
{
    int idx = blockIdx.x * 256 + threadIdx.x;
    if (idx >= B_ * C2_ * 288) return;
    int b = idx / (C2_ * 288);
    int rem = idx - b * (C2_ * 288);
    int oc = rem / 288, k = rem - oc * 288;
    float v;
    if (k < 96) {
        int h = k >> 4, d = k & 15;
        float s = 0.f;
#pragma unroll
        for (int i = 0; i < 16; i++)
            s = fmaf(wp[oc * 96 + h * 16 + i],
                     g_attn[(((size_t)b * HEADS_ + h) * 16 + i) * 16 + d], s);
        v = s;
    } else {
        v = wpos[(size_t)oc * 192 + (k - 96)];
    }
    g_wfin[idx] = to_tf32(v);
}

// ======================= depthwise 3x3, pad 1 =======================
__global__ void dw3x3_kernel(const float* __restrict__ in, const float* __restrict__ wdw,
                             float* __restrict__ out)
{
    int b = blockIdx.z, c = blockIdx.y;
    int n = blockIdx.x * 256 + threadIdx.x;
    int yy = n >> 7, xx = n & 127;
    const float* ip = in + ((size_t)b * C2_ + c) * NPIX;
    const float* wp = wdw + c * 9;
    float acc = 0.f;
#pragma unroll
    for (int ky = 0; ky < 3; ky++) {
        int gy = yy + ky - 1;
        if ((unsigned)gy < 128u) {
#pragma unroll
            for (int kx = 0; kx < 3; kx++) {
                int gx = xx + kx - 1;
                if ((unsigned)gx < 128u) acc = fmaf(wp[ky * 3 + kx], ip[gy * 128 + gx], acc);
            }
        }
    }
    out[((size_t)b * C2_ + c) * NPIX + n] = acc;
}

// ===== 16x16 gram + inline L2 norms + temperature + softmax per (b,h) =====
#define GR_NC 256
__global__ void attn_kernel(const float* __restrict__ temp)
{
    __shared__ float sq[16][GR_NC + 2];
    __shared__ float sk[16][GR_NC + 2];
    __shared__ float gm[16][17];
    __shared__ float nrm[32];
    int h = blockIdx.x, b = blockIdx.y;
    int tid = threadIdx.x;
    int i = tid >> 4, j = tid & 15;
    int tgt = tid >> 3;            // 0..31: which norm this thread helps
    int toff = (tid & 7) * 32;     // its 32-wide slice
    const float* qb = g_qv + ((size_t)b * C2_ + h * 16) * NPIX;
    const float* kb = g_kv + ((size_t)b * C2_ + h * 16) * NPIX;
    float acc = 0.f, np = 0.f;
    for (int n0 = 0; n0 < NPIX; n0 += GR_NC) {
        for (int idx = tid; idx < 16 * GR_NC; idx += 256) {
            int c = idx >> 8, nn = idx & (GR_NC - 1);
            sq[c][nn] = qb[(size_t)c * NPIX + n0 + nn];
            sk[c][nn] = kb[(size_t)c * NPIX + n0 + nn];
        }
        __syncthreads();
#pragma unroll 4
        for (int nn = 0; nn < GR_NC; nn++) acc = fmaf(sq[i][nn], sk[j][nn], acc);
        {
            const float* src = (tgt < 16) ? sq[tgt] : sk[tgt - 16];
#pragma unroll 8
            for (int u = 0; u < 32; u++) { float v = src[toff + u]; np = fmaf(v, v, np); }
        }
        __syncthreads();
    }
    np += __shfl_down_sync(0xffffffffu, np, 4);
    np += __shfl_down_sync(0xffffffffu, np, 2);
    np += __shfl_down_sync(0xffffffffu, np, 1);
    if ((tid & 7) == 0) nrm[tgt] = np;
    __syncthreads();
    float invq = 1.f / fmaxf(sqrtf(nrm[i]), 1e-12f);
    float invk = 1.f / fmaxf(sqrtf(nrm[16 + j]), 1e-12f);
    gm[i][j] = acc * invq * invk * temp[h];
    __syncthreads();
    if (tid < 16) {
        int ii = tid;
        float m = -1e30f;
        for (int jj = 0; jj < 16; jj++) m = fmaxf(m, gm[ii][jj]);
        float e[16], ssum = 0.f;
        for (int jj = 0; jj < 16; jj++) { e[jj] = expf(gm[ii][jj] - m); ssum += e[jj]; }
        float inv = 1.f / ssum;
        for (int jj = 0; jj < 16; jj++)
            g_attn[(((size_t)b * HEADS_ + h) * 16 + ii) * 16 + jj] = e[jj] * inv;
    }
}

extern "C" void kernel_launch(void* const* d_in, const int* in_sizes, int n_in,
                              void* d_out, int out_size)
{
    const float* x        = (const float*)d_in[0];
    const float* y        = (const float*)d_in[1];
    const float* w_pos    = (const float*)d_in[2];
    const float* w_qv     = (const float*)d_in[3];
    const float* w_qv_dw  = (const float*)d_in[4];
    const float* w_kv     = (const float*)d_in[5];
    const float* w_kv_dw  = (const float*)d_in[6];
    const float* w_proj   = (const float*)d_in[7];
    const float* w_fuse   = (const float*)d_in[8];
    const float* b_fuse   = (const float*)d_in[9];
    const float* temp     = (const float*)d_in[10];
    float* out = (float*)d_out;

    void *pt, *pqv, *pkv, *pv, *pwq, *pwk, *pwft, *pwfin;
    cudaGetSymbolAddress(&pt, g_t);
    cudaGetSymbolAddress(&pqv, g_qv);
    cudaGetSymbolAddress(&pkv, g_kv);
    cudaGetSymbolAddress(&pv, g_v);
    cudaGetSymbolAddress(&pwq, g_wq);
    cudaGetSymbolAddress(&pwk, g_wk);
    cudaGetSymbolAddress(&pwft, g_wft);
    cudaGetSymbolAddress(&pwfin, g_wfin);

    cudaFuncSetAttribute(mma_gemm, cudaFuncAttributeMaxDynamicSharedMemorySize, SMEM_G);
    cudaFuncSetAttribute(fuse_mma, cudaFuncAttributeMaxDynamicSharedMemorySize, SMEM_F);

    // weight packing (tf32-rounded)
    pack_a<<<(C2_ * 96 + 255) / 256, 256>>>(w_qv, (float*)pwq, C2_ * 96);
    pack_a<<<(C2_ * 96 + 255) / 256, 256>>>(w_kv, (float*)pwk, C2_ * 96);
    pack_fuse<<<(9 * 96 * 192 + 255) / 256, 256>>>(w_fuse, (float*)pwft);

    // qv branch (full-image launches — 1024 CTAs)
    mma_gemm<<<dim3(128, B_), 384, SMEM_G>>>(
        x, nullptr, nullptr, (const float*)pwq, (float*)pt, 96, 0);
    dw3x3_kernel<<<dim3(NPIX / 256, C2_, B_), 256>>>((const float*)pt, w_qv_dw, (float*)pqv);
    // kv branch
    mma_gemm<<<dim3(128, B_), 384, SMEM_G>>>(
        y, nullptr, nullptr, (const float*)pwk, (float*)pt, 96, 0);
    dw3x3_kernel<<<dim3(NPIX / 256, C2_, B_), 256>>>((const float*)pt, w_kv_dw, (float*)pkv);
    // v = fuse3x3(cat(v0, v_)) + bias
    fuse_mma<<<dim3(64, B_), 384, SMEM_F>>>((const float*)pwft, b_fuse);
    // attention (gram + norms + softmax in one pass)
    attn_kernel<<<dim3(HEADS_, B_), 256>>>(temp);
    // per-batch fused final weights: [Wproj@A_b | Wpos]
    pack_wfin<<<(B_ * C2_ * 288 + 255) / 256, 256>>>(w_proj, w_pos);
    // final: g_wfin_b @ [v; x; y]
    mma_gemm<<<dim3(128, B_), 384, SMEM_G>>>(
        (const float*)pv, x, y, (const float*)pwfin, out, 288, C2_ * 288);
}

// round 10
// speedup vs baseline: 1.8304x; 1.3202x over previous
#include <cuda_runtime.h>
#include <math.h>
#include <stdint.h>

#define B_    8
#define C_    96
#define C2_   192
#define NPIX  16384
#define HEADS_ 6

__device__ __forceinline__ float to_tf32(float f) {
    unsigned u; asm("cvt.rna.tf32.f32 %0, %1;" : "=r"(u) : "f"(f));
    return __uint_as_float(u);
}
__device__ __forceinline__ void mma8(float* c, const uint32_t* a, uint32_t b0, uint32_t b1) {
    asm volatile("mma.sync.aligned.m16n8k8.row.col.f32.tf32.tf32.f32 "
                 "{%0,%1,%2,%3}, {%4,%5,%6,%7}, {%8,%9}, {%0,%1,%2,%3};"
                 : "+f"(c[0]), "+f"(c[1]), "+f"(c[2]), "+f"(c[3])
                 : "r"(a[0]), "r"(a[1]), "r"(a[2]), "r"(a[3]), "r"(b0), "r"(b1));
}

// ---- device-global scratch ----
__device__ float g_t  [B_ * C2_ * NPIX];
__device__ float g_qv [B_ * C2_ * NPIX];
__device__ float g_kv [B_ * C2_ * NPIX];
__device__ float g_v  [B_ * C_  * NPIX];
__device__ float g_attn[B_ * HEADS_ * 16 * 16];
__device__ float g_gram[B_ * HEADS_ * 16 * 16];
__device__ float g_nrm [B_ * HEADS_ * 32];
__device__ float g_wq  [C2_ * 96];
__device__ float g_wk  [C2_ * 96];
__device__ float g_wft [9 * 96 * 192];
__device__ float g_wfin[B_ * C2_ * 288];

__device__ __forceinline__ int kp(int kin) {   // interleave within 8-k group
    return (kin & 24) + ((kin & 3) << 1) + ((kin >> 2) & 1);
}

// ============== tf32 mma.sync 1x1 GEMM: 192 oc x 128 px, 24 warps ==============
// warps = 12m x 2n, warp tile 16 oc x 64 px -> acc 32 regs.
#define GASTR 40
#define GABUF  (192 * GASTR)
#define GBBUF  (128 * GASTR)
#define GBUFSZ (GABUF + GBBUF)
#define SMEM_G (2 * GBUFSZ * 4)         // 102400 bytes

__global__ __launch_bounds__(768, 1)
void mma_gemm(const float* __restrict__ s0, const float* __restrict__ s1,
              const float* __restrict__ s2, const float* __restrict__ W,
              float* __restrict__ out, int K, int wbstride)
{
    extern __shared__ float sm[];
    const int tid = threadIdx.x;
    const int wid = tid >> 5, lane = tid & 31;
    const int mw = wid >> 1, nw = wid & 1;          // 12 x 2 warps
    const int r = lane >> 2, cl = lane & 3;
    const int b = blockIdx.y;
    const int n0 = blockIdx.x * 128;

    float acc[8][4];
#pragma unroll
    for (int j = 0; j < 8; j++)
#pragma unroll
        for (int q = 0; q < 4; q++) acc[j][q] = 0.f;

    const int nsteps = K / 32;
    const float* Wb = W + (size_t)b * wbstride;

    auto stage = [&](int kc, int buf) {
        float* sA = sm + buf * GBUFSZ;
        float* sB = sA + GABUF;
        const float* wb = Wb + kc * 32;
        for (int i = tid; i < 192 * 32; i += 768) {
            int oc = i >> 5, kin = i & 31;
            sA[oc * GASTR + kp(kin)] = wb[(size_t)oc * K + kin];
        }
        for (int i = tid; i < 128 * 32; i += 768) {
            int c = i >> 7, px = i & 127;
            int cg = kc * 32 + c;
            const float* base = (cg < 96) ? s0 : (cg < 192) ? s1 : s2;
            float v = base[((size_t)b * 96 + (cg % 96)) * NPIX + n0 + px];
            sB[px * GASTR + kp(c)] = to_tf32(v);
        }
    };

    stage(0, 0);
    __syncthreads();
    for (int s = 0; s < nsteps; s++) {
        int buf = s & 1;
        if (s + 1 < nsteps) stage(s + 1, buf ^ 1);
        const float* sA = sm + buf * GBUFSZ;
        const float* sB = sA + GABUF;
#pragma unroll
        for (int ks = 0; ks < 4; ks++) {
            uint32_t af[4];
            {
                int row = mw * 16 + r;
                float2 lo = *(const float2*)(sA + row * GASTR + ks * 8 + cl * 2);
                float2 hi = *(const float2*)(sA + (row + 8) * GASTR + ks * 8 + cl * 2);
                af[0] = __float_as_uint(lo.x);
                af[2] = __float_as_uint(lo.y);
                af[1] = __float_as_uint(hi.x);
                af[3] = __float_as_uint(hi.y);
            }
#pragma unroll
            for (int nt = 0; nt < 8; nt++) {
                int px = nw * 64 + nt * 8 + r;
                float2 bb = *(const float2*)(sB + px * GASTR + ks * 8 + cl * 2);
                mma8(acc[nt], af, __float_as_uint(bb.x), __float_as_uint(bb.y));
            }
        }
        __syncthreads();
    }

    int oc = mw * 16 + r;
    float* ob = out + ((size_t)b * 192 + oc) * NPIX + n0 + nw * 64 + 2 * cl;
#pragma unroll
    for (int nt = 0; nt < 8; nt++) {
        float* op = ob + nt * 8;
        *(float2*)op = make_float2(acc[nt][0], acc[nt][1]);
        *(float2*)(op + (size_t)8 * NPIX) = make_float2(acc[nt][2], acc[nt][3]);
    }
}

// ============== fuse conv 3x3 (192->96): halo-resident taps, 24 warps ==============
// warps = 6m x 4n (2 rows x 2 col-halves), warp tile 16 oc x 64 px.
#define FICSTR 536
#define FROWSTR 132
#define FIN_SZ (32 * FICSTR)
#define FW_SZ  (96 * 40)
#define SMEM_F ((FIN_SZ + 2 * FW_SZ) * 4)

__global__ __launch_bounds__(768, 1)
void fuse_mma(const float* __restrict__ Wt, const float* __restrict__ bias)
{
    extern __shared__ float sm[];
    float* sIn = sm;
    float* sW  = sm + FIN_SZ;
    const int tid = threadIdx.x;
    const int wid = tid >> 5, lane = tid & 31;
    const int mw = wid >> 2, nw = wid & 3;          // 6 x 4 warps
    const int r = lane >> 2, cl = lane & 3;
    const int b = blockIdx.y;
    const int r0 = blockIdx.x * 2;
    const int pr = nw >> 1;
    const int xh = (nw & 1) * 64;

    float acc[8][4];
#pragma unroll
    for (int j = 0; j < 8; j++)
#pragma unroll
        for (int q = 0; q < 4; q++) acc[j][q] = 0.f;

    auto stageW = [&](int kc, int t, int buf) {
        float* dst = sW + buf * FW_SZ;
        const float* wb = Wt + (size_t)t * 96 * 192 + kc * 32;
        for (int i = tid; i < 96 * 32; i += 768) {
            int oc = i >> 5, ic = i & 31;
            dst[oc * 40 + kp(ic)] = wb[(size_t)oc * 192 + ic];
        }
    };

    for (int kc = 0; kc < 6; kc++) {
        __syncthreads();
        {
            int icg0 = kc * 32;
            const float* srcbase = (icg0 < 96)
                ? (g_kv + ((size_t)b * C2_ + 96 + icg0) * NPIX)
                : (g_qv + ((size_t)b * C2_ + icg0) * NPIX);
            for (int seg = wid; seg < 128; seg += 24) {
                int c = seg >> 2, rr = seg & 3;
                int gy = r0 + rr - 1;
                float* drow = sIn + c * FICSTR + rr * FROWSTR;
                const float* srow = srcbase + (size_t)c * NPIX + gy * 128;
                bool rowok = (unsigned)gy < 128u;
#pragma unroll
                for (int cc = lane; cc < 132; cc += 32) {
                    int gx = cc - 1;
                    float v = (rowok && (unsigned)gx < 128u) ? srow[gx] : 0.f;
                    drow[cc] = to_tf32(v);
                }
            }
        }
        stageW(kc, 0, 0);
        __syncthreads();

        for (int t = 0; t < 9; t++) {
            int buf = t & 1;
            if (t + 1 < 9) stageW(kc, t + 1, buf ^ 1);
            int dy = t / 3 - 1, dx = t - (t / 3) * 3 - 1;
            const float* sA = sW + buf * FW_SZ;
            const float* bbase = sIn + (pr + dy + 1) * FROWSTR + xh + dx + 1 + r;
#pragma unroll
            for (int ks = 0; ks < 4; ks++) {
                uint32_t af[4];
                {
                    int row = mw * 16 + r;
                    float2 lo = *(const float2*)(sA + row * 40 + ks * 8 + cl * 2);
                    float2 hi = *(const float2*)(sA + (row + 8) * 40 + ks * 8 + cl * 2);
                    af[0] = __float_as_uint(lo.x);
                    af[2] = __float_as_uint(lo.y);
                    af[1] = __float_as_uint(hi.x);
                    af[3] = __float_as_uint(hi.y);
                }
                const float* b0p = bbase + (ks * 8 + cl) * FICSTR;
                const float* b1p = b0p + 4 * FICSTR;
#pragma unroll
                for (int nt = 0; nt < 8; nt++) {
                    mma8(acc[nt], af,
                         __float_as_uint(b0p[nt * 8]), __float_as_uint(b1p[nt * 8]));
                }
            }
            __syncthreads();
        }
    }

    int oc = mw * 16 + r;
    float bv0 = bias[oc];
    float bv8 = bias[oc + 8];
    float* ob = g_v + ((size_t)b * C_ + oc) * NPIX + (r0 + pr) * 128 + xh + 2 * cl;
#pragma unroll
    for (int nt = 0; nt < 8; nt++) {
        float* op = ob + nt * 8;
        *(float2*)op = make_float2(acc[nt][0] + bv0, acc[nt][1] + bv0);
        *(float2*)(op + (size_t)8 * NPIX) =
            make_float2(acc[nt][2] + bv8, acc[nt][3] + bv8);
    }
}

// ======================= weight pack kernels (tf32 round) =======================
__global__ void pack_a(const float* __restrict__ w, float* __restrict__ dst, int total)
{
    int idx = blockIdx.x * 256 + threadIdx.x;
    if (idx < total) dst[idx] = to_tf32(w[idx]);
}
__global__ void pack_fuse(const float* __restrict__ wf, float* __restrict__ dst)
{
    int idx = blockIdx.x * 256 + threadIdx.x;   // [t][oc 96][ic 192]
    if (idx < 9 * 96 * 192) {
        int t = idx / (96 * 192);
        int rem = idx - t * (96 * 192);
        int oc = rem / 192, ic = rem - oc * 192;
        dst[idx] = to_tf32(wf[((size_t)oc * 192 + ic) * 9 + t]);
    }
}
__global__ void pack_wfin(const float* __restrict__ wp, const float* __restrict__ wpos)
{
    int idx = blockIdx.x * 256 + threadIdx.x;
    if (idx >= B_ * C2_ * 288) return;
    int b = idx / (C2_ * 288);
    int rem = idx - b * (C2_ * 288);
    int oc = rem / 288, k = rem - oc * 288;
    float v;
    if (k < 96) {
        int h = k >> 4, d = k & 15;
        float s = 0.f;
#pragma unroll
        for (int i = 0; i < 16; i++)
            s = fmaf(wp[oc * 96 + h * 16 + i],
                     g_attn[(((size_t)b * HEADS_ + h) * 16 + i) * 16 + d], s);
        v = s;
    } else {
        v = wpos[(size_t)oc * 192 + (k - 96)];
    }
    g_wfin[idx] = to_tf32(v);
}
__global__ void zero_attn_acc()
{
    int idx = blockIdx.x * 256 + threadIdx.x;
    if (idx < B_ * HEADS_ * 256) g_gram[idx] = 0.f;
    if (idx < B_ * HEADS_ * 32) g_nrm[idx] = 0.f;
}

// ======================= depthwise 3x3, pad 1 =======================
__global__ void dw3x3_kernel(const float* __restrict__ in, const float* __restrict__ wdw,
                             float* __restrict__ out)
{
    int b = blockIdx.z, c = blockIdx.y;
    int n = blockIdx.x * 256 + threadIdx.x;
    int yy = n >> 7, xx = n & 127;
    const float* ip = in + ((size_t)b * C2_ + c) * NPIX;
    const float* wp = wdw + c * 9;
    float acc = 0.f;
#pragma unroll
    for (int ky = 0; ky < 3; ky++) {
        int gy = yy + ky - 1;
        if ((unsigned)gy < 128u) {
#pragma unroll
            for (int kx = 0; kx < 3; kx++) {
                int gx = xx + kx - 1;
                if ((unsigned)gx < 128u) acc = fmaf(wp[ky * 3 + kx], ip[gy * 128 + gx], acc);
            }
        }
    }
    out[((size_t)b * C2_ + c) * NPIX + n] = acc;
}

// ===== attention part 1: partial gram + partial norms over 1/8 of pixels =====
#define GR_NC 256
#define NSPLIT 8
__global__ void attn_part()
{
    __shared__ float sq[16][GR_NC + 2];
    __shared__ float sk[16][GR_NC + 2];
    int h = blockIdx.x, b = blockIdx.y, sp = blockIdx.z;
    int tid = threadIdx.x;
    int i = tid >> 4, j = tid & 15;
    int tgt = tid >> 3;
    int toff = (tid & 7) * 32;
    const float* qb = g_qv + ((size_t)b * C2_ + h * 16) * NPIX;
    const float* kb = g_kv + ((size_t)b * C2_ + h * 16) * NPIX;
    float acc = 0.f, np = 0.f;
    int nbeg = sp * (NPIX / NSPLIT), nend = nbeg + NPIX / NSPLIT;
    for (int n0 = nbeg; n0 < nend; n0 += GR_NC) {
        for (int idx = tid; idx < 16 * GR_NC; idx += 256) {
            int c = idx >> 8, nn = idx & (GR_NC - 1);
            sq[c][nn] = qb[(size_t)c * NPIX + n0 + nn];
            sk[c][nn] = kb[(size_t)c * NPIX + n0 + nn];
        }
        __syncthreads();
#pragma unroll 4
        for (int nn = 0; nn < GR_NC; nn++) acc = fmaf(sq[i][nn], sk[j][nn], acc);
        {
            const float* src = (tgt < 16) ? sq[tgt] : sk[tgt - 16];
#pragma unroll 8
            for (int u = 0; u < 32; u++) { float v = src[toff + u]; np = fmaf(v, v, np); }
        }
        __syncthreads();
    }
    atomicAdd(&g_gram[(((size_t)b * HEADS_ + h) * 16 + i) * 16 + j], acc);
    np += __shfl_down_sync(0xffffffffu, np, 4);
    np += __shfl_down_sync(0xffffffffu, np, 2);
    np += __shfl_down_sync(0xffffffffu, np, 1);
    if ((tid & 7) == 0) atomicAdd(&g_nrm[((size_t)b * HEADS_ + h) * 32 + tgt], np);
}

// ===== attention part 2: normalize + temperature + softmax =====
__global__ void attn_soft(const float* __restrict__ temp)
{
    __shared__ float gm[16][17];
    int h = blockIdx.x, b = blockIdx.y;
    int tid = threadIdx.x;
    if (tid < 256) {
        int i = tid >> 4, j = tid & 15;
        const float* nr = g_nrm + ((size_t)b * HEADS_ + h) * 32;
        float invq = 1.f / fmaxf(sqrtf(nr[i]), 1e-12f);
        float invk = 1.f / fmaxf(sqrtf(nr[16 + j]), 1e-12f);
        gm[i][j] = g_gram[(((size_t)b * HEADS_ + h) * 16 + i) * 16 + j]
                   * invq * invk * temp[h];
    }
    __syncthreads();
    if (tid < 16) {
        int ii = tid;
        float m = -1e30f;
        for (int jj = 0; jj < 16; jj++) m = fmaxf(m, gm[ii][jj]);
        float e[16], ssum = 0.f;
        for (int jj = 0; jj < 16; jj++) { e[jj] = expf(gm[ii][jj] - m); ssum += e[jj]; }
        float inv = 1.f / ssum;
        for (int jj = 0; jj < 16; jj++)
            g_attn[(((size_t)b * HEADS_ + h) * 16 + ii) * 16 + jj] = e[jj] * inv;
    }
}

extern "C" void kernel_launch(void* const* d_in, const int* in_sizes, int n_in,
                              void* d_out, int out_size)
{
    const float* x        = (const float*)d_in[0];
    const float* y        = (const float*)d_in[1];
    const float* w_pos    = (const float*)d_in[2];
    const float* w_qv     = (const float*)d_in[3];
    const float* w_qv_dw  = (const float*)d_in[4];
    const float* w_kv     = (const float*)d_in[5];
    const float* w_kv_dw  = (const float*)d_in[6];
    const float* w_proj   = (const float*)d_in[7];
    const float* w_fuse   = (const float*)d_in[8];
    const float* b_fuse   = (const float*)d_in[9];
    const float* temp     = (const float*)d_in[10];
    float* out = (float*)d_out;

    void *pt, *pqv, *pkv, *pv, *pwq, *pwk, *pwft, *pwfin;
    cudaGetSymbolAddress(&pt, g_t);
    cudaGetSymbolAddress(&pqv, g_qv);
    cudaGetSymbolAddress(&pkv, g_kv);
    cudaGetSymbolAddress(&pv, g_v);
    cudaGetSymbolAddress(&pwq, g_wq);
    cudaGetSymbolAddress(&pwk, g_wk);
    cudaGetSymbolAddress(&pwft, g_wft);
    cudaGetSymbolAddress(&pwfin, g_wfin);

    cudaFuncSetAttribute(mma_gemm, cudaFuncAttributeMaxDynamicSharedMemorySize, SMEM_G);
    cudaFuncSetAttribute(fuse_mma, cudaFuncAttributeMaxDynamicSharedMemorySize, SMEM_F);

    pack_a<<<(C2_ * 96 + 255) / 256, 256>>>(w_qv, (float*)pwq, C2_ * 96);
    pack_a<<<(C2_ * 96 + 255) / 256, 256>>>(w_kv, (float*)pwk, C2_ * 96);
    pack_fuse<<<(9 * 96 * 192 + 255) / 256, 256>>>(w_fuse, (float*)pwft);
    zero_attn_acc<<<(B_ * HEADS_ * 256 + 255) / 256, 256>>>();

    // qv branch
    mma_gemm<<<dim3(128, B_), 768, SMEM_G>>>(
        x, nullptr, nullptr, (const float*)pwq, (float*)pt, 96, 0);
    dw3x3_kernel<<<dim3(NPIX / 256, C2_, B_), 256>>>((const float*)pt, w_qv_dw, (float*)pqv);
    // kv branch
    mma_gemm<<<dim3(128, B_), 768, SMEM_G>>>(
        y, nullptr, nullptr, (const float*)pwk, (float*)pt, 96, 0);
    dw3x3_kernel<<<dim3(NPIX / 256, C2_, B_), 256>>>((const float*)pt, w_kv_dw, (float*)pkv);
    // v = fuse3x3(cat(v0, v_)) + bias
    fuse_mma<<<dim3(64, B_), 768, SMEM_F>>>((const float*)pwft, b_fuse);
    // attention: partial gram+norms (384 CTAs), then softmax
    attn_part<<<dim3(HEADS_, B_, NSPLIT), 256>>>();
    attn_soft<<<dim3(HEADS_, B_), 256>>>(temp);
    // per-batch fused final weights: [Wproj@A_b | Wpos]
    pack_wfin<<<(B_ * C2_ * 288 + 255) / 256, 256>>>(w_proj, w_pos);
    // final: g_wfin_b @ [v; x; y]
    mma_gemm<<<dim3(128, B_), 768, SMEM_G>>>(
        (const float*)pv, x, y, (const float*)pwfin, out, 288, C2_ * 288);
}

// round 11
// speedup vs baseline: 2.2336x; 1.2203x over previous
#include <cuda_runtime.h>
#include <math.h>
#include <stdint.h>

#define B_    8
#define C_    96
#define C2_   192
#define NPIX  16384
#define HEADS_ 6

__device__ __forceinline__ float to_tf32(float f) {
    unsigned u; asm("cvt.rna.tf32.f32 %0, %1;" : "=r"(u) : "f"(f));
    return __uint_as_float(u);
}
__device__ __forceinline__ void mma8(float* c, const uint32_t* a, uint32_t b0, uint32_t b1) {
    asm volatile("mma.sync.aligned.m16n8k8.row.col.f32.tf32.tf32.f32 "
                 "{%0,%1,%2,%3}, {%4,%5,%6,%7}, {%8,%9}, {%0,%1,%2,%3};"
                 : "+f"(c[0]), "+f"(c[1]), "+f"(c[2]), "+f"(c[3])
                 : "r"(a[0]), "r"(a[1]), "r"(a[2]), "r"(a[3]), "r"(b0), "r"(b1));
}

// ---- device-global scratch ----
__device__ float g_t  [B_ * C2_ * NPIX];   // qv pre-dw
__device__ float g_t2 [B_ * C2_ * NPIX];   // kv pre-dw
__device__ float g_qv [B_ * C2_ * NPIX];
__device__ float g_kv [B_ * C2_ * NPIX];
__device__ float g_v  [B_ * C_  * NPIX];
__device__ float g_attn[B_ * HEADS_ * 16 * 16];
__device__ float g_gram[B_ * HEADS_ * 16 * 16];
__device__ float g_nrm [B_ * HEADS_ * 32];
__device__ float g_wq  [C2_ * 96];
__device__ float g_wk  [C2_ * 96];
__device__ float g_wft [12 * 9 * 96 * 20];   // [chunk][tap][oc][20] interleaved+padded
__device__ float g_wfin[B_ * C2_ * 288];

__device__ __forceinline__ int kp(int kin) {   // interleave within 8-k group (32-k chunks)
    return (kin & 24) + ((kin & 3) << 1) + ((kin >> 2) & 1);
}
__device__ __forceinline__ int kp16(int k) {   // interleave within 8-k group (16-k chunks)
    return (k & 8) + ((k & 3) << 1) + ((k >> 2) & 1);
}

// ============== tf32 mma.sync 1x1 GEMM: 192 oc x 128 px, 24 warps ==============
#define GASTR 40
#define GABUF  (192 * GASTR)
#define GBBUF  (128 * GASTR)
#define GBUFSZ (GABUF + GBBUF)
#define SMEM_G (2 * GBUFSZ * 4)         // 102400 bytes

__global__ __launch_bounds__(768, 1)
void mma_gemm(const float* __restrict__ s0, const float* __restrict__ s1,
              const float* __restrict__ s2, const float* __restrict__ W,
              float* __restrict__ out, int K, int wbstride)
{
    extern __shared__ float sm[];
    const int tid = threadIdx.x;
    const int wid = tid >> 5, lane = tid & 31;
    const int mw = wid >> 1, nw = wid & 1;          // 12 x 2 warps
    const int r = lane >> 2, cl = lane & 3;
    const int b = blockIdx.y;
    const int n0 = blockIdx.x * 128;

    float acc[8][4];
#pragma unroll
    for (int j = 0; j < 8; j++)
#pragma unroll
        for (int q = 0; q < 4; q++) acc[j][q] = 0.f;

    const int nsteps = K / 32;
    const float* Wb = W + (size_t)b * wbstride;

    auto stage = [&](int kc, int buf) {
        float* sA = sm + buf * GBUFSZ;
        float* sB = sA + GABUF;
        const float* wb = Wb + kc * 32;
        for (int i = tid; i < 192 * 32; i += 768) {
            int oc = i >> 5, kin = i & 31;
            sA[oc * GASTR + kp(kin)] = wb[(size_t)oc * K + kin];
        }
        for (int i = tid; i < 128 * 32; i += 768) {
            int c = i >> 7, px = i & 127;
            int cg = kc * 32 + c;
            const float* base = (cg < 96) ? s0 : (cg < 192) ? s1 : s2;
            float v = base[((size_t)b * 96 + (cg % 96)) * NPIX + n0 + px];
            sB[px * GASTR + kp(c)] = to_tf32(v);
        }
    };

    stage(0, 0);
    __syncthreads();
    for (int s = 0; s < nsteps; s++) {
        int buf = s & 1;
        if (s + 1 < nsteps) stage(s + 1, buf ^ 1);
        const float* sA = sm + buf * GBUFSZ;
        const float* sB = sA + GABUF;
#pragma unroll
        for (int ks = 0; ks < 4; ks++) {
            uint32_t af[4];
            {
                int row = mw * 16 + r;
                float2 lo = *(const float2*)(sA + row * GASTR + ks * 8 + cl * 2);
                float2 hi = *(const float2*)(sA + (row + 8) * GASTR + ks * 8 + cl * 2);
                af[0] = __float_as_uint(lo.x);
                af[2] = __float_as_uint(lo.y);
                af[1] = __float_as_uint(hi.x);
                af[3] = __float_as_uint(hi.y);
            }
#pragma unroll
            for (int nt = 0; nt < 8; nt++) {
                int px = nw * 64 + nt * 8 + r;
                float2 bb = *(const float2*)(sB + px * GASTR + ks * 8 + cl * 2);
                mma8(acc[nt], af, __float_as_uint(bb.x), __float_as_uint(bb.y));
            }
        }
        __syncthreads();
    }

    int oc = mw * 16 + r;
    float* ob = out + ((size_t)b * 192 + oc) * NPIX + n0 + nw * 64 + 2 * cl;
#pragma unroll
    for (int nt = 0; nt < 8; nt++) {
        float* op = ob + nt * 8;
        *(float2*)op = make_float2(acc[nt][0], acc[nt][1]);
        *(float2*)(op + (size_t)8 * NPIX) = make_float2(acc[nt][2], acc[nt][3]);
    }
}

// ============== fuse conv 3x3 (192->96): all-9-taps-resident chunks ==============
// CTA: 96 oc x 256 px (2 out rows). ic chunks of 16:
//   input: 16 ic x 4 rows x 132 cols (halo), double buffered
//   weights: ALL 9 taps x 96 oc x 16 ic, staged once per chunk (float4 copy)
// 24 warps = 6m x 4n (2 rows x 2 col-halves), warp tile 16 oc x 64 px.
#define FICSTR 536
#define FROWSTR 132
#define FIN_SZ (16 * FICSTR)             // 8576 floats per buffer
#define FW_SZ  (9 * 96 * 20)             // 17280 floats
#define SMEM_F ((2 * FIN_SZ + FW_SZ) * 4)  // 137728 bytes

__global__ __launch_bounds__(768, 1)
void fuse_mma(const float* __restrict__ Wt, const float* __restrict__ bias)
{
    extern __shared__ float sm[];
    float* sW = sm + 2 * FIN_SZ;
    const int tid = threadIdx.x;
    const int wid = tid >> 5, lane = tid & 31;
    const int mw = wid >> 2, nw = wid & 3;          // 6 x 4 warps
    const int r = lane >> 2, cl = lane & 3;
    const int b = blockIdx.y;
    const int r0 = blockIdx.x * 2;
    const int pr = nw >> 1;
    const int xh = (nw & 1) * 64;

    float acc[8][4];
#pragma unroll
    for (int j = 0; j < 8; j++)
#pragma unroll
        for (int q = 0; q < 4; q++) acc[j][q] = 0.f;

    auto stage_in = [&](int c, int buf) {
        float* dst = sm + buf * FIN_SZ;
        int icg0 = c * 16;
        const float* srcbase = (icg0 < 96)
            ? (g_kv + ((size_t)b * C2_ + 96 + icg0) * NPIX)
            : (g_qv + ((size_t)b * C2_ + icg0) * NPIX);
        for (int seg = wid; seg < 64; seg += 24) {
            int ic = seg >> 2, rr = seg & 3;
            int gy = r0 + rr - 1;
            float* drow = dst + ic * FICSTR + rr * FROWSTR;
            const float* srow = srcbase + (size_t)ic * NPIX + gy * 128;
            bool rowok = (unsigned)gy < 128u;
#pragma unroll
            for (int cc = lane; cc < 132; cc += 32) {
                int gx = cc - 1;
                float v = (rowok && (unsigned)gx < 128u) ? srow[gx] : 0.f;
                drow[cc] = to_tf32(v);
            }
        }
    };
    auto stageW = [&](int c) {
        const float4* src = (const float4*)(Wt + (size_t)c * FW_SZ);
        float4* dst = (float4*)sW;
        for (int i = tid; i < FW_SZ / 4; i += 768) dst[i] = src[i];
    };

    stage_in(0, 0);
    stageW(0);
    __syncthreads();
    for (int c = 0; c < 12; c++) {
        int buf = c & 1;
        if (c + 1 < 12) stage_in(c + 1, buf ^ 1);
        const float* inb = sm + buf * FIN_SZ;
        // 9 taps, no barriers inside
#pragma unroll
        for (int t = 0; t < 9; t++) {
            int dy = t / 3 - 1, dx = t - (t / 3) * 3 - 1;
            const float* sA = sW + t * (96 * 20);
            const float* bbase = inb + (pr + dy + 1) * FROWSTR + xh + dx + 1 + r;
#pragma unroll
            for (int ks = 0; ks < 2; ks++) {
                uint32_t af[4];
                {
                    int row = mw * 16 + r;
                    float2 lo = *(const float2*)(sA + row * 20 + ks * 8 + cl * 2);
                    float2 hi = *(const float2*)(sA + (row + 8) * 20 + ks * 8 + cl * 2);
                    af[0] = __float_as_uint(lo.x);
                    af[2] = __float_as_uint(lo.y);
                    af[1] = __float_as_uint(hi.x);
                    af[3] = __float_as_uint(hi.y);
                }
                const float* b0p = bbase + (ks * 8 + cl) * FICSTR;
                const float* b1p = b0p + 4 * FICSTR;
#pragma unroll
                for (int nt = 0; nt < 8; nt++) {
                    mma8(acc[nt], af,
                         __float_as_uint(b0p[nt * 8]), __float_as_uint(b1p[nt * 8]));
                }
            }
        }
        __syncthreads();
        if (c + 1 < 12) {
            stageW(c + 1);
            __syncthreads();
        }
    }

    int oc = mw * 16 + r;
    float bv0 = bias[oc];
    float bv8 = bias[oc + 8];
    float* ob = g_v + ((size_t)b * C_ + oc) * NPIX + (r0 + pr) * 128 + xh + 2 * cl;
#pragma unroll
    for (int nt = 0; nt < 8; nt++) {
        float* op = ob + nt * 8;
        *(float2*)op = make_float2(acc[nt][0] + bv0, acc[nt][1] + bv0);
        *(float2*)(op + (size_t)8 * NPIX) =
            make_float2(acc[nt][2] + bv8, acc[nt][3] + bv8);
    }
}

// ======================= weight pack kernels (tf32 round) =======================
__global__ void pack_a(const float* __restrict__ w, float* __restrict__ dst, int total)
{
    int idx = blockIdx.x * 256 + threadIdx.x;
    if (idx < total) dst[idx] = to_tf32(w[idx]);
}
// g_wft layout: [chunk 12][tap 9][oc 96][kp16(ic16) in stride-20 rows]
__global__ void pack_fuse(const float* __restrict__ wf, float* __restrict__ dst)
{
    int idx = blockIdx.x * 256 + threadIdx.x;
    if (idx >= 12 * 9 * 96 * 16) return;
    int ic16 = idx & 15;
    int rem = idx >> 4;
    int oc = rem % 96; rem /= 96;
    int t = rem % 9;
    int chunk = rem / 9;
    int ic = chunk * 16 + ic16;
    dst[(((size_t)chunk * 9 + t) * 96 + oc) * 20 + kp16(ic16)] =
        to_tf32(wf[((size_t)oc * 192 + ic) * 9 + t]);
}
__global__ void pack_wfin(const float* __restrict__ wp, const float* __restrict__ wpos)
{
    int idx = blockIdx.x * 256 + threadIdx.x;
    if (idx >= B_ * C2_ * 288) return;
    int b = idx / (C2_ * 288);
    int rem = idx - b * (C2_ * 288);
    int oc = rem / 288, k = rem - oc * 288;
    float v;
    if (k < 96) {
        int h = k >> 4, d = k & 15;
        float s = 0.f;
#pragma unroll
        for (int i = 0; i < 16; i++)
            s = fmaf(wp[oc * 96 + h * 16 + i],
                     g_attn[(((size_t)b * HEADS_ + h) * 16 + i) * 16 + d], s);
        v = s;
    } else {
        v = wpos[(size_t)oc * 192 + (k - 96)];
    }
    g_wfin[idx] = to_tf32(v);
}
__global__ void zero_attn_acc()
{
    int idx = blockIdx.x * 256 + threadIdx.x;
    if (idx < B_ * HEADS_ * 256) g_gram[idx] = 0.f;
    if (idx < B_ * HEADS_ * 32) g_nrm[idx] = 0.f;
}

// ======= depthwise 3x3, pad 1: 4 px/thread, both branches in one launch =======
__global__ __launch_bounds__(256)
void dw3x3_kernel(const float* __restrict__ wdw0, const float* __restrict__ wdw1)
{
    int z = blockIdx.z;
    int b = z >> 1, br = z & 1;
    int c = blockIdx.y;
    int n4 = (blockIdx.x * 256 + threadIdx.x) * 4;
    int yy = n4 >> 7, x0 = n4 & 127;
    const float* ip = (br ? g_t2 : g_t) + ((size_t)b * C2_ + c) * NPIX;
    const float* wp = (br ? wdw1 : wdw0) + c * 9;
    float* op = (br ? g_kv : g_qv) + ((size_t)b * C2_ + c) * NPIX + n4;

    float a0 = 0.f, a1 = 0.f, a2 = 0.f, a3 = 0.f;
#pragma unroll
    for (int ky = 0; ky < 3; ky++) {
        int gy = yy + ky - 1;
        if ((unsigned)gy >= 128u) continue;
        const float* row = ip + gy * 128 + x0;
        float4 m = *(const float4*)row;
        float lft = (x0 > 0) ? row[-1] : 0.f;
        float rgt = (x0 < 124) ? row[4] : 0.f;
        float w0 = wp[ky * 3], w1 = wp[ky * 3 + 1], w2 = wp[ky * 3 + 2];
        a0 = fmaf(w0, lft, fmaf(w1, m.x, fmaf(w2, m.y, a0)));
        a1 = fmaf(w0, m.x, fmaf(w1, m.y, fmaf(w2, m.z, a1)));
        a2 = fmaf(w0, m.y, fmaf(w1, m.z, fmaf(w2, m.w, a2)));
        a3 = fmaf(w0, m.z, fmaf(w1, m.w, fmaf(w2, rgt, a3)));
    }
    *(float4*)op = make_float4(a0, a1, a2, a3);
}

// ===== attention part 1: partial gram + partial norms over 1/8 of pixels =====
#define GR_NC 256
#define NSPLIT 8
__global__ void attn_part()
{
    __shared__ float sq[16][GR_NC + 2];
    __shared__ float sk[16][GR_NC + 2];
    int h = blockIdx.x, b = blockIdx.y, sp = blockIdx.z;
    int tid = threadIdx.x;
    int i = tid >> 4, j = tid & 15;
    int tgt = tid >> 3;
    int toff = (tid & 7) * 32;
    const float* qb = g_qv + ((size_t)b * C2_ + h * 16) * NPIX;
    const float* kb = g_kv + ((size_t)b * C2_ + h * 16) * NPIX;
    float acc = 0.f, np = 0.f;
    int nbeg = sp * (NPIX / NSPLIT), nend = nbeg + NPIX / NSPLIT;
    for (int n0 = nbeg; n0 < nend; n0 += GR_NC) {
        for (int idx = tid; idx < 16 * GR_NC; idx += 256) {
            int c = idx >> 8, nn = idx & (GR_NC - 1);
            sq[c][nn] = qb[(size_t)c * NPIX + n0 + nn];
            sk[c][nn] = kb[(size_t)c * NPIX + n0 + nn];
        }
        __syncthreads();
#pragma unroll 4
        for (int nn = 0; nn < GR_NC; nn++) acc = fmaf(sq[i][nn], sk[j][nn], acc);
        {
            const float* src = (tgt < 16) ? sq[tgt] : sk[tgt - 16];
#pragma unroll 8
            for (int u = 0; u < 32; u++) { float v = src[toff + u]; np = fmaf(v, v, np); }
        }
        __syncthreads();
    }
    atomicAdd(&g_gram[(((size_t)b * HEADS_ + h) * 16 + i) * 16 + j], acc);
    np += __shfl_down_sync(0xffffffffu, np, 4);
    np += __shfl_down_sync(0xffffffffu, np, 2);
    np += __shfl_down_sync(0xffffffffu, np, 1);
    if ((tid & 7) == 0) atomicAdd(&g_nrm[((size_t)b * HEADS_ + h) * 32 + tgt], np);
}

// ===== attention part 2: normalize + temperature + softmax =====
__global__ void attn_soft(const float* __restrict__ temp)
{
    __shared__ float gm[16][17];
    int h = blockIdx.x, b = blockIdx.y;
    int tid = threadIdx.x;
    if (tid < 256) {
        int i = tid >> 4, j = tid & 15;
        const float* nr = g_nrm + ((size_t)b * HEADS_ + h) * 32;
        float invq = 1.f / fmaxf(sqrtf(nr[i]), 1e-12f);
        float invk = 1.f / fmaxf(sqrtf(nr[16 + j]), 1e-12f);
        gm[i][j] = g_gram[(((size_t)b * HEADS_ + h) * 16 + i) * 16 + j]
                   * invq * invk * temp[h];
    }
    __syncthreads();
    if (tid < 16) {
        int ii = tid;
        float m = -1e30f;
        for (int jj = 0; jj < 16; jj++) m = fmaxf(m, gm[ii][jj]);
        float e[16], ssum = 0.f;
        for (int jj = 0; jj < 16; jj++) { e[jj] = expf(gm[ii][jj] - m); ssum += e[jj]; }
        float inv = 1.f / ssum;
        for (int jj = 0; jj < 16; jj++)
            g_attn[(((size_t)b * HEADS_ + h) * 16 + ii) * 16 + jj] = e[jj] * inv;
    }
}

extern "C" void kernel_launch(void* const* d_in, const int* in_sizes, int n_in,
                              void* d_out, int out_size)
{
    const float* x        = (const float*)d_in[0];
    const float* y        = (const float*)d_in[1];
    const float* w_pos    = (const float*)d_in[2];
    const float* w_qv     = (const float*)d_in[3];
    const float* w_qv_dw  = (const float*)d_in[4];
    const float* w_kv     = (const float*)d_in[5];
    const float* w_kv_dw  = (const float*)d_in[6];
    const float* w_proj   = (const float*)d_in[7];
    const float* w_fuse   = (const float*)d_in[8];
    const float* b_fuse   = (const float*)d_in[9];
    const float* temp     = (const float*)d_in[10];
    float* out = (float*)d_out;

    void *pt, *pt2, *pv, *pwq, *pwk, *pwft, *pwfin;
    cudaGetSymbolAddress(&pt, g_t);
    cudaGetSymbolAddress(&pt2, g_t2);
    cudaGetSymbolAddress(&pv, g_v);
    cudaGetSymbolAddress(&pwq, g_wq);
    cudaGetSymbolAddress(&pwk, g_wk);
    cudaGetSymbolAddress(&pwft, g_wft);
    cudaGetSymbolAddress(&pwfin, g_wfin);

    cudaFuncSetAttribute(mma_gemm, cudaFuncAttributeMaxDynamicSharedMemorySize, SMEM_G);
    cudaFuncSetAttribute(fuse_mma, cudaFuncAttributeMaxDynamicSharedMemorySize, SMEM_F);

    pack_a<<<(C2_ * 96 + 255) / 256, 256>>>(w_qv, (float*)pwq, C2_ * 96);
    pack_a<<<(C2_ * 96 + 255) / 256, 256>>>(w_kv, (float*)pwk, C2_ * 96);
    pack_fuse<<<(12 * 9 * 96 * 16 + 255) / 256, 256>>>(w_fuse, (float*)pwft);
    zero_attn_acc<<<(B_ * HEADS_ * 256 + 255) / 256, 256>>>();

    // q/k 1x1 GEMMs
    mma_gemm<<<dim3(128, B_), 768, SMEM_G>>>(
        x, nullptr, nullptr, (const float*)pwq, (float*)pt, 96, 0);
    mma_gemm<<<dim3(128, B_), 768, SMEM_G>>>(
        y, nullptr, nullptr, (const float*)pwk, (float*)pt2, 96, 0);
    // depthwise for both branches, 4 px/thread
    dw3x3_kernel<<<dim3(16, C2_, 2 * B_), 256>>>(w_qv_dw, w_kv_dw);
    // v = fuse3x3(cat(v0, v_)) + bias
    fuse_mma<<<dim3(64, B_), 768, SMEM_F>>>((const float*)pwft, b_fuse);
    // attention: partial gram+norms (384 CTAs), then softmax
    attn_part<<<dim3(HEADS_, B_, NSPLIT), 256>>>();
    attn_soft<<<dim3(HEADS_, B_), 256>>>(temp);
    // per-batch fused final weights: [Wproj@A_b | Wpos]
    pack_wfin<<<(B_ * C2_ * 288 + 255) / 256, 256>>>(w_proj, w_pos);
    // final: g_wfin_b @ [v; x; y]
    mma_gemm<<<dim3(128, B_), 768, SMEM_G>>>(
        (const float*)pv, x, y, (const float*)pwfin, out, 288, C2_ * 288);
}

// round 12
// speedup vs baseline: 2.2943x; 1.0272x over previous
#include <cuda_runtime.h>
#include <cuda_fp16.h>
#include <math.h>
#include <stdint.h>

#define B_    8
#define C_    96
#define C2_   192
#define NPIX  16384
#define HEADS_ 6

__device__ __forceinline__ float to_tf32(float f) {
    unsigned u; asm("cvt.rna.tf32.f32 %0, %1;" : "=r"(u) : "f"(f));
    return __uint_as_float(u);
}
__device__ __forceinline__ void mma8(float* c, const uint32_t* a, uint32_t b0, uint32_t b1) {
    asm volatile("mma.sync.aligned.m16n8k8.row.col.f32.tf32.tf32.f32 "
                 "{%0,%1,%2,%3}, {%4,%5,%6,%7}, {%8,%9}, {%0,%1,%2,%3};"
                 : "+f"(c[0]), "+f"(c[1]), "+f"(c[2]), "+f"(c[3])
                 : "r"(a[0]), "r"(a[1]), "r"(a[2]), "r"(a[3]), "r"(b0), "r"(b1));
}

// ---- device-global scratch (intermediates in fp16: same 11-bit significand as tf32) ----
__device__ __half g_t  [B_ * C2_ * NPIX];   // qv pre-dw
__device__ __half g_t2 [B_ * C2_ * NPIX];   // kv pre-dw
__device__ __half g_qv [B_ * C2_ * NPIX];
__device__ __half g_kv [B_ * C2_ * NPIX];
__device__ __half g_v  [B_ * C_  * NPIX];
__device__ float g_attn[B_ * HEADS_ * 16 * 16];
__device__ float g_gram[B_ * HEADS_ * 16 * 16];
__device__ float g_nrm [B_ * HEADS_ * 32];
__device__ float g_wq  [C2_ * 96];
__device__ float g_wk  [C2_ * 96];
__device__ float g_wft [12 * 9 * 96 * 20];
__device__ float g_wfin[B_ * C2_ * 288];

__device__ __forceinline__ int kp(int kin) {
    return (kin & 24) + ((kin & 3) << 1) + ((kin >> 2) & 1);
}
__device__ __forceinline__ int kp16(int k) {
    return (k & 8) + ((k & 3) << 1) + ((k >> 2) & 1);
}

// ============== tf32 mma.sync 1x1 GEMM: 192 oc x 128 px, 24 warps ==============
#define GASTR 40
#define GABUF  (192 * GASTR)
#define GBBUF  (128 * GASTR)
#define GBUFSZ (GABUF + GBBUF)
#define SMEM_G (2 * GBUFSZ * 4)         // 102400 bytes

__global__ __launch_bounds__(768, 1)
void mma_gemm(const void* s0, const void* s1, const void* s2,
              const float* __restrict__ W, void* out, int K, int wbstride,
              int halfmask, int outhalf)
{
    extern __shared__ float sm[];
    const int tid = threadIdx.x;
    const int wid = tid >> 5, lane = tid & 31;
    const int mw = wid >> 1, nw = wid & 1;          // 12 x 2 warps
    const int r = lane >> 2, cl = lane & 3;
    const int b = blockIdx.y;
    const int n0 = blockIdx.x * 128;

    float acc[8][4];
#pragma unroll
    for (int j = 0; j < 8; j++)
#pragma unroll
        for (int q = 0; q < 4; q++) acc[j][q] = 0.f;

    const int nsteps = K / 32;
    const float* Wb = W + (size_t)b * wbstride;

    auto stage = [&](int kc, int buf) {
        float* sA = sm + buf * GBUFSZ;
        float* sB = sA + GABUF;
        const float* wb = Wb + kc * 32;
        for (int i = tid; i < 192 * 32; i += 768) {
            int oc = i >> 5, kin = i & 31;
            sA[oc * GASTR + kp(kin)] = wb[(size_t)oc * K + kin];
        }
        for (int i = tid; i < 128 * 32; i += 768) {
            int c = i >> 7, px = i & 127;
            int cg = kc * 32 + c;
            int ci = (cg < 96) ? 0 : (cg < 192) ? 1 : 2;
            const void* base = (ci == 0) ? s0 : (ci == 1) ? s1 : s2;
            size_t off = ((size_t)b * 96 + (cg % 96)) * NPIX + n0 + px;
            float v = ((halfmask >> ci) & 1)
                ? __half2float(((const __half*)base)[off])
                : to_tf32(((const float*)base)[off]);
            sB[px * GASTR + kp(c)] = v;
        }
    };

    stage(0, 0);
    __syncthreads();
    for (int s = 0; s < nsteps; s++) {
        int buf = s & 1;
        if (s + 1 < nsteps) stage(s + 1, buf ^ 1);
        const float* sA = sm + buf * GBUFSZ;
        const float* sB = sA + GABUF;
#pragma unroll
        for (int ks = 0; ks < 4; ks++) {
            uint32_t af[4];
            {
                int row = mw * 16 + r;
                float2 lo = *(const float2*)(sA + row * GASTR + ks * 8 + cl * 2);
                float2 hi = *(const float2*)(sA + (row + 8) * GASTR + ks * 8 + cl * 2);
                af[0] = __float_as_uint(lo.x);
                af[2] = __float_as_uint(lo.y);
                af[1] = __float_as_uint(hi.x);
                af[3] = __float_as_uint(hi.y);
            }
#pragma unroll
            for (int nt = 0; nt < 8; nt++) {
                int px = nw * 64 + nt * 8 + r;
                float2 bb = *(const float2*)(sB + px * GASTR + ks * 8 + cl * 2);
                mma8(acc[nt], af, __float_as_uint(bb.x), __float_as_uint(bb.y));
            }
        }
        __syncthreads();
    }

    int oc = mw * 16 + r;
    size_t obase = ((size_t)b * 192 + oc) * NPIX + n0 + nw * 64 + 2 * cl;
    if (outhalf) {
        __half* ob = (__half*)out + obase;
#pragma unroll
        for (int nt = 0; nt < 8; nt++) {
            __half* op = ob + nt * 8;
            *(__half2*)op = __floats2half2_rn(acc[nt][0], acc[nt][1]);
            *(__half2*)(op + (size_t)8 * NPIX) = __floats2half2_rn(acc[nt][2], acc[nt][3]);
        }
    } else {
        float* ob = (float*)out + obase;
#pragma unroll
        for (int nt = 0; nt < 8; nt++) {
            float* op = ob + nt * 8;
            *(float2*)op = make_float2(acc[nt][0], acc[nt][1]);
            *(float2*)(op + (size_t)8 * NPIX) = make_float2(acc[nt][2], acc[nt][3]);
        }
    }
}

// ============== fuse conv 3x3 (192->96): all-9-taps-resident chunks ==============
#define FICSTR 536
#define FROWSTR 132
#define FIN_SZ (16 * FICSTR)
#define FW_SZ  (9 * 96 * 20)
#define SMEM_F ((2 * FIN_SZ + FW_SZ) * 4)  // 137728 bytes

__global__ __launch_bounds__(768, 1)
void fuse_mma(const float* __restrict__ Wt, const float* __restrict__ bias)
{
    extern __shared__ float sm[];
    float* sW = sm + 2 * FIN_SZ;
    const int tid = threadIdx.x;
    const int wid = tid >> 5, lane = tid & 31;
    const int mw = wid >> 2, nw = wid & 3;          // 6 x 4 warps
    const int r = lane >> 2, cl = lane & 3;
    const int b = blockIdx.y;
    const int r0 = blockIdx.x * 2;
    const int pr = nw >> 1;
    const int xh = (nw & 1) * 64;

    float acc[8][4];
#pragma unroll
    for (int j = 0; j < 8; j++)
#pragma unroll
        for (int q = 0; q < 4; q++) acc[j][q] = 0.f;

    auto stage_in = [&](int c, int buf) {
        float* dst = sm + buf * FIN_SZ;
        int icg0 = c * 16;
        const __half* srcbase = (icg0 < 96)
            ? (g_kv + ((size_t)b * C2_ + 96 + icg0) * NPIX)
            : (g_qv + ((size_t)b * C2_ + icg0) * NPIX);
        for (int seg = wid; seg < 64; seg += 24) {
            int ic = seg >> 2, rr = seg & 3;
            int gy = r0 + rr - 1;
            float* drow = dst + ic * FICSTR + rr * FROWSTR;
            const __half* srow = srcbase + (size_t)ic * NPIX + gy * 128;
            bool rowok = (unsigned)gy < 128u;
#pragma unroll
            for (int cc = lane; cc < 132; cc += 32) {
                int gx = cc - 1;
                float v = (rowok && (unsigned)gx < 128u) ? __half2float(srow[gx]) : 0.f;
                drow[cc] = v;
            }
        }
    };
    auto stageW = [&](int c) {
        const float4* src = (const float4*)(Wt + (size_t)c * FW_SZ);
        float4* dst = (float4*)sW;
        for (int i = tid; i < FW_SZ / 4; i += 768) dst[i] = src[i];
    };

    stage_in(0, 0);
    stageW(0);
    __syncthreads();
    for (int c = 0; c < 12; c++) {
        int buf = c & 1;
        if (c + 1 < 12) stage_in(c + 1, buf ^ 1);
        const float* inb = sm + buf * FIN_SZ;
#pragma unroll
        for (int t = 0; t < 9; t++) {
            int dy = t / 3 - 1, dx = t - (t / 3) * 3 - 1;
            const float* sA = sW + t * (96 * 20);
            const float* bbase = inb + (pr + dy + 1) * FROWSTR + xh + dx + 1 + r;
#pragma unroll
            for (int ks = 0; ks < 2; ks++) {
                uint32_t af[4];
                {
                    int row = mw * 16 + r;
                    float2 lo = *(const float2*)(sA + row * 20 + ks * 8 + cl * 2);
                    float2 hi = *(const float2*)(sA + (row + 8) * 20 + ks * 8 + cl * 2);
                    af[0] = __float_as_uint(lo.x);
                    af[2] = __float_as_uint(lo.y);
                    af[1] = __float_as_uint(hi.x);
                    af[3] = __float_as_uint(hi.y);
                }
                const float* b0p = bbase + (ks * 8 + cl) * FICSTR;
                const float* b1p = b0p + 4 * FICSTR;
#pragma unroll
                for (int nt = 0; nt < 8; nt++) {
                    mma8(acc[nt], af,
                         __float_as_uint(b0p[nt * 8]), __float_as_uint(b1p[nt * 8]));
                }
            }
        }
        __syncthreads();
        if (c + 1 < 12) {
            stageW(c + 1);
            __syncthreads();
        }
    }

    int oc = mw * 16 + r;
    float bv0 = bias[oc];
    float bv8 = bias[oc + 8];
    __half* ob = g_v + ((size_t)b * C_ + oc) * NPIX + (r0 + pr) * 128 + xh + 2 * cl;
#pragma unroll
    for (int nt = 0; nt < 8; nt++) {
        __half* op = ob + nt * 8;
        *(__half2*)op = __floats2half2_rn(acc[nt][0] + bv0, acc[nt][1] + bv0);
        *(__half2*)(op + (size_t)8 * NPIX) =
            __floats2half2_rn(acc[nt][2] + bv8, acc[nt][3] + bv8);
    }
}

// ======================= weight pack kernels (tf32 round) =======================
__global__ void pack_a(const float* __restrict__ w, float* __restrict__ dst, int total)
{
    int idx = blockIdx.x * 256 + threadIdx.x;
    if (idx < total) dst[idx] = to_tf32(w[idx]);
}
__global__ void pack_fuse(const float* __restrict__ wf, float* __restrict__ dst)
{
    int idx = blockIdx.x * 256 + threadIdx.x;
    if (idx >= 12 * 9 * 96 * 16) return;
    int ic16 = idx & 15;
    int rem = idx >> 4;
    int oc = rem % 96; rem /= 96;
    int t = rem % 9;
    int chunk = rem / 9;
    int ic = chunk * 16 + ic16;
    dst[(((size_t)chunk * 9 + t) * 96 + oc) * 20 + kp16(ic16)] =
        to_tf32(wf[((size_t)oc * 192 + ic) * 9 + t]);
}
__global__ void pack_wfin(const float* __restrict__ wp, const float* __restrict__ wpos)
{
    int idx = blockIdx.x * 256 + threadIdx.x;
    if (idx >= B_ * C2_ * 288) return;
    int b = idx / (C2_ * 288);
    int rem = idx - b * (C2_ * 288);
    int oc = rem / 288, k = rem - oc * 288;
    float v;
    if (k < 96) {
        int h = k >> 4, d = k & 15;
        float s = 0.f;
#pragma unroll
        for (int i = 0; i < 16; i++)
            s = fmaf(wp[oc * 96 + h * 16 + i],
                     g_attn[(((size_t)b * HEADS_ + h) * 16 + i) * 16 + d], s);
        v = s;
    } else {
        v = wpos[(size_t)oc * 192 + (k - 96)];
    }
    g_wfin[idx] = to_tf32(v);
}
__global__ void zero_attn_acc()
{
    int idx = blockIdx.x * 256 + threadIdx.x;
    if (idx < B_ * HEADS_ * 256) g_gram[idx] = 0.f;
    if (idx < B_ * HEADS_ * 32) g_nrm[idx] = 0.f;
}

// ======= depthwise 3x3, pad 1: 4 px/thread, fp16 in/out, both branches =======
__global__ __launch_bounds__(256)
void dw3x3_kernel(const float* __restrict__ wdw0, const float* __restrict__ wdw1)
{
    int z = blockIdx.z;
    int b = z >> 1, br = z & 1;
    int c = blockIdx.y;
    int n4 = (blockIdx.x * 256 + threadIdx.x) * 4;
    int yy = n4 >> 7, x0 = n4 & 127;
    const __half* ip = (br ? g_t2 : g_t) + ((size_t)b * C2_ + c) * NPIX;
    const float* wp = (br ? wdw1 : wdw0) + c * 9;
    __half* op = (br ? g_kv : g_qv) + ((size_t)b * C2_ + c) * NPIX + n4;

    float a0 = 0.f, a1 = 0.f, a2 = 0.f, a3 = 0.f;
#pragma unroll
    for (int ky = 0; ky < 3; ky++) {
        int gy = yy + ky - 1;
        if ((unsigned)gy >= 128u) continue;
        const __half* row = ip + gy * 128 + x0;
        float2 h01 = __half22float2(*(const __half2*)row);
        float2 h23 = __half22float2(*(const __half2*)(row + 2));
        float lft = (x0 > 0) ? __half2float(row[-1]) : 0.f;
        float rgt = (x0 < 124) ? __half2float(row[4]) : 0.f;
        float w0 = wp[ky * 3], w1 = wp[ky * 3 + 1], w2 = wp[ky * 3 + 2];
        a0 = fmaf(w0, lft,   fmaf(w1, h01.x, fmaf(w2, h01.y, a0)));
        a1 = fmaf(w0, h01.x, fmaf(w1, h01.y, fmaf(w2, h23.x, a1)));
        a2 = fmaf(w0, h01.y, fmaf(w1, h23.x, fmaf(w2, h23.y, a2)));
        a3 = fmaf(w0, h23.x, fmaf(w1, h23.y, fmaf(w2, rgt,   a3)));
    }
    *(__half2*)op = __floats2half2_rn(a0, a1);
    *(__half2*)(op + 2) = __floats2half2_rn(a2, a3);
}

// ===== attention part 1: partial gram + partial norms over 1/8 of pixels =====
#define GR_NC 256
#define NSPLIT 8
__global__ void attn_part()
{
    __shared__ float sq[16][GR_NC + 2];
    __shared__ float sk[16][GR_NC + 2];
    int h = blockIdx.x, b = blockIdx.y, sp = blockIdx.z;
    int tid = threadIdx.x;
    int i = tid >> 4, j = tid & 15;
    int tgt = tid >> 3;
    int toff = (tid & 7) * 32;
    const __half* qb = g_qv + ((size_t)b * C2_ + h * 16) * NPIX;
    const __half* kb = g_kv + ((size_t)b * C2_ + h * 16) * NPIX;
    float acc = 0.f, np = 0.f;
    int nbeg = sp * (NPIX / NSPLIT), nend = nbeg + NPIX / NSPLIT;
    for (int n0 = nbeg; n0 < nend; n0 += GR_NC) {
        for (int idx = tid; idx < 16 * GR_NC; idx += 256) {
            int c = idx >> 8, nn = idx & (GR_NC - 1);
            sq[c][nn] = __half2float(qb[(size_t)c * NPIX + n0 + nn]);
            sk[c][nn] = __half2float(kb[(size_t)c * NPIX + n0 + nn]);
        }
        __syncthreads();
#pragma unroll 4
        for (int nn = 0; nn < GR_NC; nn++) acc = fmaf(sq[i][nn], sk[j][nn], acc);
        {
            const float* src = (tgt < 16) ? sq[tgt] : sk[tgt - 16];
#pragma unroll 8
            for (int u = 0; u < 32; u++) { float v = src[toff + u]; np = fmaf(v, v, np); }
        }
        __syncthreads();
    }
    atomicAdd(&g_gram[(((size_t)b * HEADS_ + h) * 16 + i) * 16 + j], acc);
    np += __shfl_down_sync(0xffffffffu, np, 4);
    np += __shfl_down_sync(0xffffffffu, np, 2);
    np += __shfl_down_sync(0xffffffffu, np, 1);
    if ((tid & 7) == 0) atomicAdd(&g_nrm[((size_t)b * HEADS_ + h) * 32 + tgt], np);
}

// ===== attention part 2: normalize + temperature + softmax =====
__global__ void attn_soft(const float* __restrict__ temp)
{
    __shared__ float gm[16][17];
    int h = blockIdx.x, b = blockIdx.y;
    int tid = threadIdx.x;
    if (tid < 256) {
        int i = tid >> 4, j = tid & 15;
        const float* nr = g_nrm + ((size_t)b * HEADS_ + h) * 32;
        float invq = 1.f / fmaxf(sqrtf(nr[i]), 1e-12f);
        float invk = 1.f / fmaxf(sqrtf(nr[16 + j]), 1e-12f);
        gm[i][j] = g_gram[(((size_t)b * HEADS_ + h) * 16 + i) * 16 + j]
                   * invq * invk * temp[h];
    }
    __syncthreads();
    if (tid < 16) {
        int ii = tid;
        float m = -1e30f;
        for (int jj = 0; jj < 16; jj++) m = fmaxf(m, gm[ii][jj]);
        float e[16], ssum = 0.f;
        for (int jj = 0; jj < 16; jj++) { e[jj] = expf(gm[ii][jj] - m); ssum += e[jj]; }
        float inv = 1.f / ssum;
        for (int jj = 0; jj < 16; jj++)
            g_attn[(((size_t)b * HEADS_ + h) * 16 + ii) * 16 + jj] = e[jj] * inv;
    }
}

extern "C" void kernel_launch(void* const* d_in, const int* in_sizes, int n_in,
                              void* d_out, int out_size)
{
    const float* x        = (const float*)d_in[0];
    const float* y        = (const float*)d_in[1];
    const float* w_pos    = (const float*)d_in[2];
    const float* w_qv     = (const float*)d_in[3];
    const float* w_qv_dw  = (const float*)d_in[4];
    const float* w_kv     = (const float*)d_in[5];
    const float* w_kv_dw  = (const float*)d_in[6];
    const float* w_proj   = (const float*)d_in[7];
    const float* w_fuse   = (const float*)d_in[8];
    const float* b_fuse   = (const float*)d_in[9];
    const float* temp     = (const float*)d_in[10];
    float* out = (float*)d_out;

    void *pt, *pt2, *pv, *pwq, *pwk, *pwft, *pwfin;
    cudaGetSymbolAddress(&pt, g_t);
    cudaGetSymbolAddress(&pt2, g_t2);
    cudaGetSymbolAddress(&pv, g_v);
    cudaGetSymbolAddress(&pwq, g_wq);
    cudaGetSymbolAddress(&pwk, g_wk);
    cudaGetSymbolAddress(&pwft, g_wft);
    cudaGetSymbolAddress(&pwfin, g_wfin);

    cudaFuncSetAttribute(mma_gemm, cudaFuncAttributeMaxDynamicSharedMemorySize, SMEM_G);
    cudaFuncSetAttribute(fuse_mma, cudaFuncAttributeMaxDynamicSharedMemorySize, SMEM_F);

    pack_a<<<(C2_ * 96 + 255) / 256, 256>>>(w_qv, (float*)pwq, C2_ * 96);
    pack_a<<<(C2_ * 96 + 255) / 256, 256>>>(w_kv, (float*)pwk, C2_ * 96);
    pack_fuse<<<(12 * 9 * 96 * 16 + 255) / 256, 256>>>(w_fuse, (float*)pwft);
    zero_attn_acc<<<(B_ * HEADS_ * 256 + 255) / 256, 256>>>();

    // q/k 1x1 GEMMs (fp32 in, fp16 out)
    mma_gemm<<<dim3(128, B_), 768, SMEM_G>>>(
        x, nullptr, nullptr, (const float*)pwq, pt, 96, 0, 0, 1);
    mma_gemm<<<dim3(128, B_), 768, SMEM_G>>>(
        y, nullptr, nullptr, (const float*)pwk, pt2, 96, 0, 0, 1);
    // depthwise for both branches, 4 px/thread, fp16
    dw3x3_kernel<<<dim3(16, C2_, 2 * B_), 256>>>(w_qv_dw, w_kv_dw);
    // v = fuse3x3(cat(v0, v_)) + bias (fp16 in/out)
    fuse_mma<<<dim3(64, B_), 768, SMEM_F>>>((const float*)pwft, b_fuse);
    // attention: partial gram+norms, then softmax
    attn_part<<<dim3(HEADS_, B_, NSPLIT), 256>>>();
    attn_soft<<<dim3(HEADS_, B_), 256>>>(temp);
    // per-batch fused final weights: [Wproj@A_b | Wpos]
    pack_wfin<<<(B_ * C2_ * 288 + 255) / 256, 256>>>(w_proj, w_pos);
    // final: g_wfin_b @ [v(fp16); x; y] -> fp32 out
    mma_gemm<<<dim3(128, B_), 768, SMEM_G>>>(
        pv, x, y, (const float*)pwfin, out, 288, C2_ * 288, 0b001, 0);
}

// round 13
// speedup vs baseline: 2.3206x; 1.0114x over previous
#include <cuda_runtime.h>
#include <cuda_fp16.h>
#include <math.h>
#include <stdint.h>

#define B_    8
#define C_    96
#define C2_   192
#define NPIX  16384
#define HEADS_ 6

__device__ __forceinline__ float to_tf32(float f) {
    unsigned u; asm("cvt.rna.tf32.f32 %0, %1;" : "=r"(u) : "f"(f));
    return __uint_as_float(u);
}
__device__ __forceinline__ void mma8(float* c, const uint32_t* a, uint32_t b0, uint32_t b1) {
    asm volatile("mma.sync.aligned.m16n8k8.row.col.f32.tf32.tf32.f32 "
                 "{%0,%1,%2,%3}, {%4,%5,%6,%7}, {%8,%9}, {%0,%1,%2,%3};"
                 : "+f"(c[0]), "+f"(c[1]), "+f"(c[2]), "+f"(c[3])
                 : "r"(a[0]), "r"(a[1]), "r"(a[2]), "r"(a[3]), "r"(b0), "r"(b1));
}

// ---- device-global scratch (intermediates in fp16: same 11-bit significand as tf32) ----
__device__ __half g_t  [B_ * C2_ * NPIX];   // qv pre-dw
__device__ __half g_t2 [B_ * C2_ * NPIX];   // kv pre-dw
__device__ __half g_qv [B_ * C2_ * NPIX];
__device__ __half g_kv [B_ * C2_ * NPIX];
__device__ __half g_v  [B_ * C_  * NPIX];
__device__ float g_attn[B_ * HEADS_ * 16 * 16];
__device__ float g_gram[B_ * HEADS_ * 16 * 16];
__device__ float g_nrm [B_ * HEADS_ * 32];
__device__ float g_wq  [C2_ * 96];
__device__ float g_wk  [C2_ * 96];
__device__ float g_wft [12 * 9 * 96 * 20];
__device__ float g_wfin[B_ * C2_ * 288];

__device__ __forceinline__ int kp(int kin) {
    return (kin & 24) + ((kin & 3) << 1) + ((kin >> 2) & 1);
}
__device__ __forceinline__ int kp16(int k) {
    return (k & 8) + ((k & 3) << 1) + ((k >> 2) & 1);
}

// ============== tf32 mma.sync 1x1 GEMM: 192 oc x 128 px, 24 warps ==============
#define GASTR 40
#define GABUF  (192 * GASTR)
#define GBBUF  (128 * GASTR)
#define GBUFSZ (GABUF + GBBUF)
#define SMEM_G (2 * GBUFSZ * 4)         // 102400 bytes

__global__ __launch_bounds__(768, 1)
void mma_gemm(const void* s0, const void* s1, const void* s2,
              const float* __restrict__ W, void* out, int K, int wbstride,
              int halfmask, int outhalf)
{
    extern __shared__ float sm[];
    const int tid = threadIdx.x;
    const int wid = tid >> 5, lane = tid & 31;
    const int mw = wid >> 1, nw = wid & 1;          // 12 x 2 warps
    const int r = lane >> 2, cl = lane & 3;
    const int b = blockIdx.y;
    const int n0 = blockIdx.x * 128;

    float acc[8][4];
#pragma unroll
    for (int j = 0; j < 8; j++)
#pragma unroll
        for (int q = 0; q < 4; q++) acc[j][q] = 0.f;

    const int nsteps = K / 32;
    const float* Wb = W + (size_t)b * wbstride;

    auto stage = [&](int kc, int buf) {
        float* sA = sm + buf * GBUFSZ;
        float* sB = sA + GABUF;
        const float* wb = Wb + kc * 32;
        for (int i = tid; i < 192 * 32; i += 768) {
            int oc = i >> 5, kin = i & 31;
            sA[oc * GASTR + kp(kin)] = wb[(size_t)oc * K + kin];
        }
        for (int i = tid; i < 128 * 32; i += 768) {
            int c = i >> 7, px = i & 127;
            int cg = kc * 32 + c;
            int ci = (cg < 96) ? 0 : (cg < 192) ? 1 : 2;
            const void* base = (ci == 0) ? s0 : (ci == 1) ? s1 : s2;
            size_t off = ((size_t)b * 96 + (cg % 96)) * NPIX + n0 + px;
            float v = ((halfmask >> ci) & 1)
                ? __half2float(((const __half*)base)[off])
                : to_tf32(((const float*)base)[off]);
            sB[px * GASTR + kp(c)] = v;
        }
    };

    stage(0, 0);
    __syncthreads();
    for (int s = 0; s < nsteps; s++) {
        int buf = s & 1;
        if (s + 1 < nsteps) stage(s + 1, buf ^ 1);
        const float* sA = sm + buf * GBUFSZ;
        const float* sB = sA + GABUF;
#pragma unroll
        for (int ks = 0; ks < 4; ks++) {
            uint32_t af[4];
            {
                int row = mw * 16 + r;
                float2 lo = *(const float2*)(sA + row * GASTR + ks * 8 + cl * 2);
                float2 hi = *(const float2*)(sA + (row + 8) * GASTR + ks * 8 + cl * 2);
                af[0] = __float_as_uint(lo.x);
                af[2] = __float_as_uint(lo.y);
                af[1] = __float_as_uint(hi.x);
                af[3] = __float_as_uint(hi.y);
            }
#pragma unroll
            for (int nt = 0; nt < 8; nt++) {
                int px = nw * 64 + nt * 8 + r;
                float2 bb = *(const float2*)(sB + px * GASTR + ks * 8 + cl * 2);
                mma8(acc[nt], af, __float_as_uint(bb.x), __float_as_uint(bb.y));
            }
        }
        __syncthreads();
    }

    int oc = mw * 16 + r;
    size_t obase = ((size_t)b * 192 + oc) * NPIX + n0 + nw * 64 + 2 * cl;
    if (outhalf) {
        __half* ob = (__half*)out + obase;
#pragma unroll
        for (int nt = 0; nt < 8; nt++) {
            __half* op = ob + nt * 8;
            *(__half2*)op = __floats2half2_rn(acc[nt][0], acc[nt][1]);
            *(__half2*)(op + (size_t)8 * NPIX) = __floats2half2_rn(acc[nt][2], acc[nt][3]);
        }
    } else {
        float* ob = (float*)out + obase;
#pragma unroll
        for (int nt = 0; nt < 8; nt++) {
            float* op = ob + nt * 8;
            *(float2*)op = make_float2(acc[nt][0], acc[nt][1]);
            *(float2*)(op + (size_t)8 * NPIX) = make_float2(acc[nt][2], acc[nt][3]);
        }
    }
}

// ============== fuse conv 3x3 (192->96): all-9-taps-resident chunks ==============
#define FICSTR 536
#define FROWSTR 132
#define FIN_SZ (16 * FICSTR)
#define FW_SZ  (9 * 96 * 20)
#define SMEM_F ((2 * FIN_SZ + FW_SZ) * 4)  // 137728 bytes

__global__ __launch_bounds__(768, 1)
void fuse_mma(const float* __restrict__ Wt, const float* __restrict__ bias)
{
    extern __shared__ float sm[];
    float* sW = sm + 2 * FIN_SZ;
    const int tid = threadIdx.x;
    const int wid = tid >> 5, lane = tid & 31;
    const int mw = wid >> 2, nw = wid & 3;          // 6 x 4 warps
    const int r = lane >> 2, cl = lane & 3;
    const int b = blockIdx.y;
    const int r0 = blockIdx.x * 2;
    const int pr = nw >> 1;
    const int xh = (nw & 1) * 64;

    float acc[8][4];
#pragma unroll
    for (int j = 0; j < 8; j++)
#pragma unroll
        for (int q = 0; q < 4; q++) acc[j][q] = 0.f;

    auto stage_in = [&](int c, int buf) {
        float* dst = sm + buf * FIN_SZ;
        int icg0 = c * 16;
        const __half* srcbase = (icg0 < 96)
            ? (g_kv + ((size_t)b * C2_ + 96 + icg0) * NPIX)
            : (g_qv + ((size_t)b * C2_ + icg0) * NPIX);
        for (int seg = wid; seg < 64; seg += 24) {
            int ic = seg >> 2, rr = seg & 3;
            int gy = r0 + rr - 1;
            float* drow = dst + ic * FICSTR + rr * FROWSTR;
            const __half* srow = srcbase + (size_t)ic * NPIX + gy * 128;
            bool rowok = (unsigned)gy < 128u;
#pragma unroll
            for (int cc = lane; cc < 132; cc += 32) {
                int gx = cc - 1;
                float v = (rowok && (unsigned)gx < 128u) ? __half2float(srow[gx]) : 0.f;
                drow[cc] = v;
            }
        }
    };
    auto stageW = [&](int c) {
        const float4* src = (const float4*)(Wt + (size_t)c * FW_SZ);
        float4* dst = (float4*)sW;
        for (int i = tid; i < FW_SZ / 4; i += 768) dst[i] = src[i];
    };

    stage_in(0, 0);
    stageW(0);
    __syncthreads();
    for (int c = 0; c < 12; c++) {
        int buf = c & 1;
        if (c + 1 < 12) stage_in(c + 1, buf ^ 1);
        const float* inb = sm + buf * FIN_SZ;
#pragma unroll
        for (int t = 0; t < 9; t++) {
            int dy = t / 3 - 1, dx = t - (t / 3) * 3 - 1;
            const float* sA = sW + t * (96 * 20);
            const float* bbase = inb + (pr + dy + 1) * FROWSTR + xh + dx + 1 + r;
#pragma unroll
            for (int ks = 0; ks < 2; ks++) {
                uint32_t af[4];
                {
                    int row = mw * 16 + r;
                    float2 lo = *(const float2*)(sA + row * 20 + ks * 8 + cl * 2);
                    float2 hi = *(const float2*)(sA + (row + 8) * 20 + ks * 8 + cl * 2);
                    af[0] = __float_as_uint(lo.x);
                    af[2] = __float_as_uint(lo.y);
                    af[1] = __float_as_uint(hi.x);
                    af[3] = __float_as_uint(hi.y);
                }
                const float* b0p = bbase + (ks * 8 + cl) * FICSTR;
                const float* b1p = b0p + 4 * FICSTR;
#pragma unroll
                for (int nt = 0; nt < 8; nt++) {
                    mma8(acc[nt], af,
                         __float_as_uint(b0p[nt * 8]), __float_as_uint(b1p[nt * 8]));
                }
            }
        }
        __syncthreads();
        if (c + 1 < 12) {
            stageW(c + 1);
            __syncthreads();
        }
    }

    int oc = mw * 16 + r;
    float bv0 = bias[oc];
    float bv8 = bias[oc + 8];
    __half* ob = g_v + ((size_t)b * C_ + oc) * NPIX + (r0 + pr) * 128 + xh + 2 * cl;
#pragma unroll
    for (int nt = 0; nt < 8; nt++) {
        __half* op = ob + nt * 8;
        *(__half2*)op = __floats2half2_rn(acc[nt][0] + bv0, acc[nt][1] + bv0);
        *(__half2*)(op + (size_t)8 * NPIX) =
            __floats2half2_rn(acc[nt][2] + bv8, acc[nt][3] + bv8);
    }
}

// ======================= weight pack kernels (tf32 round) =======================
__global__ void pack_a(const float* __restrict__ w, float* __restrict__ dst, int total)
{
    int idx = blockIdx.x * 256 + threadIdx.x;
    if (idx < total) dst[idx] = to_tf32(w[idx]);
}
__global__ void pack_fuse(const float* __restrict__ wf, float* __restrict__ dst)
{
    int idx = blockIdx.x * 256 + threadIdx.x;
    if (idx >= 12 * 9 * 96 * 16) return;
    int ic16 = idx & 15;
    int rem = idx >> 4;
    int oc = rem % 96; rem /= 96;
    int t = rem % 9;
    int chunk = rem / 9;
    int ic = chunk * 16 + ic16;
    dst[(((size_t)chunk * 9 + t) * 96 + oc) * 20 + kp16(ic16)] =
        to_tf32(wf[((size_t)oc * 192 + ic) * 9 + t]);
}
__global__ void pack_wfin(const float* __restrict__ wp, const float* __restrict__ wpos)
{
    int idx = blockIdx.x * 256 + threadIdx.x;
    if (idx >= B_ * C2_ * 288) return;
    int b = idx / (C2_ * 288);
    int rem = idx - b * (C2_ * 288);
    int oc = rem / 288, k = rem - oc * 288;
    float v;
    if (k < 96) {
        int h = k >> 4, d = k & 15;
        float s = 0.f;
#pragma unroll
        for (int i = 0; i < 16; i++)
            s = fmaf(wp[oc * 96 + h * 16 + i],
                     g_attn[(((size_t)b * HEADS_ + h) * 16 + i) * 16 + d], s);
        v = s;
    } else {
        v = wpos[(size_t)oc * 192 + (k - 96)];
    }
    g_wfin[idx] = to_tf32(v);
}
__global__ void zero_attn_acc()
{
    int idx = blockIdx.x * 256 + threadIdx.x;
    if (idx < B_ * HEADS_ * 256) g_gram[idx] = 0.f;
    if (idx < B_ * HEADS_ * 32) g_nrm[idx] = 0.f;
}

// ======= depthwise 3x3, pad 1: 4 px/thread, fp16 in/out, both branches =======
__global__ __launch_bounds__(256)
void dw3x3_kernel(const float* __restrict__ wdw0, const float* __restrict__ wdw1)
{
    int z = blockIdx.z;
    int b = z >> 1, br = z & 1;
    int c = blockIdx.y;
    int n4 = (blockIdx.x * 256 + threadIdx.x) * 4;
    int yy = n4 >> 7, x0 = n4 & 127;
    const __half* ip = (br ? g_t2 : g_t) + ((size_t)b * C2_ + c) * NPIX;
    const float* wp = (br ? wdw1 : wdw0) + c * 9;
    __half* op = (br ? g_kv : g_qv) + ((size_t)b * C2_ + c) * NPIX + n4;

    float a0 = 0.f, a1 = 0.f, a2 = 0.f, a3 = 0.f;
#pragma unroll
    for (int ky = 0; ky < 3; ky++) {
        int gy = yy + ky - 1;
        if ((unsigned)gy >= 128u) continue;
        const __half* row = ip + gy * 128 + x0;
        float2 h01 = __half22float2(*(const __half2*)row);
        float2 h23 = __half22float2(*(const __half2*)(row + 2));
        float lft = (x0 > 0) ? __half2float(row[-1]) : 0.f;
        float rgt = (x0 < 124) ? __half2float(row[4]) : 0.f;
        float w0 = wp[ky * 3], w1 = wp[ky * 3 + 1], w2 = wp[ky * 3 + 2];
        a0 = fmaf(w0, lft,   fmaf(w1, h01.x, fmaf(w2, h01.y, a0)));
        a1 = fmaf(w0, h01.x, fmaf(w1, h01.y, fmaf(w2, h23.x, a1)));
        a2 = fmaf(w0, h01.y, fmaf(w1, h23.x, fmaf(w2, h23.y, a2)));
        a3 = fmaf(w0, h23.x, fmaf(w1, h23.y, fmaf(w2, rgt,   a3)));
    }
    *(__half2*)op = __floats2half2_rn(a0, a1);
    *(__half2*)(op + 2) = __floats2half2_rn(a2, a3);
}

// ===== attention part 1: partial gram + partial norms over 1/8 of pixels =====
#define GR_NC 256
#define NSPLIT 8
__global__ void attn_part()
{
    __shared__ float sq[16][GR_NC + 2];
    __shared__ float sk[16][GR_NC + 2];
    int h = blockIdx.x, b = blockIdx.y, sp = blockIdx.z;
    int tid = threadIdx.x;
    int i = tid >> 4, j = tid & 15;
    int tgt = tid >> 3;
    int toff = (tid & 7) * 32;
    const __half* qb = g_qv + ((size_t)b * C2_ + h * 16) * NPIX;
    const __half* kb = g_kv + ((size_t)b * C2_ + h * 16) * NPIX;
    float acc = 0.f, np = 0.f;
    int nbeg = sp * (NPIX / NSPLIT), nend = nbeg + NPIX / NSPLIT;
    for (int n0 = nbeg; n0 < nend; n0 += GR_NC) {
        for (int idx = tid; idx < 16 * GR_NC; idx += 256) {
            int c = idx >> 8, nn = idx & (GR_NC - 1);
            sq[c][nn] = __half2float(qb[(size_t)c * NPIX + n0 + nn]);
            sk[c][nn] = __half2float(kb[(size_t)c * NPIX + n0 + nn]);
        }
        __syncthreads();
#pragma unroll 4
        for (int nn = 0; nn < GR_NC; nn++) acc = fmaf(sq[i][nn], sk[j][nn], acc);
        {
            const float* src = (tgt < 16) ? sq[tgt] : sk[tgt - 16];
#pragma unroll 8
            for (int u = 0; u < 32; u++) { float v = src[toff + u]; np = fmaf(v, v, np); }
        }
        __syncthreads();
    }
    atomicAdd(&g_gram[(((size_t)b * HEADS_ + h) * 16 + i) * 16 + j], acc);
    np += __shfl_down_sync(0xffffffffu, np, 4);
    np += __shfl_down_sync(0xffffffffu, np, 2);
    np += __shfl_down_sync(0xffffffffu, np, 1);
    if ((tid & 7) == 0) atomicAdd(&g_nrm[((size_t)b * HEADS_ + h) * 32 + tgt], np);
}

// ===== attention part 2: normalize + temperature + softmax =====
__global__ void attn_soft(const float* __restrict__ temp)
{
    __shared__ float gm[16][17];
    int h = blockIdx.x, b = blockIdx.y;
    int tid = threadIdx.x;
    if (tid < 256) {
        int i = tid >> 4, j = tid & 15;
        const float* nr = g_nrm + ((size_t)b * HEADS_ + h) * 32;
        float invq = 1.f / fmaxf(sqrtf(nr[i]), 1e-12f);
        float invk = 1.f / fmaxf(sqrtf(nr[16 + j]), 1e-12f);
        gm[i][j] = g_gram[(((size_t)b * HEADS_ + h) * 16 + i) * 16 + j]
                   * invq * invk * temp[h];
    }
    __syncthreads();
    if (tid < 16) {
        int ii = tid;
        float m = -1e30f;
        for (int jj = 0; jj < 16; jj++) m = fmaxf(m, gm[ii][jj]);
        float e[16], ssum = 0.f;
        for (int jj = 0; jj < 16; jj++) { e[jj] = expf(gm[ii][jj] - m); ssum += e[jj]; }
        float inv = 1.f / ssum;
        for (int jj = 0; jj < 16; jj++)
            g_attn[(((size_t)b * HEADS_ + h) * 16 + ii) * 16 + jj] = e[jj] * inv;
    }
}

extern "C" void kernel_launch(void* const* d_in, const int* in_sizes, int n_in,
                              void* d_out, int out_size)
{
    const float* x        = (const float*)d_in[0];
    const float* y        = (const float*)d_in[1];
    const float* w_pos    = (const float*)d_in[2];
    const float* w_qv     = (const float*)d_in[3];
    const float* w_qv_dw  = (const float*)d_in[4];
    const float* w_kv     = (const float*)d_in[5];
    const float* w_kv_dw  = (const float*)d_in[6];
    const float* w_proj   = (const float*)d_in[7];
    const float* w_fuse   = (const float*)d_in[8];
    const float* b_fuse   = (const float*)d_in[9];
    const float* temp     = (const float*)d_in[10];
    float* out = (float*)d_out;

    void *pt, *pt2, *pv, *pwq, *pwk, *pwft, *pwfin;
    cudaGetSymbolAddress(&pt, g_t);
    cudaGetSymbolAddress(&pt2, g_t2);
    cudaGetSymbolAddress(&pv, g_v);
    cudaGetSymbolAddress(&pwq, g_wq);
    cudaGetSymbolAddress(&pwk, g_wk);
    cudaGetSymbolAddress(&pwft, g_wft);
    cudaGetSymbolAddress(&pwfin, g_wfin);

    cudaFuncSetAttribute(mma_gemm, cudaFuncAttributeMaxDynamicSharedMemorySize, SMEM_G);
    cudaFuncSetAttribute(fuse_mma, cudaFuncAttributeMaxDynamicSharedMemorySize, SMEM_F);

    pack_a<<<(C2_ * 96 + 255) / 256, 256>>>(w_qv, (float*)pwq, C2_ * 96);
    pack_a<<<(C2_ * 96 + 255) / 256, 256>>>(w_kv, (float*)pwk, C2_ * 96);
    pack_fuse<<<(12 * 9 * 96 * 16 + 255) / 256, 256>>>(w_fuse, (float*)pwft);
    zero_attn_acc<<<(B_ * HEADS_ * 256 + 255) / 256, 256>>>();

    // q/k 1x1 GEMMs (fp32 in, fp16 out)
    mma_gemm<<<dim3(128, B_), 768, SMEM_G>>>(
        x, nullptr, nullptr, (const float*)pwq, pt, 96, 0, 0, 1);
    mma_gemm<<<dim3(128, B_), 768, SMEM_G>>>(
        y, nullptr, nullptr, (const float*)pwk, pt2, 96, 0, 0, 1);
    // depthwise for both branches, 4 px/thread, fp16
    dw3x3_kernel<<<dim3(16, C2_, 2 * B_), 256>>>(w_qv_dw, w_kv_dw);
    // v = fuse3x3(cat(v0, v_)) + bias (fp16 in/out)
    fuse_mma<<<dim3(64, B_), 768, SMEM_F>>>((const float*)pwft, b_fuse);
    // attention: partial gram+norms, then softmax
    attn_part<<<dim3(HEADS_, B_, NSPLIT), 256>>>();
    attn_soft<<<dim3(HEADS_, B_), 256>>>(temp);
    // per-batch fused final weights: [Wproj@A_b | Wpos]
    pack_wfin<<<(B_ * C2_ * 288 + 255) / 256, 256>>>(w_proj, w_pos);
    // final: g_wfin_b @ [v(fp16); x; y] -> fp32 out
    mma_gemm<<<dim3(128, B_), 768, SMEM_G>>>(
        pv, x, y, (const float*)pwfin, out, 288, C2_ * 288, 0b001, 0);
}

// round 14
// speedup vs baseline: 2.6563x; 1.1447x over previous
#include <cuda_runtime.h>
#include <cuda_fp16.h>
#include <math.h>
#include <stdint.h>

#define B_    8
#define C_    96
#define C2_   192
#define NPIX  16384
#define HEADS_ 6

__device__ __forceinline__ float to_tf32(float f) {
    unsigned u; asm("cvt.rna.tf32.f32 %0, %1;" : "=r"(u) : "f"(f));
    return __uint_as_float(u);
}
__device__ __forceinline__ void mma8(float* c, const uint32_t* a, uint32_t b0, uint32_t b1) {
    asm volatile("mma.sync.aligned.m16n8k8.row.col.f32.tf32.tf32.f32 "
                 "{%0,%1,%2,%3}, {%4,%5,%6,%7}, {%8,%9}, {%0,%1,%2,%3};"
                 : "+f"(c[0]), "+f"(c[1]), "+f"(c[2]), "+f"(c[3])
                 : "r"(a[0]), "r"(a[1]), "r"(a[2]), "r"(a[3]), "r"(b0), "r"(b1));
}

// ---- device-global scratch ----
__device__ __half g_t  [B_ * C2_ * NPIX];
__device__ __half g_t2 [B_ * C2_ * NPIX];
__device__ __half g_qv [B_ * C2_ * NPIX];
__device__ __half g_kv [B_ * C2_ * NPIX];
__device__ __half g_v  [B_ * C_  * NPIX];
__device__ float g_attn[B_ * HEADS_ * 16 * 16];
__device__ float g_gram[B_ * HEADS_ * 16 * 16];
__device__ float g_nrm [B_ * HEADS_ * 32];
// weights pre-interleaved+padded: [chunk][192 oc][40]
__device__ float g_wq  [3 * 192 * 40];
__device__ float g_wk  [3 * 192 * 40];
__device__ float g_wft [12 * 9 * 96 * 20];           // [chunk][tap][oc][20]
__device__ float g_wfin[B_ * 9 * 192 * 40];          // per-batch [Wproj@A_b | Wpos]

__device__ __forceinline__ int kp(int kin) {
    return (kin & 24) + ((kin & 3) << 1) + ((kin >> 2) & 1);
}
__device__ __forceinline__ int kp16(int k) {
    return (k & 8) + ((k & 3) << 1) + ((k >> 2) & 1);
}

// ============== tf32 mma.sync 1x1 GEMM: 192 oc x 128 px, 24 warps ==============
#define GASTR 40
#define GABUF  (192 * GASTR)
#define GBBUF  (128 * GASTR)
#define GBUFSZ (GABUF + GBBUF)
#define SMEM_G (2 * GBUFSZ * 4)         // 102400 bytes

__global__ __launch_bounds__(768, 1)
void mma_gemm(const void* s0, const void* s1, const void* s2,
              const float* __restrict__ W, void* out, int K, int wbstride,
              int halfmask, int outhalf)
{
    extern __shared__ float sm[];
    const int tid = threadIdx.x;
    const int wid = tid >> 5, lane = tid & 31;
    const int mw = wid >> 1, nw = wid & 1;          // 12 x 2 warps
    const int r = lane >> 2, cl = lane & 3;
    const int b = blockIdx.y;
    const int n0 = blockIdx.x * 128;

    float acc[8][4];
#pragma unroll
    for (int j = 0; j < 8; j++)
#pragma unroll
        for (int q = 0; q < 4; q++) acc[j][q] = 0.f;

    const int nsteps = K / 32;
    const float* Wb = W + (size_t)b * wbstride;

    auto stage = [&](int kc, int buf) {
        float* sA = sm + buf * GBUFSZ;
        float* sB = sA + GABUF;
        // A: straight float4 memcpy of pre-interleaved [192][40] chunk
        {
            const float4* src = (const float4*)(Wb + (size_t)kc * GABUF);
            float4* dst = (float4*)sA;
            for (int i = tid; i < GABUF / 4; i += 768) dst[i] = src[i];
        }
        // B: vectorized transpose (4 px / thread / iter)
        int cg0 = kc * 32;
        int ci = (cg0 < 96) ? 0 : (cg0 < 192) ? 1 : 2;
        const void* base = (ci == 0) ? s0 : (ci == 1) ? s1 : s2;
        size_t rowbase = ((size_t)b * 96 + (cg0 % 96)) * NPIX + n0;
        if ((halfmask >> ci) & 1) {
            const __half* hb = (const __half*)base + rowbase;
            for (int i = tid; i < 1024; i += 768) {
                int c = i >> 5, px = (i & 31) * 4;
                const __half2* hp = (const __half2*)(hb + (size_t)c * NPIX + px);
                float2 v01 = __half22float2(hp[0]);
                float2 v23 = __half22float2(hp[1]);
                float* d = sB + px * GASTR + kp(c);
                d[0] = v01.x; d[GASTR] = v01.y;
                d[2 * GASTR] = v23.x; d[3 * GASTR] = v23.y;
            }
        } else {
            const float* fb = (const float*)base + rowbase;
            for (int i = tid; i < 1024; i += 768) {
                int c = i >> 5, px = (i & 31) * 4;
                float4 v = *(const float4*)(fb + (size_t)c * NPIX + px);
                float* d = sB + px * GASTR + kp(c);
                d[0] = to_tf32(v.x); d[GASTR] = to_tf32(v.y);
                d[2 * GASTR] = to_tf32(v.z); d[3 * GASTR] = to_tf32(v.w);
            }
        }
    };

    stage(0, 0);
    __syncthreads();
    for (int s = 0; s < nsteps; s++) {
        int buf = s & 1;
        if (s + 1 < nsteps) stage(s + 1, buf ^ 1);
        const float* sA = sm + buf * GBUFSZ;
        const float* sB = sA + GABUF;
#pragma unroll
        for (int ks = 0; ks < 4; ks++) {
            uint32_t af[4];
            {
                int row = mw * 16 + r;
                float2 lo = *(const float2*)(sA + row * GASTR + ks * 8 + cl * 2);
                float2 hi = *(const float2*)(sA + (row + 8) * GASTR + ks * 8 + cl * 2);
                af[0] = __float_as_uint(lo.x);
                af[2] = __float_as_uint(lo.y);
                af[1] = __float_as_uint(hi.x);
                af[3] = __float_as_uint(hi.y);
            }
#pragma unroll
            for (int nt = 0; nt < 8; nt++) {
                int px = nw * 64 + nt * 8 + r;
                float2 bb = *(const float2*)(sB + px * GASTR + ks * 8 + cl * 2);
                mma8(acc[nt], af, __float_as_uint(bb.x), __float_as_uint(bb.y));
            }
        }
        __syncthreads();
    }

    int oc = mw * 16 + r;
    size_t obase = ((size_t)b * 192 + oc) * NPIX + n0 + nw * 64 + 2 * cl;
    if (outhalf) {
        __half* ob = (__half*)out + obase;
#pragma unroll
        for (int nt = 0; nt < 8; nt++) {
            __half* op = ob + nt * 8;
            *(__half2*)op = __floats2half2_rn(acc[nt][0], acc[nt][1]);
            *(__half2*)(op + (size_t)8 * NPIX) = __floats2half2_rn(acc[nt][2], acc[nt][3]);
        }
    } else {
        float* ob = (float*)out + obase;
#pragma unroll
        for (int nt = 0; nt < 8; nt++) {
            float* op = ob + nt * 8;
            *(float2*)op = make_float2(acc[nt][0], acc[nt][1]);
            *(float2*)(op + (size_t)8 * NPIX) = make_float2(acc[nt][2], acc[nt][3]);
        }
    }
}

// ============== fuse conv 3x3 (192->96): weights via direct LDG ==============
#define FICSTR 536
#define FROWSTR 132
#define FIN_SZ (16 * FICSTR)
#define SMEM_F (2 * FIN_SZ * 4)           // 68608 bytes (input double buffer only)

__global__ __launch_bounds__(768, 1)
void fuse_mma(const float* __restrict__ Wt, const float* __restrict__ bias)
{
    extern __shared__ float sm[];
    const int tid = threadIdx.x;
    const int wid = tid >> 5, lane = tid & 31;
    const int mw = wid >> 2, nw = wid & 3;          // 6 x 4 warps
    const int r = lane >> 2, cl = lane & 3;
    const int b = blockIdx.y;
    const int r0 = blockIdx.x * 2;
    const int pr = nw >> 1;
    const int xh = (nw & 1) * 64;

    float acc[8][4];
#pragma unroll
    for (int j = 0; j < 8; j++)
#pragma unroll
        for (int q = 0; q < 4; q++) acc[j][q] = 0.f;

    auto stage_in = [&](int c, int buf) {
        float* dst = sm + buf * FIN_SZ;
        int icg0 = c * 16;
        const __half* srcbase = (icg0 < 96)
            ? (g_kv + ((size_t)b * C2_ + 96 + icg0) * NPIX)
            : (g_qv + ((size_t)b * C2_ + icg0) * NPIX);
        for (int seg = wid; seg < 64; seg += 24) {
            int ic = seg >> 2, rr = seg & 3;
            int gy = r0 + rr - 1;
            float* drow = dst + ic * FICSTR + rr * FROWSTR;
            const __half2* s2p = (const __half2*)(srcbase + (size_t)ic * NPIX + gy * 128);
            bool rowok = (unsigned)gy < 128u;
#pragma unroll
            for (int q = 0; q < 2; q++) {
                int cc = lane + q * 32;           // half2 index 0..63 -> cols 1..128
                float2 v = rowok ? __half22float2(s2p[cc]) : make_float2(0.f, 0.f);
                drow[1 + 2 * cc] = v.x;
                drow[2 + 2 * cc] = v.y;
            }
            if (lane < 4) drow[(lane == 0) ? 0 : (128 + lane)] = 0.f;  // cols 0,129,130,131
        }
    };

    stage_in(0, 0);
    __syncthreads();
    for (int c = 0; c < 12; c++) {
        int buf = c & 1;
        if (c + 1 < 12) stage_in(c + 1, buf ^ 1);
        const float* inb = sm + buf * FIN_SZ;
        const float* wchunk = Wt + (size_t)c * (9 * 96 * 20);
#pragma unroll
        for (int t = 0; t < 9; t++) {
            int dy = t / 3 - 1, dx = t - (t / 3) * 3 - 1;
            const float* sA = wchunk + t * (96 * 20);      // global, L1/L2 resident
            const float* bbase = inb + (pr + dy + 1) * FROWSTR + xh + dx + 1 + r;
#pragma unroll
            for (int ks = 0; ks < 2; ks++) {
                uint32_t af[4];
                {
                    int row = mw * 16 + r;
                    float2 lo = *(const float2*)(sA + row * 20 + ks * 8 + cl * 2);
                    float2 hi = *(const float2*)(sA + (row + 8) * 20 + ks * 8 + cl * 2);
                    af[0] = __float_as_uint(lo.x);
                    af[2] = __float_as_uint(lo.y);
                    af[1] = __float_as_uint(hi.x);
                    af[3] = __float_as_uint(hi.y);
                }
                const float* b0p = bbase + (ks * 8 + cl) * FICSTR;
                const float* b1p = b0p + 4 * FICSTR;
#pragma unroll
                for (int nt = 0; nt < 8; nt++) {
                    mma8(acc[nt], af,
                         __float_as_uint(b0p[nt * 8]), __float_as_uint(b1p[nt * 8]));
                }
            }
        }
        __syncthreads();
    }

    int oc = mw * 16 + r;
    float bv0 = bias[oc];
    float bv8 = bias[oc + 8];
    __half* ob = g_v + ((size_t)b * C_ + oc) * NPIX + (r0 + pr) * 128 + xh + 2 * cl;
#pragma unroll
    for (int nt = 0; nt < 8; nt++) {
        __half* op = ob + nt * 8;
        *(__half2*)op = __floats2half2_rn(acc[nt][0] + bv0, acc[nt][1] + bv0);
        *(__half2*)(op + (size_t)8 * NPIX) =
            __floats2half2_rn(acc[nt][2] + bv8, acc[nt][3] + bv8);
    }
}

// ======================= weight pack kernels =======================
// [oc][K] -> pre-interleaved [chunk][192][40]
__global__ void pack_a(const float* __restrict__ w, float* __restrict__ dst, int K)
{
    int idx = blockIdx.x * 256 + threadIdx.x;
    if (idx >= 192 * K) return;
    int oc = idx / K, k = idx - oc * K;
    int chunk = k >> 5, kin = k & 31;
    dst[((size_t)chunk * 192 + oc) * 40 + kp(kin)] = to_tf32(w[idx]);
}
__global__ void pack_fuse(const float* __restrict__ wf, float* __restrict__ dst)
{
    int idx = blockIdx.x * 256 + threadIdx.x;
    if (idx >= 12 * 9 * 96 * 16) return;
    int ic16 = idx & 15;
    int rem = idx >> 4;
    int oc = rem % 96; rem /= 96;
    int t = rem % 9;
    int chunk = rem / 9;
    int ic = chunk * 16 + ic16;
    dst[(((size_t)chunk * 9 + t) * 96 + oc) * 20 + kp16(ic16)] =
        to_tf32(wf[((size_t)oc * 192 + ic) * 9 + t]);
}
// per-batch fused final weights, pre-interleaved [b][chunk 9][192][40]
__global__ void pack_wfin(const float* __restrict__ wp, const float* __restrict__ wpos)
{
    int idx = blockIdx.x * 256 + threadIdx.x;
    if (idx >= B_ * C2_ * 288) return;
    int b = idx / (C2_ * 288);
    int rem = idx - b * (C2_ * 288);
    int oc = rem / 288, k = rem - oc * 288;
    float v;
    if (k < 96) {
        int h = k >> 4, d = k & 15;
        float s = 0.f;
#pragma unroll
        for (int i = 0; i < 16; i++)
            s = fmaf(wp[oc * 96 + h * 16 + i],
                     g_attn[(((size_t)b * HEADS_ + h) * 16 + i) * 16 + d], s);
        v = s;
    } else {
        v = wpos[(size_t)oc * 192 + (k - 96)];
    }
    int chunk = k >> 5, kin = k & 31;
    g_wfin[(((size_t)b * 9 + chunk) * 192 + oc) * 40 + kp(kin)] = to_tf32(v);
}
__global__ void zero_attn_acc()
{
    int idx = blockIdx.x * 256 + threadIdx.x;
    if (idx < B_ * HEADS_ * 256) g_gram[idx] = 0.f;
    if (idx < B_ * HEADS_ * 32) g_nrm[idx] = 0.f;
}

// ======= depthwise 3x3, pad 1: 4 px/thread, fp16, both branches =======
__global__ __launch_bounds__(256)
void dw3x3_kernel(const float* __restrict__ wdw0, const float* __restrict__ wdw1)
{
    int z = blockIdx.z;
    int b = z >> 1, br = z & 1;
    int c = blockIdx.y;
    int n4 = (blockIdx.x * 256 + threadIdx.x) * 4;
    int yy = n4 >> 7, x0 = n4 & 127;
    const __half* ip = (br ? g_t2 : g_t) + ((size_t)b * C2_ + c) * NPIX;
    const float* wp = (br ? wdw1 : wdw0) + c * 9;
    __half* op = (br ? g_kv : g_qv) + ((size_t)b * C2_ + c) * NPIX + n4;

    float a0 = 0.f, a1 = 0.f, a2 = 0.f, a3 = 0.f;
#pragma unroll
    for (int ky = 0; ky < 3; ky++) {
        int gy = yy + ky - 1;
        if ((unsigned)gy >= 128u) continue;
        const __half* row = ip + gy * 128 + x0;
        float2 h01 = __half22float2(*(const __half2*)row);
        float2 h23 = __half22float2(*(const __half2*)(row + 2));
        float lft = (x0 > 0) ? __half2float(row[-1]) : 0.f;
        float rgt = (x0 < 124) ? __half2float(row[4]) : 0.f;
        float w0 = wp[ky * 3], w1 = wp[ky * 3 + 1], w2 = wp[ky * 3 + 2];
        a0 = fmaf(w0, lft,   fmaf(w1, h01.x, fmaf(w2, h01.y, a0)));
        a1 = fmaf(w0, h01.x, fmaf(w1, h01.y, fmaf(w2, h23.x, a1)));
        a2 = fmaf(w0, h01.y, fmaf(w1, h23.x, fmaf(w2, h23.y, a2)));
        a3 = fmaf(w0, h23.x, fmaf(w1, h23.y, fmaf(w2, rgt,   a3)));
    }
    *(__half2*)op = __floats2half2_rn(a0, a1);
    *(__half2*)(op + 2) = __floats2half2_rn(a2, a3);
}

// ===== attention part 1: partial gram + partial norms over 1/8 of pixels =====
#define GR_NC 256
#define NSPLIT 8
__global__ void attn_part()
{
    __shared__ float sq[16][GR_NC + 2];
    __shared__ float sk[16][GR_NC + 2];
    int h = blockIdx.x, b = blockIdx.y, sp = blockIdx.z;
    int tid = threadIdx.x;
    int i = tid >> 4, j = tid & 15;
    int tgt = tid >> 3;
    int toff = (tid & 7) * 32;
    const __half* qb = g_qv + ((size_t)b * C2_ + h * 16) * NPIX;
    const __half* kb = g_kv + ((size_t)b * C2_ + h * 16) * NPIX;
    float acc = 0.f, np = 0.f;
    int nbeg = sp * (NPIX / NSPLIT), nend = nbeg + NPIX / NSPLIT;
    for (int n0 = nbeg; n0 < nend; n0 += GR_NC) {
        for (int idx = tid; idx < 16 * (GR_NC / 2); idx += 256) {
            int c = idx >> 7, nn2 = idx & 127;
            float2 vq = __half22float2(*(const __half2*)(qb + (size_t)c * NPIX + n0 + 2 * nn2));
            float2 vk = __half22float2(*(const __half2*)(kb + (size_t)c * NPIX + n0 + 2 * nn2));
            sq[c][2 * nn2] = vq.x; sq[c][2 * nn2 + 1] = vq.y;
            sk[c][2 * nn2] = vk.x; sk[c][2 * nn2 + 1] = vk.y;
        }
        __syncthreads();
#pragma unroll 4
        for (int nn = 0; nn < GR_NC; nn++) acc = fmaf(sq[i][nn], sk[j][nn], acc);
        {
            const float* src = (tgt < 16) ? sq[tgt] : sk[tgt - 16];
#pragma unroll 8
            for (int u = 0; u < 32; u++) { float v = src[toff + u]; np = fmaf(v, v, np); }
        }
        __syncthreads();
    }
    atomicAdd(&g_gram[(((size_t)b * HEADS_ + h) * 16 + i) * 16 + j], acc);
    np += __shfl_down_sync(0xffffffffu, np, 4);
    np += __shfl_down_sync(0xffffffffu, np, 2);
    np += __shfl_down_sync(0xffffffffu, np, 1);
    if ((tid & 7) == 0) atomicAdd(&g_nrm[((size_t)b * HEADS_ + h) * 32 + tgt], np);
}

// ===== attention part 2: normalize + temperature + softmax =====
__global__ void attn_soft(const float* __restrict__ temp)
{
    __shared__ float gm[16][17];
    int h = blockIdx.x, b = blockIdx.y;
    int tid = threadIdx.x;
    if (tid < 256) {
        int i = tid >> 4, j = tid & 15;
        const float* nr = g_nrm + ((size_t)b * HEADS_ + h) * 32;
        float invq = 1.f / fmaxf(sqrtf(nr[i]), 1e-12f);
        float invk = 1.f / fmaxf(sqrtf(nr[16 + j]), 1e-12f);
        gm[i][j] = g_gram[(((size_t)b * HEADS_ + h) * 16 + i) * 16 + j]
                   * invq * invk * temp[h];
    }
    __syncthreads();
    if (tid < 16) {
        int ii = tid;
        float m = -1e30f;
        for (int jj = 0; jj < 16; jj++) m = fmaxf(m, gm[ii][jj]);
        float e[16], ssum = 0.f;
        for (int jj = 0; jj < 16; jj++) { e[jj] = expf(gm[ii][jj] - m); ssum += e[jj]; }
        float inv = 1.f / ssum;
        for (int jj = 0; jj < 16; jj++)
            g_attn[(((size_t)b * HEADS_ + h) * 16 + ii) * 16 + jj] = e[jj] * inv;
    }
}

extern "C" void kernel_launch(void* const* d_in, const int* in_sizes, int n_in,
                              void* d_out, int out_size)
{
    const float* x        = (const float*)d_in[0];
    const float* y        = (const float*)d_in[1];
    const float* w_pos    = (const float*)d_in[2];
    const float* w_qv     = (const float*)d_in[3];
    const float* w_qv_dw  = (const float*)d_in[4];
    const float* w_kv     = (const float*)d_in[5];
    const float* w_kv_dw  = (const float*)d_in[6];
    const float* w_proj   = (const float*)d_in[7];
    const float* w_fuse   = (const float*)d_in[8];
    const float* b_fuse   = (const float*)d_in[9];
    const float* temp     = (const float*)d_in[10];
    float* out = (float*)d_out;

    void *pt, *pt2, *pv, *pwq, *pwk, *pwft, *pwfin;
    cudaGetSymbolAddress(&pt, g_t);
    cudaGetSymbolAddress(&pt2, g_t2);
    cudaGetSymbolAddress(&pv, g_v);
    cudaGetSymbolAddress(&pwq, g_wq);
    cudaGetSymbolAddress(&pwk, g_wk);
    cudaGetSymbolAddress(&pwft, g_wft);
    cudaGetSymbolAddress(&pwfin, g_wfin);

    cudaFuncSetAttribute(mma_gemm, cudaFuncAttributeMaxDynamicSharedMemorySize, SMEM_G);
    cudaFuncSetAttribute(fuse_mma, cudaFuncAttributeMaxDynamicSharedMemorySize, SMEM_F);

    pack_a<<<(C2_ * 96 + 255) / 256, 256>>>(w_qv, (float*)pwq, 96);
    pack_a<<<(C2_ * 96 + 255) / 256, 256>>>(w_kv, (float*)pwk, 96);
    pack_fuse<<<(12 * 9 * 96 * 16 + 255) / 256, 256>>>(w_fuse, (float*)pwft);
    zero_attn_acc<<<(B_ * HEADS_ * 256 + 255) / 256, 256>>>();

    // q/k 1x1 GEMMs (fp32 in, fp16 out)
    mma_gemm<<<dim3(128, B_), 768, SMEM_G>>>(
        x, nullptr, nullptr, (const float*)pwq, pt, 96, 0, 0, 1);
    mma_gemm<<<dim3(128, B_), 768, SMEM_G>>>(
        y, nullptr, nullptr, (const float*)pwk, pt2, 96, 0, 0, 1);
    // depthwise for both branches
    dw3x3_kernel<<<dim3(16, C2_, 2 * B_), 256>>>(w_qv_dw, w_kv_dw);
    // v = fuse3x3(cat(v0, v_)) + bias
    fuse_mma<<<dim3(64, B_), 768, SMEM_F>>>((const float*)pwft, b_fuse);
    // attention
    attn_part<<<dim3(HEADS_, B_, NSPLIT), 256>>>();
    attn_soft<<<dim3(HEADS_, B_), 256>>>(temp);
    // per-batch fused final weights
    pack_wfin<<<(B_ * C2_ * 288 + 255) / 256, 256>>>(w_proj, w_pos);
    // final: g_wfin_b @ [v(fp16); x; y] -> fp32 out
    mma_gemm<<<dim3(128, B_), 768, SMEM_G>>>(
        pv, x, y, (const float*)pwfin, out, 288, 9 * 192 * 40, 0b001, 0);
}

// round 15
// speedup vs baseline: 3.6474x; 1.3731x over previous
#include <cuda_runtime.h>
#include <cuda_fp16.h>
#include <math.h>
#include <stdint.h>

#define B_    8
#define C_    96
#define C2_   192
#define NPIX  16384
#define HEADS_ 6

__device__ __forceinline__ void mma16(float* c, const uint32_t* a, uint32_t b0, uint32_t b1) {
    asm volatile("mma.sync.aligned.m16n8k16.row.col.f32.f16.f16.f32 "
                 "{%0,%1,%2,%3}, {%4,%5,%6,%7}, {%8,%9}, {%0,%1,%2,%3};"
                 : "+f"(c[0]), "+f"(c[1]), "+f"(c[2]), "+f"(c[3])
                 : "r"(a[0]), "r"(a[1]), "r"(a[2]), "r"(a[3]), "r"(b0), "r"(b1));
}

// ---- device-global scratch ----
__device__ __half g_t  [B_ * C2_ * NPIX];
__device__ __half g_t2 [B_ * C2_ * NPIX];
__device__ __half g_qv [B_ * C2_ * NPIX];
__device__ __half g_kv [B_ * C2_ * NPIX];
__device__ __half g_v  [B_ * C_  * NPIX];
__device__ float g_attn[B_ * HEADS_ * 16 * 16];
__device__ float g_gram[B_ * HEADS_ * 16 * 16];
__device__ float g_nrm [B_ * HEADS_ * 32];
// fp16 weights, k-interleaved for m16n8k16 fragments
__device__ __half g_wq  [3 * 192 * 36];
__device__ __half g_wk  [3 * 192 * 36];
__device__ __half g_wft [12 * 9 * 96 * 16];          // [chunk][tap][oc][16]
__device__ __half g_wfin[B_ * 9 * 192 * 36];         // per-batch [Wproj@A_b | Wpos]

// k16 fragment interleave: positions cl*4.. hold k = {2cl, 2cl+1, 2cl+8, 2cl+9}
__device__ __host__ __forceinline__ int pos16(int k) {
    return 4 * ((k >> 1) & 3) + 2 * ((k >> 3) & 1) + (k & 1);
}

// ============== fp16 mma.sync 1x1 GEMM: 192 oc x 128 px, 24 warps ==============
#define GASTR 36
#define GABUF  (192 * GASTR)             // fp16 elems
#define GBBUF  (128 * GASTR)
#define GBUFSZ (GABUF + GBBUF)
#define SMEM_G (2 * GBUFSZ * 2)          // 46080 bytes

__global__ __launch_bounds__(768, 1)
void mma_gemm(const void* s0, const void* s1, const void* s2,
              const __half* __restrict__ W, void* out, int K, int wbstride,
              int halfmask, int outhalf)
{
    extern __shared__ __half smh[];
    const int tid = threadIdx.x;
    const int wid = tid >> 5, lane = tid & 31;
    const int mw = wid >> 1, nw = wid & 1;          // 12 x 2 warps
    const int r = lane >> 2, cl = lane & 3;
    const int b = blockIdx.y;
    const int n0 = blockIdx.x * 128;

    float acc[8][4];
#pragma unroll
    for (int j = 0; j < 8; j++)
#pragma unroll
        for (int q = 0; q < 4; q++) acc[j][q] = 0.f;

    const int nsteps = K / 32;
    const __half* Wb = W + (size_t)b * wbstride;

    auto stage = [&](int kc, int buf) {
        __half* sA = smh + buf * GBUFSZ;
        __half* sB = sA + GABUF;
        // A: uint4 memcpy of pre-interleaved fp16 [192][36] chunk
        {
            const uint4* src = (const uint4*)(Wb + (size_t)kc * GABUF);
            uint4* dst = (uint4*)sA;
            for (int i = tid; i < GABUF / 8; i += 768) dst[i] = src[i];
        }
        // B: transpose 32 ch x 128 px into interleaved fp16
        int cg0 = kc * 32;
        int ci = (cg0 < 96) ? 0 : (cg0 < 192) ? 1 : 2;
        const void* base = (ci == 0) ? s0 : (ci == 1) ? s1 : s2;
        size_t rowbase = ((size_t)b * 96 + (cg0 % 96)) * NPIX + n0;
        if ((halfmask >> ci) & 1) {
            const __half* hb = (const __half*)base + rowbase;
            for (int i = tid; i < 1024; i += 768) {
                int c = i >> 5, px = (i & 31) * 4;
                int pp = ((c >> 4) << 4) + pos16(c & 15);
                const __half2* hp = (const __half2*)(hb + (size_t)c * NPIX + px);
                __half2 v01 = hp[0], v23 = hp[1];
                __half* d = sB + px * GASTR + pp;
                d[0] = __low2half(v01); d[GASTR] = __high2half(v01);
                d[2 * GASTR] = __low2half(v23); d[3 * GASTR] = __high2half(v23);
            }
        } else {
            const float* fb = (const float*)base + rowbase;
            for (int i = tid; i < 1024; i += 768) {
                int c = i >> 5, px = (i & 31) * 4;
                int pp = ((c >> 4) << 4) + pos16(c & 15);
                float4 v = *(const float4*)(fb + (size_t)c * NPIX + px);
                __half* d = sB + px * GASTR + pp;
                d[0] = __float2half_rn(v.x); d[GASTR] = __float2half_rn(v.y);
                d[2 * GASTR] = __float2half_rn(v.z); d[3 * GASTR] = __float2half_rn(v.w);
            }
        }
    };

    stage(0, 0);
    __syncthreads();
    for (int s = 0; s < nsteps; s++) {
        int buf = s & 1;
        if (s + 1 < nsteps) stage(s + 1, buf ^ 1);
        const __half* sA = smh + buf * GBUFSZ;
        const __half* sB = sA + GABUF;
#pragma unroll
        for (int ks = 0; ks < 2; ks++) {
            uint32_t af[4];
            {
                int row = mw * 16 + r;
                uint2 alo = *(const uint2*)(sA + row * GASTR + ks * 16 + cl * 4);
                uint2 ahi = *(const uint2*)(sA + (row + 8) * GASTR + ks * 16 + cl * 4);
                af[0] = alo.x; af[2] = alo.y;
                af[1] = ahi.x; af[3] = ahi.y;
            }
#pragma unroll
            for (int nt = 0; nt < 8; nt++) {
                int px = nw * 64 + nt * 8 + r;
                uint2 bb = *(const uint2*)(sB + px * GASTR + ks * 16 + cl * 4);
                mma16(acc[nt], af, bb.x, bb.y);
            }
        }
        __syncthreads();
    }

    int oc = mw * 16 + r;
    size_t obase = ((size_t)b * 192 + oc) * NPIX + n0 + nw * 64 + 2 * cl;
    if (outhalf) {
        __half* ob = (__half*)out + obase;
#pragma unroll
        for (int nt = 0; nt < 8; nt++) {
            __half* op = ob + nt * 8;
            *(__half2*)op = __floats2half2_rn(acc[nt][0], acc[nt][1]);
            *(__half2*)(op + (size_t)8 * NPIX) = __floats2half2_rn(acc[nt][2], acc[nt][3]);
        }
    } else {
        float* ob = (float*)out + obase;
#pragma unroll
        for (int nt = 0; nt < 8; nt++) {
            float* op = ob + nt * 8;
            *(float2*)op = make_float2(acc[nt][0], acc[nt][1]);
            *(float2*)(op + (size_t)8 * NPIX) = make_float2(acc[nt][2], acc[nt][3]);
        }
    }
}

// ============== fuse conv 3x3 (192->96), fp16 k16 MMA ==============
// input smem: [4 rows][132 cols][16 ic interleaved] fp16, double buffered.
// weights: direct LDG from g_wft. ic chunks of 16 -> 1 MMA per (tap, nt).
#define FCOLS 132
#define FIN_SZ (4 * FCOLS * 16)           // 8448 fp16 per buffer
#define SMEM_F (2 * FIN_SZ * 2)           // 33792 bytes

__global__ __launch_bounds__(768, 1)
void fuse_mma(const __half* __restrict__ Wt, const float* __restrict__ bias)
{
    extern __shared__ __half smh[];
    const int tid = threadIdx.x;
    const int wid = tid >> 5, lane = tid & 31;
    const int mw = wid >> 2, nw = wid & 3;          // 6 x 4 warps
    const int r = lane >> 2, cl = lane & 3;
    const int b = blockIdx.y;
    const int r0 = blockIdx.x * 2;
    const int pr = nw >> 1;
    const int xh = (nw & 1) * 64;

    float acc[8][4];
#pragma unroll
    for (int j = 0; j < 8; j++)
#pragma unroll
        for (int q = 0; q < 4; q++) acc[j][q] = 0.f;

    auto stage_in = [&](int c, int buf) {
        __half* dst = smh + buf * FIN_SZ;
        int icg0 = c * 16;
        const __half* srcbase = (icg0 < 96)
            ? (g_kv + ((size_t)b * C2_ + 96 + icg0) * NPIX)
            : (g_qv + ((size_t)b * C2_ + icg0) * NPIX);
        for (int seg = wid; seg < 64; seg += 24) {
            int ic = seg >> 2, rr = seg & 3;
            int gy = r0 + rr - 1;
            int pp = pos16(ic);
            __half* drow = dst + (rr * FCOLS) * 16 + pp;
            const __half2* s2p = (const __half2*)(srcbase + (size_t)ic * NPIX + gy * 128);
            bool rowok = (unsigned)gy < 128u;
            __half2 zz = __floats2half2_rn(0.f, 0.f);
#pragma unroll
            for (int q = 0; q < 2; q++) {
                int cc = lane + q * 32;           // half2 idx 0..63 -> cols 1..128
                __half2 v = rowok ? s2p[cc] : zz;
                drow[(1 + 2 * cc) * 16] = __low2half(v);
                drow[(2 + 2 * cc) * 16] = __high2half(v);
            }
            if (lane < 4) {
                int col = (lane == 0) ? 0 : (128 + lane);
                drow[col * 16] = __float2half_rn(0.f);
            }
        }
    };

    stage_in(0, 0);
    __syncthreads();
    for (int c = 0; c < 12; c++) {
        int buf = c & 1;
        if (c + 1 < 12) stage_in(c + 1, buf ^ 1);
        const __half* inb = smh + buf * FIN_SZ;
        const __half* wchunk = Wt + (size_t)c * (9 * 96 * 16);
#pragma unroll
        for (int t = 0; t < 9; t++) {
            int dy = t / 3 - 1, dx = t - (t / 3) * 3 - 1;
            const __half* wp = wchunk + t * (96 * 16);
            uint32_t af[4];
            {
                int row = mw * 16 + r;
                uint2 alo = *(const uint2*)(wp + (size_t)row * 16 + cl * 4);
                uint2 ahi = *(const uint2*)(wp + (size_t)(row + 8) * 16 + cl * 4);
                af[0] = alo.x; af[2] = alo.y;
                af[1] = ahi.x; af[3] = ahi.y;
            }
            const __half* bbase = inb +
                ((size_t)(pr + dy + 1) * FCOLS + (xh + dx + 1 + r)) * 16 + cl * 4;
#pragma unroll
            for (int nt = 0; nt < 8; nt++) {
                uint2 bb = *(const uint2*)(bbase + nt * 8 * 16);
                mma16(acc[nt], af, bb.x, bb.y);
            }
        }
        __syncthreads();
    }

    int oc = mw * 16 + r;
    float bv0 = bias[oc];
    float bv8 = bias[oc + 8];
    __half* ob = g_v + ((size_t)b * C_ + oc) * NPIX + (r0 + pr) * 128 + xh + 2 * cl;
#pragma unroll
    for (int nt = 0; nt < 8; nt++) {
        __half* op = ob + nt * 8;
        *(__half2*)op = __floats2half2_rn(acc[nt][0] + bv0, acc[nt][1] + bv0);
        *(__half2*)(op + (size_t)8 * NPIX) =
            __floats2half2_rn(acc[nt][2] + bv8, acc[nt][3] + bv8);
    }
}

// ======================= weight pack kernels (fp16) =======================
__global__ void pack_a(const float* __restrict__ w, __half* __restrict__ dst, int K)
{
    int idx = blockIdx.x * 256 + threadIdx.x;
    if (idx >= 192 * K) return;
    int oc = idx / K, k = idx - oc * K;
    int chunk = k >> 5, kin = k & 31;
    int pp = ((kin >> 4) << 4) + pos16(kin & 15);
    dst[((size_t)chunk * 192 + oc) * GASTR + pp] = __float2half_rn(w[idx]);
}
__global__ void pack_fuse(const float* __restrict__ wf, __half* __restrict__ dst)
{
    int idx = blockIdx.x * 256 + threadIdx.x;
    if (idx >= 12 * 9 * 96 * 16) return;
    int ic16 = idx & 15;
    int rem = idx >> 4;
    int oc = rem % 96; rem /= 96;
    int t = rem % 9;
    int chunk = rem / 9;
    int ic = chunk * 16 + ic16;
    dst[(((size_t)chunk * 9 + t) * 96 + oc) * 16 + pos16(ic16)] =
        __float2half_rn(wf[((size_t)oc * 192 + ic) * 9 + t]);
}
__global__ void pack_wfin(const float* __restrict__ wp, const float* __restrict__ wpos,
                          __half* __restrict__ dst)
{
    int idx = blockIdx.x * 256 + threadIdx.x;
    if (idx >= B_ * C2_ * 288) return;
    int b = idx / (C2_ * 288);
    int rem = idx - b * (C2_ * 288);
    int oc = rem / 288, k = rem - oc * 288;
    float v;
    if (k < 96) {
        int h = k >> 4, d = k & 15;
        float s = 0.f;
#pragma unroll
        for (int i = 0; i < 16; i++)
            s = fmaf(wp[oc * 96 + h * 16 + i],
                     g_attn[(((size_t)b * HEADS_ + h) * 16 + i) * 16 + d], s);
        v = s;
    } else {
        v = wpos[(size_t)oc * 192 + (k - 96)];
    }
    int chunk = k >> 5, kin = k & 31;
    int pp = ((kin >> 4) << 4) + pos16(kin & 15);
    dst[(((size_t)b * 9 + chunk) * 192 + oc) * GASTR + pp] = __float2half_rn(v);
}
__global__ void zero_attn_acc()
{
    int idx = blockIdx.x * 256 + threadIdx.x;
    if (idx < B_ * HEADS_ * 256) g_gram[idx] = 0.f;
    if (idx < B_ * HEADS_ * 32) g_nrm[idx] = 0.f;
}

// ======= depthwise 3x3, pad 1: 4 px/thread, fp16, both branches =======
__global__ __launch_bounds__(256)
void dw3x3_kernel(const float* __restrict__ wdw0, const float* __restrict__ wdw1)
{
    int z = blockIdx.z;
    int b = z >> 1, br = z & 1;
    int c = blockIdx.y;
    int n4 = (blockIdx.x * 256 + threadIdx.x) * 4;
    int yy = n4 >> 7, x0 = n4 & 127;
    const __half* ip = (br ? g_t2 : g_t) + ((size_t)b * C2_ + c) * NPIX;
    const float* wp = (br ? wdw1 : wdw0) + c * 9;
    __half* op = (br ? g_kv : g_qv) + ((size_t)b * C2_ + c) * NPIX + n4;

    float a0 = 0.f, a1 = 0.f, a2 = 0.f, a3 = 0.f;
#pragma unroll
    for (int ky = 0; ky < 3; ky++) {
        int gy = yy + ky - 1;
        if ((unsigned)gy >= 128u) continue;
        const __half* row = ip + gy * 128 + x0;
        float2 h01 = __half22float2(*(const __half2*)row);
        float2 h23 = __half22float2(*(const __half2*)(row + 2));
        float lft = (x0 > 0) ? __half2float(row[-1]) : 0.f;
        float rgt = (x0 < 124) ? __half2float(row[4]) : 0.f;
        float w0 = wp[ky * 3], w1 = wp[ky * 3 + 1], w2 = wp[ky * 3 + 2];
        a0 = fmaf(w0, lft,   fmaf(w1, h01.x, fmaf(w2, h01.y, a0)));
        a1 = fmaf(w0, h01.x, fmaf(w1, h01.y, fmaf(w2, h23.x, a1)));
        a2 = fmaf(w0, h01.y, fmaf(w1, h23.x, fmaf(w2, h23.y, a2)));
        a3 = fmaf(w0, h23.x, fmaf(w1, h23.y, fmaf(w2, rgt,   a3)));
    }
    *(__half2*)op = __floats2half2_rn(a0, a1);
    *(__half2*)(op + 2) = __floats2half2_rn(a2, a3);
}

// ===== attention part 1: partial gram + partial norms over 1/8 of pixels =====
#define GR_NC 256
#define NSPLIT 8
__global__ void attn_part()
{
    __shared__ float sq[16][GR_NC + 2];
    __shared__ float sk[16][GR_NC + 2];
    int h = blockIdx.x, b = blockIdx.y, sp = blockIdx.z;
    int tid = threadIdx.x;
    int i = tid >> 4, j = tid & 15;
    int tgt = tid >> 3;
    int toff = (tid & 7) * 32;
    const __half* qb = g_qv + ((size_t)b * C2_ + h * 16) * NPIX;
    const __half* kb = g_kv + ((size_t)b * C2_ + h * 16) * NPIX;
    float acc = 0.f, np = 0.f;
    int nbeg = sp * (NPIX / NSPLIT), nend = nbeg + NPIX / NSPLIT;
    for (int n0 = nbeg; n0 < nend; n0 += GR_NC) {
        for (int idx = tid; idx < 16 * (GR_NC / 2); idx += 256) {
            int c = idx >> 7, nn2 = idx & 127;
            float2 vq = __half22float2(*(const __half2*)(qb + (size_t)c * NPIX + n0 + 2 * nn2));
            float2 vk = __half22float2(*(const __half2*)(kb + (size_t)c * NPIX + n0 + 2 * nn2));
            sq[c][2 * nn2] = vq.x; sq[c][2 * nn2 + 1] = vq.y;
            sk[c][2 * nn2] = vk.x; sk[c][2 * nn2 + 1] = vk.y;
        }
        __syncthreads();
#pragma unroll 4
        for (int nn = 0; nn < GR_NC; nn++) acc = fmaf(sq[i][nn], sk[j][nn], acc);
        {
            const float* src = (tgt < 16) ? sq[tgt] : sk[tgt - 16];
#pragma unroll 8
            for (int u = 0; u < 32; u++) { float v = src[toff + u]; np = fmaf(v, v, np); }
        }
        __syncthreads();
    }
    atomicAdd(&g_gram[(((size_t)b * HEADS_ + h) * 16 + i) * 16 + j], acc);
    np += __shfl_down_sync(0xffffffffu, np, 4);
    np += __shfl_down_sync(0xffffffffu, np, 2);
    np += __shfl_down_sync(0xffffffffu, np, 1);
    if ((tid & 7) == 0) atomicAdd(&g_nrm[((size_t)b * HEADS_ + h) * 32 + tgt], np);
}

// ===== attention part 2: normalize + temperature + softmax =====
__global__ void attn_soft(const float* __restrict__ temp)
{
    __shared__ float gm[16][17];
    int h = blockIdx.x, b = blockIdx.y;
    int tid = threadIdx.x;
    if (tid < 256) {
        int i = tid >> 4, j = tid & 15;
        const float* nr = g_nrm + ((size_t)b * HEADS_ + h) * 32;
        float invq = 1.f / fmaxf(sqrtf(nr[i]), 1e-12f);
        float invk = 1.f / fmaxf(sqrtf(nr[16 + j]), 1e-12f);
        gm[i][j] = g_gram[(((size_t)b * HEADS_ + h) * 16 + i) * 16 + j]
                   * invq * invk * temp[h];
    }
    __syncthreads();
    if (tid < 16) {
        int ii = tid;
        float m = -1e30f;
        for (int jj = 0; jj < 16; jj++) m = fmaxf(m, gm[ii][jj]);
        float e[16], ssum = 0.f;
        for (int jj = 0; jj < 16; jj++) { e[jj] = expf(gm[ii][jj] - m); ssum += e[jj]; }
        float inv = 1.f / ssum;
        for (int jj = 0; jj < 16; jj++)
            g_attn[(((size_t)b * HEADS_ + h) * 16 + ii) * 16 + jj] = e[jj] * inv;
    }
}

extern "C" void kernel_launch(void* const* d_in, const int* in_sizes, int n_in,
                              void* d_out, int out_size)
{
    const float* x        = (const float*)d_in[0];
    const float* y        = (const float*)d_in[1];
    const float* w_pos    = (const float*)d_in[2];
    const float* w_qv     = (const float*)d_in[3];
    const float* w_qv_dw  = (const float*)d_in[4];
    const float* w_kv     = (const float*)d_in[5];
    const float* w_kv_dw  = (const float*)d_in[6];
    const float* w_proj   = (const float*)d_in[7];
    const float* w_fuse   = (const float*)d_in[8];
    const float* b_fuse   = (const float*)d_in[9];
    const float* temp     = (const float*)d_in[10];
    float* out = (float*)d_out;

    void *pt, *pt2, *pv, *pwq, *pwk, *pwft, *pwfin;
    cudaGetSymbolAddress(&pt, g_t);
    cudaGetSymbolAddress(&pt2, g_t2);
    cudaGetSymbolAddress(&pv, g_v);
    cudaGetSymbolAddress(&pwq, g_wq);
    cudaGetSymbolAddress(&pwk, g_wk);
    cudaGetSymbolAddress(&pwft, g_wft);
    cudaGetSymbolAddress(&pwfin, g_wfin);

    cudaFuncSetAttribute(mma_gemm, cudaFuncAttributeMaxDynamicSharedMemorySize, SMEM_G);
    cudaFuncSetAttribute(fuse_mma, cudaFuncAttributeMaxDynamicSharedMemorySize, SMEM_F);

    pack_a<<<(C2_ * 96 + 255) / 256, 256>>>(w_qv, (__half*)pwq, 96);
    pack_a<<<(C2_ * 96 + 255) / 256, 256>>>(w_kv, (__half*)pwk, 96);
    pack_fuse<<<(12 * 9 * 96 * 16 + 255) / 256, 256>>>(w_fuse, (__half*)pwft);
    zero_attn_acc<<<(B_ * HEADS_ * 256 + 255) / 256, 256>>>();

    // q/k 1x1 GEMMs (fp32 in, fp16 out)
    mma_gemm<<<dim3(128, B_), 768, SMEM_G>>>(
        x, nullptr, nullptr, (const __half*)pwq, pt, 96, 0, 0, 1);
    mma_gemm<<<dim3(128, B_), 768, SMEM_G>>>(
        y, nullptr, nullptr, (const __half*)pwk, pt2, 96, 0, 0, 1);
    // depthwise for both branches
    dw3x3_kernel<<<dim3(16, C2_, 2 * B_), 256>>>(w_qv_dw, w_kv_dw);
    // v = fuse3x3(cat(v0, v_)) + bias
    fuse_mma<<<dim3(64, B_), 768, SMEM_F>>>((const __half*)pwft, b_fuse);
    // attention
    attn_part<<<dim3(HEADS_, B_, NSPLIT), 256>>>();
    attn_soft<<<dim3(HEADS_, B_), 256>>>(temp);
    // per-batch fused final weights
    pack_wfin<<<(B_ * C2_ * 288 + 255) / 256, 256>>>(w_proj, w_pos, (__half*)pwfin);
    // final: g_wfin_b @ [v(fp16); x; y] -> fp32 out
    mma_gemm<<<dim3(128, B_), 768, SMEM_G>>>(
        pv, x, y, (const __half*)pwfin, out, 288, 9 * 192 * GASTR, 0b001, 0);
}

// round 16
// speedup vs baseline: 3.9546x; 1.0842x over previous
#include <cuda_runtime.h>
#include <cuda_fp16.h>
#include <math.h>
#include <stdint.h>

#define B_    8
#define C_    96
#define C2_   192
#define NPIX  16384
#define HEADS_ 6

__device__ __forceinline__ void mma16(float* c, const uint32_t* a, uint32_t b0, uint32_t b1) {
    asm volatile("mma.sync.aligned.m16n8k16.row.col.f32.f16.f16.f32 "
                 "{%0,%1,%2,%3}, {%4,%5,%6,%7}, {%8,%9}, {%0,%1,%2,%3};"
                 : "+f"(c[0]), "+f"(c[1]), "+f"(c[2]), "+f"(c[3])
                 : "r"(a[0]), "r"(a[1]), "r"(a[2]), "r"(a[3]), "r"(b0), "r"(b1));
}
__device__ __forceinline__ uint32_t sm2u(const void* p) {
    return (uint32_t)__cvta_generic_to_shared(p);
}
__device__ __forceinline__ void ldsm4(uint32_t& a, uint32_t& b, uint32_t& c, uint32_t& d,
                                      uint32_t addr) {
    asm volatile("ldmatrix.sync.aligned.m8n8.x4.shared.b16 {%0,%1,%2,%3}, [%4];"
                 : "=r"(a), "=r"(b), "=r"(c), "=r"(d) : "r"(addr));
}
__device__ __forceinline__ void ldsm4t(uint32_t& a, uint32_t& b, uint32_t& c, uint32_t& d,
                                       uint32_t addr) {
    asm volatile("ldmatrix.sync.aligned.m8n8.x4.trans.shared.b16 {%0,%1,%2,%3}, [%4];"
                 : "=r"(a), "=r"(b), "=r"(c), "=r"(d) : "r"(addr));
}

// ---- device-global scratch ----
__device__ __half g_xh [B_ * C_  * NPIX];
__device__ __half g_yh [B_ * C_  * NPIX];
__device__ __half g_t  [B_ * C2_ * NPIX];
__device__ __half g_t2 [B_ * C2_ * NPIX];
__device__ __half g_qv [B_ * C2_ * NPIX];
__device__ __half g_kv [B_ * C2_ * NPIX];
__device__ __half g_v  [B_ * C_  * NPIX];
__device__ float g_attn[B_ * HEADS_ * 16 * 16];
__device__ float g_gram[B_ * HEADS_ * 16 * 16];
__device__ float g_nrm [B_ * HEADS_ * 32];
// plain fp16 weights [chunk][192 oc][40 k-pitch]
__device__ __half g_wq  [3 * 192 * 40];
__device__ __half g_wk  [3 * 192 * 40];
__device__ __half g_wft [12 * 9 * 96 * 16];          // fuse: [chunk][tap][oc][16] pos16
__device__ __half g_wfin[B_ * 9 * 192 * 40];

__device__ __host__ __forceinline__ int pos16(int k) {
    return 4 * ((k >> 1) & 3) + 2 * ((k >> 3) & 1) + (k & 1);
}

// ============== fp16 mma + ldmatrix 1x1 GEMM: 192 oc x 128 px, 24 warps ==============
#define APITCH 40
#define BPITCH 136
#define GABUF  (192 * APITCH)            // 7680 halves
#define GBBUF  (32 * BPITCH)             // 4352 halves
#define GBUFSZ (GABUF + GBBUF)           // 12032 halves
#define SMEM_G (2 * GBUFSZ * 2)          // 48128 bytes

__global__ __launch_bounds__(768, 1)
void mma_gemm(const __half* __restrict__ s0, const __half* __restrict__ s1,
              const __half* __restrict__ s2, const __half* __restrict__ W,
              void* out, int K, int wbstride, int outhalf)
{
    extern __shared__ __half smh[];
    const int tid = threadIdx.x;
    const int wid = tid >> 5, lane = tid & 31;
    const int mw = wid >> 1, nw = wid & 1;          // 12 x 2 warps
    const int r = lane >> 2, cl = lane & 3;
    const int b = blockIdx.y;
    const int n0 = blockIdx.x * 128;

    float acc[8][4];
#pragma unroll
    for (int j = 0; j < 8; j++)
#pragma unroll
        for (int q = 0; q < 4; q++) acc[j][q] = 0.f;

    const int nsteps = K / 32;
    const __half* Wb = W + (size_t)b * wbstride;

    auto stage = [&](int kc, int buf) {
        __half* sA = smh + buf * GBUFSZ;
        __half* sB = sA + GABUF;
        {
            const uint4* src = (const uint4*)(Wb + (size_t)kc * GABUF);
            uint4* dst = (uint4*)sA;
            for (int i = tid; i < GABUF / 8; i += 768) dst[i] = src[i];
        }
        int cg0 = kc * 32;
        const __half* src = ((cg0 < 96) ? s0 : (cg0 < 192) ? s1 : s2)
                            + ((size_t)b * 96 + (cg0 % 96)) * NPIX + n0;
        for (int i = tid; i < 512; i += 768) {
            int c = i >> 4, q = i & 15;
            *(uint4*)(sB + c * BPITCH + q * 8) =
                *(const uint4*)(src + (size_t)c * NPIX + q * 8);
        }
    };

    // per-lane ldmatrix addresses (element offsets computed once)
    const int a_row = mw * 16 + (lane & 7) + ((lane >> 3) & 1) * 8;
    const int a_ko  = ((lane >> 4) & 1) * 8;
    const int b_krow = (lane & 7) + ((lane >> 3) & 1) * 8;
    const int b_nadd = ((lane >> 4) & 1) * 8;

    stage(0, 0);
    __syncthreads();
    for (int s = 0; s < nsteps; s++) {
        int buf = s & 1;
        if (s + 1 < nsteps) stage(s + 1, buf ^ 1);
        const __half* sA = smh + buf * GBUFSZ;
        const __half* sB = sA + GABUF;
#pragma unroll
        for (int ks = 0; ks < 2; ks++) {
            uint32_t af[4];
            ldsm4(af[0], af[1], af[2], af[3],
                  sm2u(sA + a_row * APITCH + ks * 16 + a_ko));
#pragma unroll
            for (int j = 0; j < 4; j++) {
                int px0 = nw * 64 + j * 16 + b_nadd;
                uint32_t b0, b1, b2, b3;
                ldsm4t(b0, b1, b2, b3,
                       sm2u(sB + (ks * 16 + b_krow) * BPITCH + px0));
                mma16(acc[2 * j], af, b0, b1);
                mma16(acc[2 * j + 1], af, b2, b3);
            }
        }
        __syncthreads();
    }

    int oc = mw * 16 + r;
    size_t obase = ((size_t)b * 192 + oc) * NPIX + n0 + nw * 64 + 2 * cl;
    if (outhalf) {
        __half* ob = (__half*)out + obase;
#pragma unroll
        for (int nt = 0; nt < 8; nt++) {
            __half* op = ob + nt * 8;
            *(__half2*)op = __floats2half2_rn(acc[nt][0], acc[nt][1]);
            *(__half2*)(op + (size_t)8 * NPIX) = __floats2half2_rn(acc[nt][2], acc[nt][3]);
        }
    } else {
        float* ob = (float*)out + obase;
#pragma unroll
        for (int nt = 0; nt < 8; nt++) {
            float* op = ob + nt * 8;
            *(float2*)op = make_float2(acc[nt][0], acc[nt][1]);
            *(float2*)(op + (size_t)8 * NPIX) = make_float2(acc[nt][2], acc[nt][3]);
        }
    }
}

// ============== fuse conv 3x3 (192->96), fp16 k16 MMA (unchanged engine) ==============
#define FCOLS 132
#define FIN_SZ (4 * FCOLS * 16)
#define SMEM_F (2 * FIN_SZ * 2)           // 33792 bytes

__global__ __launch_bounds__(768, 1)
void fuse_mma(const __half* __restrict__ Wt, const float* __restrict__ bias)
{
    extern __shared__ __half smh[];
    const int tid = threadIdx.x;
    const int wid = tid >> 5, lane = tid & 31;
    const int mw = wid >> 2, nw = wid & 3;          // 6 x 4 warps
    const int r = lane >> 2, cl = lane & 3;
    const int b = blockIdx.y;
    const int r0 = blockIdx.x * 2;
    const int pr = nw >> 1;
    const int xh = (nw & 1) * 64;

    float acc[8][4];
#pragma unroll
    for (int j = 0; j < 8; j++)
#pragma unroll
        for (int q = 0; q < 4; q++) acc[j][q] = 0.f;

    auto stage_in = [&](int c, int buf) {
        __half* dst = smh + buf * FIN_SZ;
        int icg0 = c * 16;
        const __half* srcbase = (icg0 < 96)
            ? (g_kv + ((size_t)b * C2_ + 96 + icg0) * NPIX)
            : (g_qv + ((size_t)b * C2_ + icg0) * NPIX);
        for (int seg = wid; seg < 64; seg += 24) {
            int ic = seg >> 2, rr = seg & 3;
            int gy = r0 + rr - 1;
            int pp = pos16(ic);
            __half* drow = dst + (rr * FCOLS) * 16 + pp;
            const __half2* s2p = (const __half2*)(srcbase + (size_t)ic * NPIX + gy * 128);
            bool rowok = (unsigned)gy < 128u;
            __half2 zz = __floats2half2_rn(0.f, 0.f);
#pragma unroll
            for (int q = 0; q < 2; q++) {
                int cc = lane + q * 32;
                __half2 v = rowok ? s2p[cc] : zz;
                drow[(1 + 2 * cc) * 16] = __low2half(v);
                drow[(2 + 2 * cc) * 16] = __high2half(v);
            }
            if (lane < 4) {
                int col = (lane == 0) ? 0 : (128 + lane);
                drow[col * 16] = __float2half_rn(0.f);
            }
        }
    };

    stage_in(0, 0);
    __syncthreads();
    for (int c = 0; c < 12; c++) {
        int buf = c & 1;
        if (c + 1 < 12) stage_in(c + 1, buf ^ 1);
        const __half* inb = smh + buf * FIN_SZ;
        const __half* wchunk = Wt + (size_t)c * (9 * 96 * 16);
#pragma unroll
        for (int t = 0; t < 9; t++) {
            int dy = t / 3 - 1, dx = t - (t / 3) * 3 - 1;
            const __half* wp = wchunk + t * (96 * 16);
            uint32_t af[4];
            {
                int row = mw * 16 + r;
                uint2 alo = *(const uint2*)(wp + (size_t)row * 16 + cl * 4);
                uint2 ahi = *(const uint2*)(wp + (size_t)(row + 8) * 16 + cl * 4);
                af[0] = alo.x; af[2] = alo.y;
                af[1] = ahi.x; af[3] = ahi.y;
            }
            const __half* bbase = inb +
                ((size_t)(pr + dy + 1) * FCOLS + (xh + dx + 1 + r)) * 16 + cl * 4;
#pragma unroll
            for (int nt = 0; nt < 8; nt++) {
                uint2 bb = *(const uint2*)(bbase + nt * 8 * 16);
                mma16(acc[nt], af, bb.x, bb.y);
            }
        }
        __syncthreads();
    }

    int oc = mw * 16 + r;
    float bv0 = bias[oc];
    float bv8 = bias[oc + 8];
    __half* ob = g_v + ((size_t)b * C_ + oc) * NPIX + (r0 + pr) * 128 + xh + 2 * cl;
#pragma unroll
    for (int nt = 0; nt < 8; nt++) {
        __half* op = ob + nt * 8;
        *(__half2*)op = __floats2half2_rn(acc[nt][0] + bv0, acc[nt][1] + bv0);
        *(__half2*)(op + (size_t)8 * NPIX) =
            __floats2half2_rn(acc[nt][2] + bv8, acc[nt][3] + bv8);
    }
}

// ======================= packs / conversions =======================
__global__ void cvt_fp16(const float* __restrict__ src, __half* __restrict__ dst, int total4)
{
    int i = blockIdx.x * 256 + threadIdx.x;
    if (i < total4) {
        float4 v = ((const float4*)src)[i];
        __half2* d = (__half2*)dst + 2 * i;
        d[0] = __floats2half2_rn(v.x, v.y);
        d[1] = __floats2half2_rn(v.z, v.w);
    }
}
__global__ void pack_a(const float* __restrict__ w, __half* __restrict__ dst, int K)
{
    int idx = blockIdx.x * 256 + threadIdx.x;
    if (idx >= 192 * K) return;
    int oc = idx / K, k = idx - oc * K;
    int chunk = k >> 5, kin = k & 31;
    dst[((size_t)chunk * 192 + oc) * APITCH + kin] = __float2half_rn(w[idx]);
}
__global__ void pack_fuse(const float* __restrict__ wf, __half* __restrict__ dst)
{
    int idx = blockIdx.x * 256 + threadIdx.x;
    if (idx >= 12 * 9 * 96 * 16) return;
    int ic16 = idx & 15;
    int rem = idx >> 4;
    int oc = rem % 96; rem /= 96;
    int t = rem % 9;
    int chunk = rem / 9;
    int ic = chunk * 16 + ic16;
    dst[(((size_t)chunk * 9 + t) * 96 + oc) * 16 + pos16(ic16)] =
        __float2half_rn(wf[((size_t)oc * 192 + ic) * 9 + t]);
}
__global__ void pack_wfin(const float* __restrict__ wp, const float* __restrict__ wpos,
                          __half* __restrict__ dst)
{
    int idx = blockIdx.x * 256 + threadIdx.x;
    if (idx >= B_ * C2_ * 288) return;
    int b = idx / (C2_ * 288);
    int rem = idx - b * (C2_ * 288);
    int oc = rem / 288, k = rem - oc * 288;
    float v;
    if (k < 96) {
        int h = k >> 4, d = k & 15;
        float s = 0.f;
#pragma unroll
        for (int i = 0; i < 16; i++)
            s = fmaf(wp[oc * 96 + h * 16 + i],
                     g_attn[(((size_t)b * HEADS_ + h) * 16 + i) * 16 + d], s);
        v = s;
    } else {
        v = wpos[(size_t)oc * 192 + (k - 96)];
    }
    int chunk = k >> 5, kin = k & 31;
    dst[(((size_t)b * 9 + chunk) * 192 + oc) * APITCH + kin] = __float2half_rn(v);
}
__global__ void zero_attn_acc()
{
    int idx = blockIdx.x * 256 + threadIdx.x;
    if (idx < B_ * HEADS_ * 256) g_gram[idx] = 0.f;
    if (idx < B_ * HEADS_ * 32) g_nrm[idx] = 0.f;
}

// ======= depthwise 3x3, pad 1: 4 px/thread, fp16, both branches =======
__global__ __launch_bounds__(256)
void dw3x3_kernel(const float* __restrict__ wdw0, const float* __restrict__ wdw1)
{
    int z = blockIdx.z;
    int b = z >> 1, br = z & 1;
    int c = blockIdx.y;
    int n4 = (blockIdx.x * 256 + threadIdx.x) * 4;
    int yy = n4 >> 7, x0 = n4 & 127;
    const __half* ip = (br ? g_t2 : g_t) + ((size_t)b * C2_ + c) * NPIX;
    const float* wp = (br ? wdw1 : wdw0) + c * 9;
    __half* op = (br ? g_kv : g_qv) + ((size_t)b * C2_ + c) * NPIX + n4;

    float a0 = 0.f, a1 = 0.f, a2 = 0.f, a3 = 0.f;
#pragma unroll
    for (int ky = 0; ky < 3; ky++) {
        int gy = yy + ky - 1;
        if ((unsigned)gy >= 128u) continue;
        const __half* row = ip + gy * 128 + x0;
        float2 h01 = __half22float2(*(const __half2*)row);
        float2 h23 = __half22float2(*(const __half2*)(row + 2));
        float lft = (x0 > 0) ? __half2float(row[-1]) : 0.f;
        float rgt = (x0 < 124) ? __half2float(row[4]) : 0.f;
        float w0 = wp[ky * 3], w1 = wp[ky * 3 + 1], w2 = wp[ky * 3 + 2];
        a0 = fmaf(w0, lft,   fmaf(w1, h01.x, fmaf(w2, h01.y, a0)));
        a1 = fmaf(w0, h01.x, fmaf(w1, h01.y, fmaf(w2, h23.x, a1)));
        a2 = fmaf(w0, h01.y, fmaf(w1, h23.x, fmaf(w2, h23.y, a2)));
        a3 = fmaf(w0, h23.x, fmaf(w1, h23.y, fmaf(w2, rgt,   a3)));
    }
    *(__half2*)op = __floats2half2_rn(a0, a1);
    *(__half2*)(op + 2) = __floats2half2_rn(a2, a3);
}

// ===== attention part 1: partial gram + partial norms over 1/8 of pixels =====
#define GR_NC 256
#define NSPLIT 8
__global__ void attn_part()
{
    __shared__ float sq[16][GR_NC + 2];
    __shared__ float sk[16][GR_NC + 2];
    int h = blockIdx.x, b = blockIdx.y, sp = blockIdx.z;
    int tid = threadIdx.x;
    int i = tid >> 4, j = tid & 15;
    int tgt = tid >> 3;
    int toff = (tid & 7) * 32;
    const __half* qb = g_qv + ((size_t)b * C2_ + h * 16) * NPIX;
    const __half* kb = g_kv + ((size_t)b * C2_ + h * 16) * NPIX;
    float acc = 0.f, np = 0.f;
    int nbeg = sp * (NPIX / NSPLIT), nend = nbeg + NPIX / NSPLIT;
    for (int n0 = nbeg; n0 < nend; n0 += GR_NC) {
        for (int idx = tid; idx < 16 * (GR_NC / 2); idx += 256) {
            int c = idx >> 7, nn2 = idx & 127;
            float2 vq = __half22float2(*(const __half2*)(qb + (size_t)c * NPIX + n0 + 2 * nn2));
            float2 vk = __half22float2(*(const __half2*)(kb + (size_t)c * NPIX + n0 + 2 * nn2));
            sq[c][2 * nn2] = vq.x; sq[c][2 * nn2 + 1] = vq.y;
            sk[c][2 * nn2] = vk.x; sk[c][2 * nn2 + 1] = vk.y;
        }
        __syncthreads();
#pragma unroll 4
        for (int nn = 0; nn < GR_NC; nn++) acc = fmaf(sq[i][nn], sk[j][nn], acc);
        {
            const float* src = (tgt < 16) ? sq[tgt] : sk[tgt - 16];
#pragma unroll 8
            for (int u = 0; u < 32; u++) { float v = src[toff + u]; np = fmaf(v, v, np); }
        }
        __syncthreads();
    }
    atomicAdd(&g_gram[(((size_t)b * HEADS_ + h) * 16 + i) * 16 + j], acc);
    np += __shfl_down_sync(0xffffffffu, np, 4);
    np += __shfl_down_sync(0xffffffffu, np, 2);
    np += __shfl_down_sync(0xffffffffu, np, 1);
    if ((tid & 7) == 0) atomicAdd(&g_nrm[((size_t)b * HEADS_ + h) * 32 + tgt], np);
}

// ===== attention part 2: normalize + temperature + softmax =====
__global__ void attn_soft(const float* __restrict__ temp)
{
    __shared__ float gm[16][17];
    int h = blockIdx.x, b = blockIdx.y;
    int tid = threadIdx.x;
    if (tid < 256) {
        int i = tid >> 4, j = tid & 15;
        const float* nr = g_nrm + ((size_t)b * HEADS_ + h) * 32;
        float invq = 1.f / fmaxf(sqrtf(nr[i]), 1e-12f);
        float invk = 1.f / fmaxf(sqrtf(nr[16 + j]), 1e-12f);
        gm[i][j] = g_gram[(((size_t)b * HEADS_ + h) * 16 + i) * 16 + j]
                   * invq * invk * temp[h];
    }
    __syncthreads();
    if (tid < 16) {
        int ii = tid;
        float m = -1e30f;
        for (int jj = 0; jj < 16; jj++) m = fmaxf(m, gm[ii][jj]);
        float e[16], ssum = 0.f;
        for (int jj = 0; jj < 16; jj++) { e[jj] = expf(gm[ii][jj] - m); ssum += e[jj]; }
        float inv = 1.f / ssum;
        for (int jj = 0; jj < 16; jj++)
            g_attn[(((size_t)b * HEADS_ + h) * 16 + ii) * 16 + jj] = e[jj] * inv;
    }
}

extern "C" void kernel_launch(void* const* d_in, const int* in_sizes, int n_in,
                              void* d_out, int out_size)
{
    const float* x        = (const float*)d_in[0];
    const float* y        = (const float*)d_in[1];
    const float* w_pos    = (const float*)d_in[2];
    const float* w_qv     = (const float*)d_in[3];
    const float* w_qv_dw  = (const float*)d_in[4];
    const float* w_kv     = (const float*)d_in[5];
    const float* w_kv_dw  = (const float*)d_in[6];
    const float* w_proj   = (const float*)d_in[7];
    const float* w_fuse   = (const float*)d_in[8];
    const float* b_fuse   = (const float*)d_in[9];
    const float* temp     = (const float*)d_in[10];
    float* out = (float*)d_out;

    void *pxh, *pyh, *pt, *pt2, *pv, *pwq, *pwk, *pwft, *pwfin;
    cudaGetSymbolAddress(&pxh, g_xh);
    cudaGetSymbolAddress(&pyh, g_yh);
    cudaGetSymbolAddress(&pt, g_t);
    cudaGetSymbolAddress(&pt2, g_t2);
    cudaGetSymbolAddress(&pv, g_v);
    cudaGetSymbolAddress(&pwq, g_wq);
    cudaGetSymbolAddress(&pwk, g_wk);
    cudaGetSymbolAddress(&pwft, g_wft);
    cudaGetSymbolAddress(&pwfin, g_wfin);

    cudaFuncSetAttribute(mma_gemm, cudaFuncAttributeMaxDynamicSharedMemorySize, SMEM_G);
    cudaFuncSetAttribute(fuse_mma, cudaFuncAttributeMaxDynamicSharedMemorySize, SMEM_F);

    const int TOT4 = B_ * C_ * NPIX / 4;
    cvt_fp16<<<(TOT4 + 255) / 256, 256>>>(x, (__half*)pxh, TOT4);
    cvt_fp16<<<(TOT4 + 255) / 256, 256>>>(y, (__half*)pyh, TOT4);
    pack_a<<<(C2_ * 96 + 255) / 256, 256>>>(w_qv, (__half*)pwq, 96);
    pack_a<<<(C2_ * 96 + 255) / 256, 256>>>(w_kv, (__half*)pwk, 96);
    pack_fuse<<<(12 * 9 * 96 * 16 + 255) / 256, 256>>>(w_fuse, (__half*)pwft);
    zero_attn_acc<<<(B_ * HEADS_ * 256 + 255) / 256, 256>>>();

    // q/k 1x1 GEMMs (fp16 in/out)
    mma_gemm<<<dim3(128, B_), 768, SMEM_G>>>(
        (const __half*)pxh, nullptr, nullptr, (const __half*)pwq, pt, 96, 0, 1);
    mma_gemm<<<dim3(128, B_), 768, SMEM_G>>>(
        (const __half*)pyh, nullptr, nullptr, (const __half*)pwk, pt2, 96, 0, 1);
    // depthwise for both branches
    dw3x3_kernel<<<dim3(16, C2_, 2 * B_), 256>>>(w_qv_dw, w_kv_dw);
    // v = fuse3x3(cat(v0, v_)) + bias
    fuse_mma<<<dim3(64, B_), 768, SMEM_F>>>((const __half*)pwft, b_fuse);
    // attention
    attn_part<<<dim3(HEADS_, B_, NSPLIT), 256>>>();
    attn_soft<<<dim3(HEADS_, B_), 256>>>(temp);
    // per-batch fused final weights
    pack_wfin<<<(B_ * C2_ * 288 + 255) / 256, 256>>>(w_proj, w_pos, (__half*)pwfin);
    // final: g_wfin_b @ [v; x; y] -> fp32 out
    mma_gemm<<<dim3(128, B_), 768, SMEM_G>>>(
        (const __half*)pv, (const __half*)pxh, (const __half*)pyh,
        (const __half*)pwfin, out, 288, 9 * 192 * APITCH, 0);
}